// round 1
// baseline (speedup 1.0000x reference)
#include <cuda_runtime.h>
#include <math.h>

#define N_SEQ 384
#define C_DIM 128
#define H_NUM 4
#define DH_NUM 32
#define R_RANK 96
#define SD_DIM 449
#define ZD_DIM 577
#define MLP_H 256
#define HR_DIM 384
#define M_TOT (N_SEQ * N_SEQ)   // 147456

// ---------------- scratch (device globals; no allocations allowed) ----------------
__device__ float g_xn[(size_t)M_TOT * C_DIM];      // layernormed x
__device__ float g_rowmean[N_SEQ * C_DIM];
__device__ float g_colmean[N_SEQ * C_DIM];
__device__ float g_zq[N_SEQ * ZD_DIM];
__device__ float g_zk[N_SEQ * ZD_DIM];
__device__ float g_h1[N_SEQ * MLP_H];
__device__ float g_h2[N_SEQ * MLP_H];
__device__ float g_qb[N_SEQ * HR_DIM];
__device__ float g_kb[N_SEQ * HR_DIM];
__device__ float g_bias[(size_t)H_NUM * N_SEQ * N_SEQ];  // precomputed low-rank bias
__device__ float g_q[(size_t)M_TOT * C_DIM];
__device__ float g_k[(size_t)M_TOT * C_DIM];
__device__ float g_v[(size_t)M_TOT * C_DIM];
__device__ float g_g[(size_t)M_TOT * C_DIM];
__device__ float g_o[(size_t)M_TOT * C_DIM];

// ---------------- LayerNorm: one warp per pixel, float4 ----------------
__global__ void ln_kernel(const float* __restrict__ x, const float* __restrict__ gamma,
                          const float* __restrict__ beta, float* __restrict__ xn) {
    size_t pix = (size_t)blockIdx.x * 8 + (threadIdx.x >> 5);
    int l = threadIdx.x & 31;
    const float4* xp = reinterpret_cast<const float4*>(x + pix * 128);
    float4 v = xp[l];
    float s = v.x + v.y + v.z + v.w;
    float s2 = v.x * v.x + v.y * v.y + v.z * v.z + v.w * v.w;
#pragma unroll
    for (int o = 16; o; o >>= 1) {
        s  += __shfl_xor_sync(0xffffffffu, s, o);
        s2 += __shfl_xor_sync(0xffffffffu, s2, o);
    }
    float mu = s * (1.f / 128.f);
    float var = s2 * (1.f / 128.f) - mu * mu;
    float rs = rsqrtf(var + 1e-5f);
    float4 gm = reinterpret_cast<const float4*>(gamma)[l];
    float4 bt = reinterpret_cast<const float4*>(beta)[l];
    float4 o4;
    o4.x = (v.x - mu) * rs * gm.x + bt.x;
    o4.y = (v.y - mu) * rs * gm.y + bt.y;
    o4.z = (v.z - mu) * rs * gm.z + bt.z;
    o4.w = (v.w - mu) * rs * gm.w + bt.w;
    reinterpret_cast<float4*>(xn + pix * 128)[l] = o4;
}

// ---------------- row/col means over the pair rep ----------------
__global__ void mean_kernel(const float* __restrict__ xn, float* __restrict__ rowmean,
                            float* __restrict__ colmean) {
    int c = threadIdx.x;      // 128
    int idx = blockIdx.x;     // 0..767
    if (idx < N_SEQ) {
        size_t base = (size_t)idx * N_SEQ * C_DIM;
        float s = 0.f;
        for (int j = 0; j < N_SEQ; j++) s += xn[base + (size_t)j * C_DIM + c];
        rowmean[idx * C_DIM + c] = s * (1.f / N_SEQ);
    } else {
        int j = idx - N_SEQ;
        float s = 0.f;
        for (int i = 0; i < N_SEQ; i++) s += xn[((size_t)i * N_SEQ + j) * C_DIM + c];
        colmean[j * C_DIM + c] = s * (1.f / N_SEQ);
    }
}

// ---------------- build concat(mean, s_inputs) ----------------
__global__ void buildz_kernel(const float* __restrict__ rowmean, const float* __restrict__ colmean,
                              const float* __restrict__ s_inputs,
                              float* __restrict__ zq, float* __restrict__ zk) {
    int n = blockIdx.x;
    for (int t = threadIdx.x; t < ZD_DIM; t += blockDim.x) {
        float sv = (t >= C_DIM) ? s_inputs[n * SD_DIM + t - C_DIM] : 0.f;
        zq[n * ZD_DIM + t] = (t < C_DIM) ? rowmean[n * C_DIM + t] : sv;
        zk[n * ZD_DIM + t] = (t < C_DIM) ? colmean[n * C_DIM + t] : sv;
    }
}

// ---------------- tiny MLP GEMM: C = act(A @ W), A row in shared ----------------
__global__ void mlp_gemm(const float* __restrict__ A, const float* __restrict__ W,
                         float* __restrict__ Cout, int K, int Nout, int act) {
    __shared__ float As[608];
    int m = blockIdx.x;
    for (int t = threadIdx.x; t < K; t += 128) As[t] = A[m * K + t];
    __syncthreads();
    int n = blockIdx.y * 128 + threadIdx.x;
    if (n < Nout) {
        float acc = 0.f;
        for (int k = 0; k < K; k++) acc = fmaf(As[k], W[k * Nout + n], acc);
        Cout[m * Nout + n] = act ? tanhf(acc) : acc;
    }
}

// ---------------- low-rank bias matrix B[h,q,k] = sum_r qb[q,h*R+r]*kb[k,h*R+r] ----------------
__global__ void bias_kernel(const float* __restrict__ qb, const float* __restrict__ kb,
                            float* __restrict__ B) {
    __shared__ float qs[32][97];
    __shared__ float ks[64][97];
    int h = blockIdx.x, q0 = blockIdx.y * 32, k0 = blockIdx.z * 64;
    for (int e = threadIdx.x; e < 32 * 96; e += 256) {
        int q = e / 96, r = e % 96;
        qs[q][r] = qb[(q0 + q) * HR_DIM + h * R_RANK + r];
    }
    for (int e = threadIdx.x; e < 64 * 96; e += 256) {
        int k = e / 96, r = e % 96;
        ks[k][r] = kb[(k0 + k) * HR_DIM + h * R_RANK + r];
    }
    __syncthreads();
    int ki = threadIdx.x & 63, qg = threadIdx.x >> 6;  // 4 groups x 8 q each
    float acc[8];
#pragma unroll
    for (int u = 0; u < 8; u++) acc[u] = 0.f;
    for (int r = 0; r < 96; r++) {
        float kv = ks[ki][r];
#pragma unroll
        for (int u = 0; u < 8; u++) acc[u] = fmaf(kv, qs[qg * 8 + u][r], acc[u]);
    }
#pragma unroll
    for (int u = 0; u < 8; u++)
        B[((size_t)h * N_SEQ + q0 + qg * 8 + u) * N_SEQ + k0 + ki] = acc[u];
}

// ---------------- fused q/k/v/g projection GEMM (64x64 tiles, 4x4 microtile) ----------------
__global__ void proj_gemm(const float* __restrict__ xn,
                          const float* __restrict__ Wq, const float* __restrict__ Wk,
                          const float* __restrict__ Wv, const float* __restrict__ Wg,
                          const float* __restrict__ bg,
                          float* __restrict__ Qo, float* __restrict__ Ko,
                          float* __restrict__ Vo, float* __restrict__ Go) {
    __shared__ float As[64][32];
    __shared__ float Bs[32][64];
    int mb = blockIdx.x;
    int nb = blockIdx.y;                 // 0..7
    int which = nb >> 1;
    int ncol0 = (nb & 1) * 64;
    const float* W = (which == 0) ? Wq : (which == 1) ? Wk : (which == 2) ? Wv : Wg;
    float* Out = (which == 0) ? Qo : (which == 1) ? Ko : (which == 2) ? Vo : Go;
    int tx = threadIdx.x, ty = threadIdx.y, tid = ty * 16 + tx;
    float acc[4][4];
#pragma unroll
    for (int u = 0; u < 4; u++)
#pragma unroll
        for (int v = 0; v < 4; v++) acc[u][v] = 0.f;

    for (int kc = 0; kc < 128; kc += 32) {
        for (int e = tid; e < 2048; e += 256) {
            int r = e >> 5, c = e & 31;
            As[r][c] = xn[(size_t)(mb * 64 + r) * 128 + kc + c];
        }
        for (int e = tid; e < 2048; e += 256) {
            int r = e >> 6, c = e & 63;
            Bs[r][c] = W[(kc + r) * 128 + ncol0 + c];
        }
        __syncthreads();
#pragma unroll
        for (int kk = 0; kk < 32; kk++) {
            float4 b = *reinterpret_cast<float4*>(&Bs[kk][tx * 4]);
            float a0 = As[ty * 4 + 0][kk], a1 = As[ty * 4 + 1][kk];
            float a2 = As[ty * 4 + 2][kk], a3 = As[ty * 4 + 3][kk];
            acc[0][0] = fmaf(a0, b.x, acc[0][0]); acc[0][1] = fmaf(a0, b.y, acc[0][1]);
            acc[0][2] = fmaf(a0, b.z, acc[0][2]); acc[0][3] = fmaf(a0, b.w, acc[0][3]);
            acc[1][0] = fmaf(a1, b.x, acc[1][0]); acc[1][1] = fmaf(a1, b.y, acc[1][1]);
            acc[1][2] = fmaf(a1, b.z, acc[1][2]); acc[1][3] = fmaf(a1, b.w, acc[1][3]);
            acc[2][0] = fmaf(a2, b.x, acc[2][0]); acc[2][1] = fmaf(a2, b.y, acc[2][1]);
            acc[2][2] = fmaf(a2, b.z, acc[2][2]); acc[2][3] = fmaf(a2, b.w, acc[2][3]);
            acc[3][0] = fmaf(a3, b.x, acc[3][0]); acc[3][1] = fmaf(a3, b.y, acc[3][1]);
            acc[3][2] = fmaf(a3, b.z, acc[3][2]); acc[3][3] = fmaf(a3, b.w, acc[3][3]);
        }
        __syncthreads();
    }
#pragma unroll
    for (int u = 0; u < 4; u++) {
        size_t m = (size_t)mb * 64 + ty * 4 + u;
        float v0 = acc[u][0], v1 = acc[u][1], v2 = acc[u][2], v3 = acc[u][3];
        if (which == 0) {
            const float sc = 0.17677669529663687f;  // 1/sqrt(32)
            v0 *= sc; v1 *= sc; v2 *= sc; v3 *= sc;
        } else if (which == 3) {
            int c0 = ncol0 + tx * 4;
            v0 = 1.f / (1.f + expf(-(v0 + bg[c0 + 0])));
            v1 = 1.f / (1.f + expf(-(v1 + bg[c0 + 1])));
            v2 = 1.f / (1.f + expf(-(v2 + bg[c0 + 2])));
            v3 = 1.f / (1.f + expf(-(v3 + bg[c0 + 3])));
        }
        float4 r; r.x = v0; r.y = v1; r.z = v2; r.w = v3;
        *reinterpret_cast<float4*>(&Out[m * 128 + ncol0 + tx * 4]) = r;
    }
}

// ---------------- per-row flash attention: 1 thread = 1 query, k/v tiles in shared ----------------
__global__ void attn_kernel(const float* __restrict__ Q, const float* __restrict__ K,
                            const float* __restrict__ V, const float* __restrict__ B,
                            float* __restrict__ O) {
    __shared__ float ks[64][32];
    __shared__ float vs[64][32];
    int qt = blockIdx.x, h = blockIdx.y, i = blockIdx.z;
    int qpos = qt * 128 + threadIdx.x;
    const float4* qptr = reinterpret_cast<const float4*>(Q + ((size_t)i * N_SEQ + qpos) * 128 + h * 32);
    float4 qr[8];
#pragma unroll
    for (int d = 0; d < 8; d++) qr[d] = qptr[d];
    float4 a[8];
#pragma unroll
    for (int d = 0; d < 8; d++) a[d] = make_float4(0.f, 0.f, 0.f, 0.f);
    float mrun = -1e30f, lsum = 0.f;
    const float* brow = B + ((size_t)h * N_SEQ + qpos) * N_SEQ;
    const float L2E = 1.4426950408889634f;

    for (int kt = 0; kt < 6; kt++) {
        int k0 = kt * 64;
        const float4* kg = reinterpret_cast<const float4*>(K + ((size_t)i * N_SEQ + k0) * 128 + h * 32);
        const float4* vg = reinterpret_cast<const float4*>(V + ((size_t)i * N_SEQ + k0) * 128 + h * 32);
        for (int e = threadIdx.x; e < 512; e += 128) {
            int kp = e >> 3, d4 = e & 7;
            reinterpret_cast<float4*>(ks)[kp * 8 + d4] = kg[kp * 32 + d4];
            reinterpret_cast<float4*>(vs)[kp * 8 + d4] = vg[kp * 32 + d4];
        }
        __syncthreads();

        for (int kc = 0; kc < 64; kc += 8) {
            float4 b0 = *reinterpret_cast<const float4*>(brow + k0 + kc);
            float4 b1 = *reinterpret_cast<const float4*>(brow + k0 + kc + 4);
            float s[8] = {b0.x, b0.y, b0.z, b0.w, b1.x, b1.y, b1.z, b1.w};
#pragma unroll
            for (int u = 0; u < 8; u++) {
                const float4* kp = reinterpret_cast<const float4*>(ks[kc + u]);
                float accv = s[u];
#pragma unroll
                for (int d = 0; d < 8; d++) {
                    float4 kv = kp[d];
                    accv = fmaf(qr[d].x, kv.x, accv);
                    accv = fmaf(qr[d].y, kv.y, accv);
                    accv = fmaf(qr[d].z, kv.z, accv);
                    accv = fmaf(qr[d].w, kv.w, accv);
                }
                s[u] = accv;
            }
            float cmax = mrun;
#pragma unroll
            for (int u = 0; u < 8; u++) cmax = fmaxf(cmax, s[u]);
            float corr = exp2f((mrun - cmax) * L2E);
            mrun = cmax;
            lsum *= corr;
#pragma unroll
            for (int d = 0; d < 8; d++) {
                a[d].x *= corr; a[d].y *= corr; a[d].z *= corr; a[d].w *= corr;
            }
#pragma unroll
            for (int u = 0; u < 8; u++) {
                float p = exp2f((s[u] - mrun) * L2E);
                lsum += p;
                const float4* vp = reinterpret_cast<const float4*>(vs[kc + u]);
#pragma unroll
                for (int d = 0; d < 8; d++) {
                    float4 vv = vp[d];
                    a[d].x = fmaf(p, vv.x, a[d].x);
                    a[d].y = fmaf(p, vv.y, a[d].y);
                    a[d].z = fmaf(p, vv.z, a[d].z);
                    a[d].w = fmaf(p, vv.w, a[d].w);
                }
            }
        }
        __syncthreads();
    }
    float inv = 1.f / lsum;
    float4* op = reinterpret_cast<float4*>(O + ((size_t)i * N_SEQ + qpos) * 128 + h * 32);
#pragma unroll
    for (int d = 0; d < 8; d++) {
        float4 t = a[d];
        t.x *= inv; t.y *= inv; t.z *= inv; t.w *= inv;
        op[d] = t;
    }
}

// ---------------- out = (g .* o) @ Wo + bo ----------------
__global__ void out_gemm(const float* __restrict__ Gg, const float* __restrict__ Oo,
                         const float* __restrict__ Wo, const float* __restrict__ bo,
                         float* __restrict__ out) {
    __shared__ float As[64][32];
    __shared__ float Bs[32][64];
    int mb = blockIdx.x;
    int ncol0 = blockIdx.y * 64;
    int tx = threadIdx.x, ty = threadIdx.y, tid = ty * 16 + tx;
    float acc[4][4];
#pragma unroll
    for (int u = 0; u < 4; u++)
#pragma unroll
        for (int v = 0; v < 4; v++) acc[u][v] = 0.f;

    for (int kc = 0; kc < 128; kc += 32) {
        for (int e = tid; e < 2048; e += 256) {
            int r = e >> 5, c = e & 31;
            size_t gi = (size_t)(mb * 64 + r) * 128 + kc + c;
            As[r][c] = Gg[gi] * Oo[gi];
        }
        for (int e = tid; e < 2048; e += 256) {
            int r = e >> 6, c = e & 63;
            Bs[r][c] = Wo[(kc + r) * 128 + ncol0 + c];
        }
        __syncthreads();
#pragma unroll
        for (int kk = 0; kk < 32; kk++) {
            float4 b = *reinterpret_cast<float4*>(&Bs[kk][tx * 4]);
            float a0 = As[ty * 4 + 0][kk], a1 = As[ty * 4 + 1][kk];
            float a2 = As[ty * 4 + 2][kk], a3 = As[ty * 4 + 3][kk];
            acc[0][0] = fmaf(a0, b.x, acc[0][0]); acc[0][1] = fmaf(a0, b.y, acc[0][1]);
            acc[0][2] = fmaf(a0, b.z, acc[0][2]); acc[0][3] = fmaf(a0, b.w, acc[0][3]);
            acc[1][0] = fmaf(a1, b.x, acc[1][0]); acc[1][1] = fmaf(a1, b.y, acc[1][1]);
            acc[1][2] = fmaf(a1, b.z, acc[1][2]); acc[1][3] = fmaf(a1, b.w, acc[1][3]);
            acc[2][0] = fmaf(a2, b.x, acc[2][0]); acc[2][1] = fmaf(a2, b.y, acc[2][1]);
            acc[2][2] = fmaf(a2, b.z, acc[2][2]); acc[2][3] = fmaf(a2, b.w, acc[2][3]);
            acc[3][0] = fmaf(a3, b.x, acc[3][0]); acc[3][1] = fmaf(a3, b.y, acc[3][1]);
            acc[3][2] = fmaf(a3, b.z, acc[3][2]); acc[3][3] = fmaf(a3, b.w, acc[3][3]);
        }
        __syncthreads();
    }
#pragma unroll
    for (int u = 0; u < 4; u++) {
        size_t m = (size_t)mb * 64 + ty * 4 + u;
        int c0 = ncol0 + tx * 4;
        float4 r;
        r.x = acc[u][0] + bo[c0 + 0];
        r.y = acc[u][1] + bo[c0 + 1];
        r.z = acc[u][2] + bo[c0 + 2];
        r.w = acc[u][3] + bo[c0 + 3];
        *reinterpret_cast<float4*>(&out[m * 128 + c0]) = r;
    }
}

// ---------------- launch ----------------
extern "C" void kernel_launch(void* const* d_in, const int* in_sizes, int n_in,
                              void* d_out, int out_size) {
    const float* x        = (const float*)d_in[0];
    const float* s_inputs = (const float*)d_in[1];
    const float* gamma    = (const float*)d_in[2];
    const float* beta     = (const float*)d_in[3];
    const float* Wq1      = (const float*)d_in[4];
    const float* Wq2      = (const float*)d_in[5];
    const float* Wq3      = (const float*)d_in[6];
    const float* Wk1      = (const float*)d_in[7];
    const float* Wk2      = (const float*)d_in[8];
    const float* Wk3      = (const float*)d_in[9];
    const float* Wq_att   = (const float*)d_in[10];
    const float* Wk_att   = (const float*)d_in[11];
    const float* Wv_att   = (const float*)d_in[12];
    const float* Wg       = (const float*)d_in[13];
    const float* bg       = (const float*)d_in[14];
    const float* Wo       = (const float*)d_in[15];
    const float* bo       = (const float*)d_in[16];
    float* out = (float*)d_out;

    float *xn, *rowmean, *colmean, *zq, *zk, *h1, *h2, *qb, *kb, *bias;
    float *q_, *k_, *v_, *gg, *oo;
    cudaGetSymbolAddress((void**)&xn, g_xn);
    cudaGetSymbolAddress((void**)&rowmean, g_rowmean);
    cudaGetSymbolAddress((void**)&colmean, g_colmean);
    cudaGetSymbolAddress((void**)&zq, g_zq);
    cudaGetSymbolAddress((void**)&zk, g_zk);
    cudaGetSymbolAddress((void**)&h1, g_h1);
    cudaGetSymbolAddress((void**)&h2, g_h2);
    cudaGetSymbolAddress((void**)&qb, g_qb);
    cudaGetSymbolAddress((void**)&kb, g_kb);
    cudaGetSymbolAddress((void**)&bias, g_bias);
    cudaGetSymbolAddress((void**)&q_, g_q);
    cudaGetSymbolAddress((void**)&k_, g_k);
    cudaGetSymbolAddress((void**)&v_, g_v);
    cudaGetSymbolAddress((void**)&gg, g_g);
    cudaGetSymbolAddress((void**)&oo, g_o);

    // 1. LayerNorm
    ln_kernel<<<M_TOT / 8, 256>>>(x, gamma, beta, xn);
    // 2. row/col means
    mean_kernel<<<2 * N_SEQ, 128>>>(xn, rowmean, colmean);
    // 3. concat inputs for bias MLPs
    buildz_kernel<<<N_SEQ, 128>>>(rowmean, colmean, s_inputs, zq, zk);
    // 4. bias MLPs (q then k chain)
    mlp_gemm<<<dim3(N_SEQ, 2), 128>>>(zq, Wq1, h1, ZD_DIM, MLP_H, 1);
    mlp_gemm<<<dim3(N_SEQ, 2), 128>>>(h1, Wq2, h2, MLP_H, MLP_H, 1);
    mlp_gemm<<<dim3(N_SEQ, 3), 128>>>(h2, Wq3, qb, MLP_H, HR_DIM, 0);
    mlp_gemm<<<dim3(N_SEQ, 2), 128>>>(zk, Wk1, h1, ZD_DIM, MLP_H, 1);
    mlp_gemm<<<dim3(N_SEQ, 2), 128>>>(h1, Wk2, h2, MLP_H, MLP_H, 1);
    mlp_gemm<<<dim3(N_SEQ, 3), 128>>>(h2, Wk3, kb, MLP_H, HR_DIM, 0);
    // 5. low-rank bias matrix (row-independent, computed once)
    bias_kernel<<<dim3(H_NUM, N_SEQ / 32, N_SEQ / 64), 256>>>(qb, kb, bias);
    // 6. fused q/k/v/g projections
    proj_gemm<<<dim3(M_TOT / 64, 8), dim3(16, 16)>>>(xn, Wq_att, Wk_att, Wv_att, Wg, bg,
                                                     q_, k_, v_, gg);
    // 7. flash attention per (row, head)
    attn_kernel<<<dim3(3, H_NUM, N_SEQ), 128>>>(q_, k_, v_, bias, oo);
    // 8. gated output projection
    out_gemm<<<dim3(M_TOT / 64, 2), dim3(16, 16)>>>(gg, oo, Wo, bo, out);
}

// round 3
// speedup vs baseline: 1.2252x; 1.2252x over previous
#include <cuda_runtime.h>
#include <cuda_bf16.h>
#include <cstdint>
#include <math.h>

#define N_SEQ 384
#define C_DIM 128
#define H_NUM 4
#define DH_NUM 32
#define R_RANK 96
#define SD_DIM 449
#define ZD_DIM 577
#define MLP_H 256
#define HR_DIM 384
#define M_TOT (N_SEQ * N_SEQ)   // 147456

typedef __nv_bfloat16 bf16;

// ---------------- scratch (device globals) ----------------
__device__ bf16  g_xh[(size_t)M_TOT * C_DIM];
__device__ bf16  g_xl[(size_t)M_TOT * C_DIM];
__device__ float g_rowmean[N_SEQ * C_DIM];
__device__ float g_colmean[N_SEQ * C_DIM];
__device__ float g_zq[N_SEQ * ZD_DIM];
__device__ float g_zk[N_SEQ * ZD_DIM];
__device__ float g_h1[N_SEQ * MLP_H];
__device__ float g_h2[N_SEQ * MLP_H];
__device__ float g_qb[N_SEQ * HR_DIM];
__device__ float g_kb[N_SEQ * HR_DIM];
__device__ float g_bias[(size_t)H_NUM * N_SEQ * N_SEQ];
__device__ bf16  g_Qh[(size_t)M_TOT * C_DIM];
__device__ bf16  g_Ql[(size_t)M_TOT * C_DIM];
__device__ bf16  g_Kh[(size_t)M_TOT * C_DIM];
__device__ bf16  g_Kl[(size_t)M_TOT * C_DIM];
__device__ bf16  g_Vh[(size_t)M_TOT * C_DIM];
__device__ bf16  g_Vl[(size_t)M_TOT * C_DIM];
__device__ float g_G[(size_t)M_TOT * C_DIM];
__device__ float g_O[(size_t)M_TOT * C_DIM];

// ---------------- helpers ----------------
__device__ __forceinline__ uint32_t pk2(float a, float b) {
    __nv_bfloat162 t = __floats2bfloat162_rn(a, b);
    return *reinterpret_cast<uint32_t*>(&t);
}
__device__ __forceinline__ float bhi(float x) {
    return __bfloat162float(__float2bfloat16(x));
}
__device__ __forceinline__ void mma_bf16(float* c, const uint32_t* a, uint32_t b0, uint32_t b1) {
    asm volatile(
        "mma.sync.aligned.m16n8k16.row.col.f32.bf16.bf16.f32 "
        "{%0,%1,%2,%3},{%4,%5,%6,%7},{%8,%9},{%0,%1,%2,%3};"
        : "+f"(c[0]), "+f"(c[1]), "+f"(c[2]), "+f"(c[3])
        : "r"(a[0]), "r"(a[1]), "r"(a[2]), "r"(a[3]), "r"(b0), "r"(b1));
}

// ---------------- LayerNorm -> split bf16 hi/lo ----------------
__global__ void ln_kernel(const float* __restrict__ x, const float* __restrict__ gamma,
                          const float* __restrict__ beta,
                          bf16* __restrict__ xh, bf16* __restrict__ xl) {
    size_t pix = (size_t)blockIdx.x * 8 + (threadIdx.x >> 5);
    int l = threadIdx.x & 31;
    const float4* xp = reinterpret_cast<const float4*>(x + pix * 128);
    float4 v = xp[l];
    float s = v.x + v.y + v.z + v.w;
    float s2 = v.x * v.x + v.y * v.y + v.z * v.z + v.w * v.w;
#pragma unroll
    for (int o = 16; o; o >>= 1) {
        s  += __shfl_xor_sync(0xffffffffu, s, o);
        s2 += __shfl_xor_sync(0xffffffffu, s2, o);
    }
    float mu = s * (1.f / 128.f);
    float var = s2 * (1.f / 128.f) - mu * mu;
    float rs = rsqrtf(var + 1e-5f);
    float4 gm = reinterpret_cast<const float4*>(gamma)[l];
    float4 bt = reinterpret_cast<const float4*>(beta)[l];
    float o0 = (v.x - mu) * rs * gm.x + bt.x;
    float o1 = (v.y - mu) * rs * gm.y + bt.y;
    float o2 = (v.z - mu) * rs * gm.z + bt.z;
    float o3 = (v.w - mu) * rs * gm.w + bt.w;
    size_t base = pix * 128 + 4 * l;
    *(uint32_t*)&xh[base]     = pk2(o0, o1);
    *(uint32_t*)&xh[base + 2] = pk2(o2, o3);
    *(uint32_t*)&xl[base]     = pk2(o0 - bhi(o0), o1 - bhi(o1));
    *(uint32_t*)&xl[base + 2] = pk2(o2 - bhi(o2), o3 - bhi(o3));
}

// ---------------- row/col means ----------------
__global__ void mean_kernel(const bf16* __restrict__ xh, const bf16* __restrict__ xl,
                            float* __restrict__ rowmean, float* __restrict__ colmean) {
    int c = threadIdx.x;
    int idx = blockIdx.x;
    if (idx < N_SEQ) {
        size_t base = (size_t)idx * N_SEQ * C_DIM;
        float s = 0.f;
        for (int j = 0; j < N_SEQ; j++) {
            size_t e = base + (size_t)j * C_DIM + c;
            s += __bfloat162float(xh[e]) + __bfloat162float(xl[e]);
        }
        rowmean[idx * C_DIM + c] = s * (1.f / N_SEQ);
    } else {
        int j = idx - N_SEQ;
        float s = 0.f;
        for (int i = 0; i < N_SEQ; i++) {
            size_t e = ((size_t)i * N_SEQ + j) * C_DIM + c;
            s += __bfloat162float(xh[e]) + __bfloat162float(xl[e]);
        }
        colmean[j * C_DIM + c] = s * (1.f / N_SEQ);
    }
}

// ---------------- concat(mean, s_inputs) ----------------
__global__ void buildz_kernel(const float* __restrict__ rowmean, const float* __restrict__ colmean,
                              const float* __restrict__ s_inputs,
                              float* __restrict__ zq, float* __restrict__ zk) {
    int n = blockIdx.x;
    for (int t = threadIdx.x; t < ZD_DIM; t += blockDim.x) {
        float sv = (t >= C_DIM) ? s_inputs[n * SD_DIM + t - C_DIM] : 0.f;
        zq[n * ZD_DIM + t] = (t < C_DIM) ? rowmean[n * C_DIM + t] : sv;
        zk[n * ZD_DIM + t] = (t < C_DIM) ? colmean[n * C_DIM + t] : sv;
    }
}

// ---------------- tiled fp32 MLP GEMM: 32x64 tiles ----------------
__global__ void mlp_tiled(const float* __restrict__ A, const float* __restrict__ W,
                          float* __restrict__ C, int M, int K, int Nout, int act) {
    __shared__ float As[32][33];
    __shared__ float Bs[32][68];
    int m0 = blockIdx.x * 32, n0 = blockIdx.y * 64;
    int tx = threadIdx.x, ty = threadIdx.y, tid = ty * 16 + tx;
    float acc[2][4];
#pragma unroll
    for (int u = 0; u < 2; u++)
#pragma unroll
        for (int j = 0; j < 4; j++) acc[u][j] = 0.f;
    for (int k0 = 0; k0 < K; k0 += 32) {
        for (int e = tid; e < 1024; e += 256) {
            int r = e >> 5, c = e & 31;
            As[r][c] = (k0 + c < K) ? A[(m0 + r) * K + k0 + c] : 0.f;
        }
        for (int e = tid; e < 2048; e += 256) {
            int r = e >> 6, c = e & 63;
            Bs[r][c] = (k0 + r < K) ? W[(k0 + r) * Nout + n0 + c] : 0.f;
        }
        __syncthreads();
#pragma unroll
        for (int kk = 0; kk < 32; kk++) {
            float4 b = *reinterpret_cast<float4*>(&Bs[kk][tx * 4]);
            float a0 = As[ty * 2][kk], a1 = As[ty * 2 + 1][kk];
            acc[0][0] = fmaf(a0, b.x, acc[0][0]); acc[0][1] = fmaf(a0, b.y, acc[0][1]);
            acc[0][2] = fmaf(a0, b.z, acc[0][2]); acc[0][3] = fmaf(a0, b.w, acc[0][3]);
            acc[1][0] = fmaf(a1, b.x, acc[1][0]); acc[1][1] = fmaf(a1, b.y, acc[1][1]);
            acc[1][2] = fmaf(a1, b.z, acc[1][2]); acc[1][3] = fmaf(a1, b.w, acc[1][3]);
        }
        __syncthreads();
    }
#pragma unroll
    for (int u = 0; u < 2; u++) {
        int m = m0 + ty * 2 + u;
#pragma unroll
        for (int j = 0; j < 4; j++) {
            float v = acc[u][j];
            C[m * Nout + n0 + tx * 4 + j] = act ? tanhf(v) : v;
        }
    }
}

// ---------------- low-rank bias matrix ----------------
__global__ void bias_kernel(const float* __restrict__ qb, const float* __restrict__ kb,
                            float* __restrict__ B) {
    __shared__ float qs[32][97];
    __shared__ float ks[64][97];
    int h = blockIdx.x, q0 = blockIdx.y * 32, k0 = blockIdx.z * 64;
    for (int e = threadIdx.x; e < 32 * 96; e += 256) {
        int q = e / 96, r = e % 96;
        qs[q][r] = qb[(q0 + q) * HR_DIM + h * R_RANK + r];
    }
    for (int e = threadIdx.x; e < 64 * 96; e += 256) {
        int k = e / 96, r = e % 96;
        ks[k][r] = kb[(k0 + k) * HR_DIM + h * R_RANK + r];
    }
    __syncthreads();
    int ki = threadIdx.x & 63, qg = threadIdx.x >> 6;
    float acc[8];
#pragma unroll
    for (int u = 0; u < 8; u++) acc[u] = 0.f;
    for (int r = 0; r < 96; r++) {
        float kv = ks[ki][r];
#pragma unroll
        for (int u = 0; u < 8; u++) acc[u] = fmaf(kv, qs[qg * 8 + u][r], acc[u]);
    }
#pragma unroll
    for (int u = 0; u < 8; u++)
        B[((size_t)h * N_SEQ + q0 + qg * 8 + u) * N_SEQ + k0 + ki] = acc[u];
}

// ---------------- tensor-core q/k/v/g projection (bf16-split, 3-pass) ----------------
__global__ __launch_bounds__(256) void proj_tc(
    const bf16* __restrict__ xh, const bf16* __restrict__ xl,
    const float* __restrict__ Wq, const float* __restrict__ Wk,
    const float* __restrict__ Wv, const float* __restrict__ Wg,
    const float* __restrict__ bg,
    bf16* __restrict__ Qh, bf16* __restrict__ Ql,
    bf16* __restrict__ Kh, bf16* __restrict__ Kl,
    bf16* __restrict__ Vh, bf16* __restrict__ Vl,
    float* __restrict__ G) {
    extern __shared__ bf16 sm[];
    bf16 (*As)[136] = reinterpret_cast<bf16(*)[136]>(sm);             // rows 0-127 hi, 128-255 lo
    bf16 (*Bs)[136] = reinterpret_cast<bf16(*)[136]>(sm + 256 * 136); // rows 0-63 hi, 64-127 lo (n-major)
    int mb = blockIdx.x;
    int which = blockIdx.y >> 1, n0 = (blockIdx.y & 1) * 64;
    const float* W = (which == 0) ? Wq : (which == 1) ? Wk : (which == 2) ? Wv : Wg;
    int tid = threadIdx.x;
    size_t abase = (size_t)mb * 128 * 128;
    for (int e = tid; e < 2048; e += 256) {
        int r = e >> 4, c8 = (e & 15) * 8;
        *(uint4*)&As[r][c8]       = *(const uint4*)&xh[abase + (size_t)r * 128 + c8];
        *(uint4*)&As[128 + r][c8] = *(const uint4*)&xl[abase + (size_t)r * 128 + c8];
    }
    for (int e = tid; e < 8192; e += 256) {
        int k = e >> 6, n = e & 63;
        float wv = W[k * 128 + n0 + n];
        bf16 h = __float2bfloat16(wv);
        Bs[n][k] = h;
        Bs[64 + n][k] = __float2bfloat16(wv - __bfloat162float(h));
    }
    __syncthreads();
    int w = tid >> 5, lane = tid & 31, g = lane >> 2, tg = lane & 3;
    int wm = (w & 3) * 32, wn = (w >> 2) * 32;
    float acc[2][4][4];
#pragma unroll
    for (int mi = 0; mi < 2; mi++)
#pragma unroll
        for (int ni = 0; ni < 4; ni++)
#pragma unroll
            for (int j = 0; j < 4; j++) acc[mi][ni][j] = 0.f;
#pragma unroll
    for (int p = 0; p < 3; p++) {
        int ao = (p == 2) ? 128 : 0;
        int bo = (p == 1) ? 64 : 0;
#pragma unroll
        for (int kc = 0; kc < 8; kc++) {
            int k2 = kc * 16 + tg * 2;
            uint32_t a[2][4], b[4][2];
#pragma unroll
            for (int mi = 0; mi < 2; mi++) {
                int r = ao + wm + mi * 16;
                a[mi][0] = *(const uint32_t*)&As[r + g][k2];
                a[mi][1] = *(const uint32_t*)&As[r + g + 8][k2];
                a[mi][2] = *(const uint32_t*)&As[r + g][k2 + 8];
                a[mi][3] = *(const uint32_t*)&As[r + g + 8][k2 + 8];
            }
#pragma unroll
            for (int ni = 0; ni < 4; ni++) {
                int rn = bo + wn + ni * 8 + g;
                b[ni][0] = *(const uint32_t*)&Bs[rn][k2];
                b[ni][1] = *(const uint32_t*)&Bs[rn][k2 + 8];
            }
#pragma unroll
            for (int mi = 0; mi < 2; mi++)
#pragma unroll
                for (int ni = 0; ni < 4; ni++)
                    mma_bf16(acc[mi][ni], a[mi], b[ni][0], b[ni][1]);
        }
    }
    const float qscale = 0.17677669529663687f;  // 1/sqrt(32)
#pragma unroll
    for (int mi = 0; mi < 2; mi++)
#pragma unroll
    for (int ni = 0; ni < 4; ni++) {
        size_t row0 = (size_t)mb * 128 + wm + mi * 16 + g;
        int col = n0 + wn + ni * 8 + tg * 2;
        float* c = acc[mi][ni];
        if (which == 0) { c[0] *= qscale; c[1] *= qscale; c[2] *= qscale; c[3] *= qscale; }
        if (which == 3) {
            float b0v = bg[col], b1v = bg[col + 1];
            float g0 = 1.f / (1.f + expf(-(c[0] + b0v)));
            float g1 = 1.f / (1.f + expf(-(c[1] + b1v)));
            float g2 = 1.f / (1.f + expf(-(c[2] + b0v)));
            float g3 = 1.f / (1.f + expf(-(c[3] + b1v)));
            *(float2*)&G[row0 * 128 + col] = make_float2(g0, g1);
            *(float2*)&G[(row0 + 8) * 128 + col] = make_float2(g2, g3);
        } else {
            bf16* Oh = (which == 0) ? Qh : (which == 1) ? Kh : Vh;
            bf16* Ol = (which == 0) ? Ql : (which == 1) ? Kl : Vl;
            *(uint32_t*)&Oh[row0 * 128 + col] = pk2(c[0], c[1]);
            *(uint32_t*)&Ol[row0 * 128 + col] = pk2(c[0] - bhi(c[0]), c[1] - bhi(c[1]));
            *(uint32_t*)&Oh[(row0 + 8) * 128 + col] = pk2(c[2], c[3]);
            *(uint32_t*)&Ol[(row0 + 8) * 128 + col] = pk2(c[2] - bhi(c[2]), c[3] - bhi(c[3]));
        }
    }
}

// ---------------- tensor-core flash attention ----------------
__global__ __launch_bounds__(256) void attn_tc(
    const bf16* __restrict__ Qh, const bf16* __restrict__ Ql,
    const bf16* __restrict__ Kh, const bf16* __restrict__ Kl,
    const bf16* __restrict__ Vh, const bf16* __restrict__ Vl,
    const float* __restrict__ B, float* __restrict__ O) {
    __shared__ bf16 Qs[256][40];   // rows 0-127 hi, 128-255 lo ; [qrow][d]
    __shared__ bf16 Ks[128][40];   // rows 0-63 hi, 64-127 lo   ; [kpos][d]
    __shared__ bf16 Vs[64][72];    // rows 0-31 hi, 32-63 lo    ; [d][kpos]
    int qt = blockIdx.x, h = blockIdx.y, i = blockIdx.z;
    int q0 = qt * 128, tid = threadIdx.x;
    size_t qgb = ((size_t)(i * N_SEQ + q0)) * 128 + h * 32;
    for (int e = tid; e < 512; e += 256) {
        int r = e >> 2, c8 = (e & 3) * 8;
        *(uint4*)&Qs[r][c8]       = *(const uint4*)&Qh[qgb + (size_t)r * 128 + c8];
        *(uint4*)&Qs[128 + r][c8] = *(const uint4*)&Ql[qgb + (size_t)r * 128 + c8];
    }
    int w = tid >> 5, lane = tid & 31, g = lane >> 2, tg = lane & 3;
    int qr = w * 16;
    __syncthreads();
    uint32_t qa[2][2][4];
#pragma unroll
    for (int s = 0; s < 2; s++)
#pragma unroll
        for (int kc = 0; kc < 2; kc++) {
            int r = s * 128 + qr;
            int k2 = kc * 16 + tg * 2;
            qa[s][kc][0] = *(const uint32_t*)&Qs[r + g][k2];
            qa[s][kc][1] = *(const uint32_t*)&Qs[r + g + 8][k2];
            qa[s][kc][2] = *(const uint32_t*)&Qs[r + g][k2 + 8];
            qa[s][kc][3] = *(const uint32_t*)&Qs[r + g + 8][k2 + 8];
        }
    float oacc[4][4];
#pragma unroll
    for (int ni = 0; ni < 4; ni++)
#pragma unroll
        for (int j = 0; j < 4; j++) oacc[ni][j] = 0.f;
    float m0 = -1e30f, m1 = -1e30f, l0 = 0.f, l1 = 0.f;
    const float L2E = 1.4426950408889634f;
    size_t brow0 = ((size_t)h * N_SEQ + q0 + qr + g) * N_SEQ;
    size_t brow1 = brow0 + (size_t)8 * N_SEQ;

    for (int kt = 0; kt < 6; kt++) {
        int k0 = kt * 64;
        __syncthreads();
        size_t kb = ((size_t)(i * N_SEQ + k0)) * 128 + h * 32;
        {   // K tile: 64x32 hi/lo
            int r = tid >> 2, c8 = (tid & 3) * 8;
            if (tid < 256) {
                *(uint4*)&Ks[r][c8]      = *(const uint4*)&Kh[kb + (size_t)r * 128 + c8];
                *(uint4*)&Ks[64 + r][c8] = *(const uint4*)&Kl[kb + (size_t)r * 128 + c8];
            }
        }
        {   // V tile transpose: [kpos][d] -> Vs[d][kpos]
            int r = tid >> 2, d0 = (tid & 3) * 8;
            uint4 vh4 = *(const uint4*)&Vh[kb + (size_t)r * 128 + d0];
            uint4 vl4 = *(const uint4*)&Vl[kb + (size_t)r * 128 + d0];
            const bf16* ph = (const bf16*)&vh4;
            const bf16* pl = (const bf16*)&vl4;
#pragma unroll
            for (int u = 0; u < 8; u++) {
                Vs[d0 + u][r] = ph[u];
                Vs[32 + d0 + u][r] = pl[u];
            }
        }
        __syncthreads();

        float sc[8][4];
#pragma unroll
        for (int nf = 0; nf < 8; nf++) {   // init scores with bias
            int col = k0 + nf * 8 + tg * 2;
            float2 b0 = *(const float2*)&B[brow0 + col];
            float2 b1 = *(const float2*)&B[brow1 + col];
            sc[nf][0] = b0.x; sc[nf][1] = b0.y; sc[nf][2] = b1.x; sc[nf][3] = b1.y;
        }
#pragma unroll
        for (int p = 0; p < 3; p++) {      // QK^T: hh, hl, lh
            int aso = (p == 2) ? 1 : 0;
            int kso = (p == 1) ? 64 : 0;
#pragma unroll
            for (int kc = 0; kc < 2; kc++) {
                int k2 = kc * 16 + tg * 2;
#pragma unroll
                for (int nf = 0; nf < 8; nf++) {
                    uint32_t b0 = *(const uint32_t*)&Ks[kso + nf * 8 + g][k2];
                    uint32_t b1 = *(const uint32_t*)&Ks[kso + nf * 8 + g][k2 + 8];
                    mma_bf16(sc[nf], qa[aso][kc], b0, b1);
                }
            }
        }
        // online softmax
        float nm0 = m0, nm1 = m1;
#pragma unroll
        for (int nf = 0; nf < 8; nf++) {
            nm0 = fmaxf(nm0, fmaxf(sc[nf][0], sc[nf][1]));
            nm1 = fmaxf(nm1, fmaxf(sc[nf][2], sc[nf][3]));
        }
        nm0 = fmaxf(nm0, __shfl_xor_sync(0xffffffffu, nm0, 1));
        nm0 = fmaxf(nm0, __shfl_xor_sync(0xffffffffu, nm0, 2));
        nm1 = fmaxf(nm1, __shfl_xor_sync(0xffffffffu, nm1, 1));
        nm1 = fmaxf(nm1, __shfl_xor_sync(0xffffffffu, nm1, 2));
        float cor0 = exp2f((m0 - nm0) * L2E);
        float cor1 = exp2f((m1 - nm1) * L2E);
        m0 = nm0; m1 = nm1;
        l0 *= cor0; l1 *= cor1;
#pragma unroll
        for (int ni = 0; ni < 4; ni++) {
            oacc[ni][0] *= cor0; oacc[ni][1] *= cor0;
            oacc[ni][2] *= cor1; oacc[ni][3] *= cor1;
        }
#pragma unroll
        for (int nf = 0; nf < 8; nf++) {
            sc[nf][0] = exp2f((sc[nf][0] - m0) * L2E);
            sc[nf][1] = exp2f((sc[nf][1] - m0) * L2E);
            sc[nf][2] = exp2f((sc[nf][2] - m1) * L2E);
            sc[nf][3] = exp2f((sc[nf][3] - m1) * L2E);
            l0 += sc[nf][0] + sc[nf][1];
            l1 += sc[nf][2] + sc[nf][3];
        }
        // PV: split P into hi/lo, 3 passes (PhVh, PhVl, PlVh)
#pragma unroll
        for (int kc = 0; kc < 4; kc++) {
            float* f0 = sc[2 * kc];
            float* f1 = sc[2 * kc + 1];
            uint32_t pah[4], pal[4];
            pah[0] = pk2(f0[0], f0[1]); pah[1] = pk2(f0[2], f0[3]);
            pah[2] = pk2(f1[0], f1[1]); pah[3] = pk2(f1[2], f1[3]);
            pal[0] = pk2(f0[0] - bhi(f0[0]), f0[1] - bhi(f0[1]));
            pal[1] = pk2(f0[2] - bhi(f0[2]), f0[3] - bhi(f0[3]));
            pal[2] = pk2(f1[0] - bhi(f1[0]), f1[1] - bhi(f1[1]));
            pal[3] = pk2(f1[2] - bhi(f1[2]), f1[3] - bhi(f1[3]));
            int k2 = kc * 16 + tg * 2;
#pragma unroll
            for (int ni = 0; ni < 4; ni++) {
                uint32_t bh0 = *(const uint32_t*)&Vs[ni * 8 + g][k2];
                uint32_t bh1 = *(const uint32_t*)&Vs[ni * 8 + g][k2 + 8];
                uint32_t bl0 = *(const uint32_t*)&Vs[32 + ni * 8 + g][k2];
                uint32_t bl1 = *(const uint32_t*)&Vs[32 + ni * 8 + g][k2 + 8];
                mma_bf16(oacc[ni], pah, bh0, bh1);
                mma_bf16(oacc[ni], pah, bl0, bl1);
                mma_bf16(oacc[ni], pal, bh0, bh1);
            }
        }
    }
    l0 += __shfl_xor_sync(0xffffffffu, l0, 1);
    l0 += __shfl_xor_sync(0xffffffffu, l0, 2);
    l1 += __shfl_xor_sync(0xffffffffu, l1, 1);
    l1 += __shfl_xor_sync(0xffffffffu, l1, 2);
    float i0 = 1.f / l0, i1 = 1.f / l1;
    size_t ob0 = ((size_t)(i * N_SEQ + q0 + qr + g)) * 128 + h * 32;
    size_t ob1 = ob0 + 8 * 128;
#pragma unroll
    for (int ni = 0; ni < 4; ni++) {
        int d = ni * 8 + tg * 2;
        *(float2*)&O[ob0 + d] = make_float2(oacc[ni][0] * i0, oacc[ni][1] * i0);
        *(float2*)&O[ob1 + d] = make_float2(oacc[ni][2] * i1, oacc[ni][3] * i1);
    }
}

// ---------------- tensor-core output GEMM: out = (g.*o) @ Wo + bo ----------------
__global__ __launch_bounds__(256) void out_tc(
    const float* __restrict__ G, const float* __restrict__ O,
    const float* __restrict__ Wo, const float* __restrict__ bo,
    float* __restrict__ out) {
    extern __shared__ bf16 sm[];
    bf16 (*As)[136] = reinterpret_cast<bf16(*)[136]>(sm);
    bf16 (*Bs)[136] = reinterpret_cast<bf16(*)[136]>(sm + 256 * 136);
    int mb = blockIdx.x;
    int n0 = blockIdx.y * 64;
    int tid = threadIdx.x;
    size_t abase = (size_t)mb * 128 * 128;
    for (int e = tid; e < 4096; e += 256) {
        int r = e >> 5, c4 = (e & 31) * 4;
        float4 g4 = *(const float4*)&G[abase + (size_t)r * 128 + c4];
        float4 o4 = *(const float4*)&O[abase + (size_t)r * 128 + c4];
        float a0 = g4.x * o4.x, a1 = g4.y * o4.y, a2 = g4.z * o4.z, a3 = g4.w * o4.w;
        *(uint32_t*)&As[r][c4]           = pk2(a0, a1);
        *(uint32_t*)&As[r][c4 + 2]       = pk2(a2, a3);
        *(uint32_t*)&As[128 + r][c4]     = pk2(a0 - bhi(a0), a1 - bhi(a1));
        *(uint32_t*)&As[128 + r][c4 + 2] = pk2(a2 - bhi(a2), a3 - bhi(a3));
    }
    for (int e = tid; e < 8192; e += 256) {
        int k = e >> 6, n = e & 63;
        float wv = Wo[k * 128 + n0 + n];
        bf16 h = __float2bfloat16(wv);
        Bs[n][k] = h;
        Bs[64 + n][k] = __float2bfloat16(wv - __bfloat162float(h));
    }
    __syncthreads();
    int w = tid >> 5, lane = tid & 31, g = lane >> 2, tg = lane & 3;
    int wm = (w & 3) * 32, wn = (w >> 2) * 32;
    float acc[2][4][4];
#pragma unroll
    for (int mi = 0; mi < 2; mi++)
#pragma unroll
        for (int ni = 0; ni < 4; ni++)
#pragma unroll
            for (int j = 0; j < 4; j++) acc[mi][ni][j] = 0.f;
#pragma unroll
    for (int p = 0; p < 3; p++) {
        int ao = (p == 2) ? 128 : 0;
        int bo2 = (p == 1) ? 64 : 0;
#pragma unroll
        for (int kc = 0; kc < 8; kc++) {
            int k2 = kc * 16 + tg * 2;
            uint32_t a[2][4], b[4][2];
#pragma unroll
            for (int mi = 0; mi < 2; mi++) {
                int r = ao + wm + mi * 16;
                a[mi][0] = *(const uint32_t*)&As[r + g][k2];
                a[mi][1] = *(const uint32_t*)&As[r + g + 8][k2];
                a[mi][2] = *(const uint32_t*)&As[r + g][k2 + 8];
                a[mi][3] = *(const uint32_t*)&As[r + g + 8][k2 + 8];
            }
#pragma unroll
            for (int ni = 0; ni < 4; ni++) {
                int rn = bo2 + wn + ni * 8 + g;
                b[ni][0] = *(const uint32_t*)&Bs[rn][k2];
                b[ni][1] = *(const uint32_t*)&Bs[rn][k2 + 8];
            }
#pragma unroll
            for (int mi = 0; mi < 2; mi++)
#pragma unroll
                for (int ni = 0; ni < 4; ni++)
                    mma_bf16(acc[mi][ni], a[mi], b[ni][0], b[ni][1]);
        }
    }
#pragma unroll
    for (int mi = 0; mi < 2; mi++)
#pragma unroll
    for (int ni = 0; ni < 4; ni++) {
        size_t row0 = (size_t)mb * 128 + wm + mi * 16 + g;
        int col = n0 + wn + ni * 8 + tg * 2;
        float b0v = bo[col], b1v = bo[col + 1];
        float* c = acc[mi][ni];
        *(float2*)&out[row0 * 128 + col] = make_float2(c[0] + b0v, c[1] + b1v);
        *(float2*)&out[(row0 + 8) * 128 + col] = make_float2(c[2] + b0v, c[3] + b1v);
    }
}

// ---------------- launch ----------------
extern "C" void kernel_launch(void* const* d_in, const int* in_sizes, int n_in,
                              void* d_out, int out_size) {
    const float* x        = (const float*)d_in[0];
    const float* s_inputs = (const float*)d_in[1];
    const float* gamma    = (const float*)d_in[2];
    const float* beta     = (const float*)d_in[3];
    const float* Wq1      = (const float*)d_in[4];
    const float* Wq2      = (const float*)d_in[5];
    const float* Wq3      = (const float*)d_in[6];
    const float* Wk1      = (const float*)d_in[7];
    const float* Wk2      = (const float*)d_in[8];
    const float* Wk3      = (const float*)d_in[9];
    const float* Wq_att   = (const float*)d_in[10];
    const float* Wk_att   = (const float*)d_in[11];
    const float* Wv_att   = (const float*)d_in[12];
    const float* Wg       = (const float*)d_in[13];
    const float* bg       = (const float*)d_in[14];
    const float* Wo       = (const float*)d_in[15];
    const float* bo       = (const float*)d_in[16];
    float* out = (float*)d_out;

    bf16 *xh, *xl, *Qh, *Ql, *Kh, *Kl, *Vh, *Vl;
    float *rowmean, *colmean, *zq, *zk, *h1, *h2, *qb, *kb, *bias, *G, *O;
    cudaGetSymbolAddress((void**)&xh, g_xh);
    cudaGetSymbolAddress((void**)&xl, g_xl);
    cudaGetSymbolAddress((void**)&rowmean, g_rowmean);
    cudaGetSymbolAddress((void**)&colmean, g_colmean);
    cudaGetSymbolAddress((void**)&zq, g_zq);
    cudaGetSymbolAddress((void**)&zk, g_zk);
    cudaGetSymbolAddress((void**)&h1, g_h1);
    cudaGetSymbolAddress((void**)&h2, g_h2);
    cudaGetSymbolAddress((void**)&qb, g_qb);
    cudaGetSymbolAddress((void**)&kb, g_kb);
    cudaGetSymbolAddress((void**)&bias, g_bias);
    cudaGetSymbolAddress((void**)&Qh, g_Qh);
    cudaGetSymbolAddress((void**)&Ql, g_Ql);
    cudaGetSymbolAddress((void**)&Kh, g_Kh);
    cudaGetSymbolAddress((void**)&Kl, g_Kl);
    cudaGetSymbolAddress((void**)&Vh, g_Vh);
    cudaGetSymbolAddress((void**)&Vl, g_Vl);
    cudaGetSymbolAddress((void**)&G, g_G);
    cudaGetSymbolAddress((void**)&O, g_O);

    const int PROJ_SMEM = (256 * 136 + 128 * 136) * 2;  // 104448 bytes
    cudaFuncSetAttribute(proj_tc, cudaFuncAttributeMaxDynamicSharedMemorySize, PROJ_SMEM);
    cudaFuncSetAttribute(out_tc, cudaFuncAttributeMaxDynamicSharedMemorySize, PROJ_SMEM);

    ln_kernel<<<M_TOT / 8, 256>>>(x, gamma, beta, xh, xl);
    mean_kernel<<<2 * N_SEQ, 128>>>(xh, xl, rowmean, colmean);
    buildz_kernel<<<N_SEQ, 128>>>(rowmean, colmean, s_inputs, zq, zk);

    mlp_tiled<<<dim3(12, 4), dim3(16, 16)>>>(zq, Wq1, h1, N_SEQ, ZD_DIM, MLP_H, 1);
    mlp_tiled<<<dim3(12, 4), dim3(16, 16)>>>(h1, Wq2, h2, N_SEQ, MLP_H, MLP_H, 1);
    mlp_tiled<<<dim3(12, 6), dim3(16, 16)>>>(h2, Wq3, qb, N_SEQ, MLP_H, HR_DIM, 0);
    mlp_tiled<<<dim3(12, 4), dim3(16, 16)>>>(zk, Wk1, h1, N_SEQ, ZD_DIM, MLP_H, 1);
    mlp_tiled<<<dim3(12, 4), dim3(16, 16)>>>(h1, Wk2, h2, N_SEQ, MLP_H, MLP_H, 1);
    mlp_tiled<<<dim3(12, 6), dim3(16, 16)>>>(h2, Wk3, kb, N_SEQ, MLP_H, HR_DIM, 0);

    bias_kernel<<<dim3(H_NUM, N_SEQ / 32, N_SEQ / 64), 256>>>(qb, kb, bias);

    proj_tc<<<dim3(M_TOT / 128, 8), 256, PROJ_SMEM>>>(xh, xl, Wq_att, Wk_att, Wv_att, Wg, bg,
                                                      Qh, Ql, Kh, Kl, Vh, Vl, G);
    attn_tc<<<dim3(3, H_NUM, N_SEQ), 256>>>(Qh, Ql, Kh, Kl, Vh, Vl, bias, O);
    out_tc<<<dim3(M_TOT / 128, 2), 256, PROJ_SMEM>>>(G, O, Wo, bo, out);
}

// round 4
// speedup vs baseline: 1.3657x; 1.1147x over previous
#include <cuda_runtime.h>
#include <cuda_bf16.h>
#include <cstdint>
#include <math.h>

#define N_SEQ 384
#define C_DIM 128
#define H_NUM 4
#define DH_NUM 32
#define R_RANK 96
#define SD_DIM 449
#define ZD_DIM 577
#define MLP_H 256
#define HR_DIM 384
#define M_TOT (N_SEQ * N_SEQ)   // 147456

typedef __nv_bfloat16 bf16;

// ---------------- scratch (device globals) ----------------
__device__ bf16  g_xh[(size_t)M_TOT * C_DIM];
__device__ bf16  g_xl[(size_t)M_TOT * C_DIM];
__device__ float g_Z[2 * N_SEQ * ZD_DIM];        // combined zq|zk (768 x 577)
__device__ float g_H1[2 * N_SEQ * MLP_H];        // combined hidden
__device__ float g_H2[2 * N_SEQ * MLP_H];
__device__ float g_QKB[2 * N_SEQ * HR_DIM];      // rows 0-383 qb, 384-767 kb
__device__ float g_bias[(size_t)H_NUM * N_SEQ * N_SEQ];
__device__ bf16  g_Qh[(size_t)M_TOT * C_DIM];
__device__ bf16  g_Ql[(size_t)M_TOT * C_DIM];
__device__ bf16  g_Kh[(size_t)M_TOT * C_DIM];
__device__ bf16  g_Kl[(size_t)M_TOT * C_DIM];
__device__ bf16  g_Vh[(size_t)M_TOT * C_DIM];
__device__ bf16  g_Vl[(size_t)M_TOT * C_DIM];
__device__ float g_G[(size_t)M_TOT * C_DIM];
__device__ float g_O[(size_t)M_TOT * C_DIM];

// ---------------- helpers ----------------
__device__ __forceinline__ uint32_t pk2(float a, float b) {
    __nv_bfloat162 t = __floats2bfloat162_rn(a, b);
    return *reinterpret_cast<uint32_t*>(&t);
}
__device__ __forceinline__ float bhi(float x) {
    return __bfloat162float(__float2bfloat16(x));
}
__device__ __forceinline__ void mma_bf16(float* c, const uint32_t* a, uint32_t b0, uint32_t b1) {
    asm volatile(
        "mma.sync.aligned.m16n8k16.row.col.f32.bf16.bf16.f32 "
        "{%0,%1,%2,%3},{%4,%5,%6,%7},{%8,%9},{%0,%1,%2,%3};"
        : "+f"(c[0]), "+f"(c[1]), "+f"(c[2]), "+f"(c[3])
        : "r"(a[0]), "r"(a[1]), "r"(a[2]), "r"(a[3]), "r"(b0), "r"(b1));
}

// ---------------- LayerNorm -> split bf16 hi/lo ----------------
__global__ void ln_kernel(const float* __restrict__ x, const float* __restrict__ gamma,
                          const float* __restrict__ beta,
                          bf16* __restrict__ xh, bf16* __restrict__ xl) {
    size_t pix = (size_t)blockIdx.x * 8 + (threadIdx.x >> 5);
    int l = threadIdx.x & 31;
    const float4* xp = reinterpret_cast<const float4*>(x + pix * 128);
    float4 v = xp[l];
    float s = v.x + v.y + v.z + v.w;
    float s2 = v.x * v.x + v.y * v.y + v.z * v.z + v.w * v.w;
#pragma unroll
    for (int o = 16; o; o >>= 1) {
        s  += __shfl_xor_sync(0xffffffffu, s, o);
        s2 += __shfl_xor_sync(0xffffffffu, s2, o);
    }
    float mu = s * (1.f / 128.f);
    float var = s2 * (1.f / 128.f) - mu * mu;
    float rs = rsqrtf(var + 1e-5f);
    float4 gm = reinterpret_cast<const float4*>(gamma)[l];
    float4 bt = reinterpret_cast<const float4*>(beta)[l];
    float o0 = (v.x - mu) * rs * gm.x + bt.x;
    float o1 = (v.y - mu) * rs * gm.y + bt.y;
    float o2 = (v.z - mu) * rs * gm.z + bt.z;
    float o3 = (v.w - mu) * rs * gm.w + bt.w;
    size_t base = pix * 128 + 4 * l;
    *(uint32_t*)&xh[base]     = pk2(o0, o1);
    *(uint32_t*)&xh[base + 2] = pk2(o2, o3);
    *(uint32_t*)&xl[base]     = pk2(o0 - bhi(o0), o1 - bhi(o1));
    *(uint32_t*)&xl[base + 2] = pk2(o2 - bhi(o2), o3 - bhi(o3));
}

// ---------------- fused row/col means + concat s_inputs -> Z (768 x 577) ----------------
__global__ void meanz_kernel(const bf16* __restrict__ xh, const bf16* __restrict__ xl,
                             const float* __restrict__ s_inputs, float* __restrict__ Z) {
    int c = threadIdx.x;      // 128
    int idx = blockIdx.x;     // 0..767 ; <384 row-mean (q side), >=384 col-mean (k side)
    float s = 0.f;
    if (idx < N_SEQ) {
        size_t base = (size_t)idx * N_SEQ * C_DIM;
        for (int j = 0; j < N_SEQ; j++) {
            size_t e = base + (size_t)j * C_DIM + c;
            s += __bfloat162float(xh[e]) + __bfloat162float(xl[e]);
        }
    } else {
        int j = idx - N_SEQ;
        for (int i = 0; i < N_SEQ; i++) {
            size_t e = ((size_t)i * N_SEQ + j) * C_DIM + c;
            s += __bfloat162float(xh[e]) + __bfloat162float(xl[e]);
        }
    }
    Z[(size_t)idx * ZD_DIM + c] = s * (1.f / N_SEQ);
    int n = (idx < N_SEQ) ? idx : idx - N_SEQ;
    for (int t = c; t < SD_DIM; t += 128)
        Z[(size_t)idx * ZD_DIM + C_DIM + t] = s_inputs[n * SD_DIM + t];
}

// ---------------- TC MLP layer: C = act(A @ W), q/k fused along M ----------------
// A: combined (768 x K), W selected per block-half; bf16-split 3-pass.
__global__ __launch_bounds__(256) void mlp_tc(
    const float* __restrict__ A, const float* __restrict__ Wq, const float* __restrict__ Wk,
    float* __restrict__ C, int K, int Nout, int act) {
    __shared__ bf16 As[128][34];   // rows 0-63 hi, 64-127 lo ; [m][k]
    __shared__ bf16 Bs[128][34];   // rows 0-63 hi, 64-127 lo ; [n][k]
    int m0 = blockIdx.x * 64;
    int n0 = blockIdx.y * 64;
    const float* W = (blockIdx.x < 6) ? Wq : Wk;
    int tid = threadIdx.x;
    int w = tid >> 5, lane = tid & 31, g = lane >> 2, tg = lane & 3;
    int wm = (w & 3) * 16, wn = (w >> 2) * 32;
    float acc[4][4];
#pragma unroll
    for (int ni = 0; ni < 4; ni++)
#pragma unroll
        for (int j = 0; j < 4; j++) acc[ni][j] = 0.f;

    for (int k0 = 0; k0 < K; k0 += 32) {
        for (int e = tid; e < 2048; e += 256) {
            int r = e >> 5, c = e & 31;
            int gk = k0 + c;
            float v = (gk < K) ? A[(size_t)(m0 + r) * K + gk] : 0.f;
            bf16 h = __float2bfloat16(v);
            As[r][c] = h;
            As[64 + r][c] = __float2bfloat16(v - __bfloat162float(h));
        }
        for (int e = tid; e < 2048; e += 256) {
            int k = e >> 6, n = e & 63;
            int gk = k0 + k;
            float v = (gk < K) ? W[(size_t)gk * Nout + n0 + n] : 0.f;
            bf16 h = __float2bfloat16(v);
            Bs[n][k] = h;
            Bs[64 + n][k] = __float2bfloat16(v - __bfloat162float(h));
        }
        __syncthreads();
#pragma unroll
        for (int p = 0; p < 3; p++) {
            int ao = (p == 2) ? 64 : 0;
            int bo = (p == 1) ? 64 : 0;
#pragma unroll
            for (int kc = 0; kc < 2; kc++) {
                int k2 = kc * 16 + tg * 2;
                uint32_t a[4];
                int ar = ao + wm;
                a[0] = *(const uint32_t*)&As[ar + g][k2];
                a[1] = *(const uint32_t*)&As[ar + g + 8][k2];
                a[2] = *(const uint32_t*)&As[ar + g][k2 + 8];
                a[3] = *(const uint32_t*)&As[ar + g + 8][k2 + 8];
#pragma unroll
                for (int ni = 0; ni < 4; ni++) {
                    int bn = bo + wn + ni * 8 + g;
                    uint32_t b0 = *(const uint32_t*)&Bs[bn][k2];
                    uint32_t b1 = *(const uint32_t*)&Bs[bn][k2 + 8];
                    mma_bf16(acc[ni], a, b0, b1);
                }
            }
        }
        __syncthreads();
    }
#pragma unroll
    for (int ni = 0; ni < 4; ni++) {
        int col = n0 + wn + ni * 8 + tg * 2;
        size_t r0 = (size_t)(m0 + wm + g) * Nout + col;
        size_t r1 = r0 + (size_t)8 * Nout;
        float v0 = acc[ni][0], v1 = acc[ni][1], v2 = acc[ni][2], v3 = acc[ni][3];
        if (act) { v0 = tanhf(v0); v1 = tanhf(v1); v2 = tanhf(v2); v3 = tanhf(v3); }
        *(float2*)&C[r0] = make_float2(v0, v1);
        *(float2*)&C[r1] = make_float2(v2, v3);
    }
}

// ---------------- low-rank bias matrix ----------------
__global__ void bias_kernel(const float* __restrict__ qb, const float* __restrict__ kb,
                            float* __restrict__ B) {
    __shared__ float qs[32][97];
    __shared__ float ks[64][97];
    int h = blockIdx.x, q0 = blockIdx.y * 32, k0 = blockIdx.z * 64;
    for (int e = threadIdx.x; e < 32 * 96; e += 256) {
        int q = e / 96, r = e % 96;
        qs[q][r] = qb[(q0 + q) * HR_DIM + h * R_RANK + r];
    }
    for (int e = threadIdx.x; e < 64 * 96; e += 256) {
        int k = e / 96, r = e % 96;
        ks[k][r] = kb[(k0 + k) * HR_DIM + h * R_RANK + r];
    }
    __syncthreads();
    int ki = threadIdx.x & 63, qg = threadIdx.x >> 6;
    float acc[8];
#pragma unroll
    for (int u = 0; u < 8; u++) acc[u] = 0.f;
    for (int r = 0; r < 96; r++) {
        float kv = ks[ki][r];
#pragma unroll
        for (int u = 0; u < 8; u++) acc[u] = fmaf(kv, qs[qg * 8 + u][r], acc[u]);
    }
#pragma unroll
    for (int u = 0; u < 8; u++)
        B[((size_t)h * N_SEQ + q0 + qg * 8 + u) * N_SEQ + k0 + ki] = acc[u];
}

// ---------------- tensor-core q/k/v/g projection (bf16-split, 3-pass) ----------------
__global__ __launch_bounds__(256) void proj_tc(
    const bf16* __restrict__ xh, const bf16* __restrict__ xl,
    const float* __restrict__ Wq, const float* __restrict__ Wk,
    const float* __restrict__ Wv, const float* __restrict__ Wg,
    const float* __restrict__ bg,
    bf16* __restrict__ Qh, bf16* __restrict__ Ql,
    bf16* __restrict__ Kh, bf16* __restrict__ Kl,
    bf16* __restrict__ Vh, bf16* __restrict__ Vl,
    float* __restrict__ G) {
    extern __shared__ bf16 sm[];
    bf16 (*As)[136] = reinterpret_cast<bf16(*)[136]>(sm);             // rows 0-127 hi, 128-255 lo
    bf16 (*Bs)[136] = reinterpret_cast<bf16(*)[136]>(sm + 256 * 136); // rows 0-63 hi, 64-127 lo (n-major)
    int mb = blockIdx.x;
    int which = blockIdx.y >> 1, n0 = (blockIdx.y & 1) * 64;
    const float* W = (which == 0) ? Wq : (which == 1) ? Wk : (which == 2) ? Wv : Wg;
    int tid = threadIdx.x;
    size_t abase = (size_t)mb * 128 * 128;
    for (int e = tid; e < 2048; e += 256) {
        int r = e >> 4, c8 = (e & 15) * 8;
        *(uint4*)&As[r][c8]       = *(const uint4*)&xh[abase + (size_t)r * 128 + c8];
        *(uint4*)&As[128 + r][c8] = *(const uint4*)&xl[abase + (size_t)r * 128 + c8];
    }
    for (int e = tid; e < 8192; e += 256) {
        int k = e >> 6, n = e & 63;
        float wv = W[k * 128 + n0 + n];
        bf16 h = __float2bfloat16(wv);
        Bs[n][k] = h;
        Bs[64 + n][k] = __float2bfloat16(wv - __bfloat162float(h));
    }
    __syncthreads();
    int w = tid >> 5, lane = tid & 31, g = lane >> 2, tg = lane & 3;
    int wm = (w & 3) * 32, wn = (w >> 2) * 32;
    float acc[2][4][4];
#pragma unroll
    for (int mi = 0; mi < 2; mi++)
#pragma unroll
        for (int ni = 0; ni < 4; ni++)
#pragma unroll
            for (int j = 0; j < 4; j++) acc[mi][ni][j] = 0.f;
#pragma unroll
    for (int p = 0; p < 3; p++) {
        int ao = (p == 2) ? 128 : 0;
        int bo = (p == 1) ? 64 : 0;
#pragma unroll
        for (int kc = 0; kc < 8; kc++) {
            int k2 = kc * 16 + tg * 2;
            uint32_t a[2][4], b[4][2];
#pragma unroll
            for (int mi = 0; mi < 2; mi++) {
                int r = ao + wm + mi * 16;
                a[mi][0] = *(const uint32_t*)&As[r + g][k2];
                a[mi][1] = *(const uint32_t*)&As[r + g + 8][k2];
                a[mi][2] = *(const uint32_t*)&As[r + g][k2 + 8];
                a[mi][3] = *(const uint32_t*)&As[r + g + 8][k2 + 8];
            }
#pragma unroll
            for (int ni = 0; ni < 4; ni++) {
                int rn = bo + wn + ni * 8 + g;
                b[ni][0] = *(const uint32_t*)&Bs[rn][k2];
                b[ni][1] = *(const uint32_t*)&Bs[rn][k2 + 8];
            }
#pragma unroll
            for (int mi = 0; mi < 2; mi++)
#pragma unroll
                for (int ni = 0; ni < 4; ni++)
                    mma_bf16(acc[mi][ni], a[mi], b[ni][0], b[ni][1]);
        }
    }
    const float qscale = 0.17677669529663687f;  // 1/sqrt(32)
#pragma unroll
    for (int mi = 0; mi < 2; mi++)
#pragma unroll
    for (int ni = 0; ni < 4; ni++) {
        size_t row0 = (size_t)mb * 128 + wm + mi * 16 + g;
        int col = n0 + wn + ni * 8 + tg * 2;
        float* c = acc[mi][ni];
        if (which == 0) { c[0] *= qscale; c[1] *= qscale; c[2] *= qscale; c[3] *= qscale; }
        if (which == 3) {
            float b0v = bg[col], b1v = bg[col + 1];
            float g0 = 1.f / (1.f + expf(-(c[0] + b0v)));
            float g1 = 1.f / (1.f + expf(-(c[1] + b1v)));
            float g2 = 1.f / (1.f + expf(-(c[2] + b0v)));
            float g3 = 1.f / (1.f + expf(-(c[3] + b1v)));
            *(float2*)&G[row0 * 128 + col] = make_float2(g0, g1);
            *(float2*)&G[(row0 + 8) * 128 + col] = make_float2(g2, g3);
        } else {
            bf16* Oh = (which == 0) ? Qh : (which == 1) ? Kh : Vh;
            bf16* Ol = (which == 0) ? Ql : (which == 1) ? Kl : Vl;
            *(uint32_t*)&Oh[row0 * 128 + col] = pk2(c[0], c[1]);
            *(uint32_t*)&Ol[row0 * 128 + col] = pk2(c[0] - bhi(c[0]), c[1] - bhi(c[1]));
            *(uint32_t*)&Oh[(row0 + 8) * 128 + col] = pk2(c[2], c[3]);
            *(uint32_t*)&Ol[(row0 + 8) * 128 + col] = pk2(c[2] - bhi(c[2]), c[3] - bhi(c[3]));
        }
    }
}

// ---------------- tensor-core flash attention ----------------
__global__ __launch_bounds__(256) void attn_tc(
    const bf16* __restrict__ Qh, const bf16* __restrict__ Ql,
    const bf16* __restrict__ Kh, const bf16* __restrict__ Kl,
    const bf16* __restrict__ Vh, const bf16* __restrict__ Vl,
    const float* __restrict__ B, float* __restrict__ O) {
    __shared__ bf16 Qs[256][40];   // rows 0-127 hi, 128-255 lo ; [qrow][d]
    __shared__ bf16 Ks[128][40];   // rows 0-63 hi, 64-127 lo   ; [kpos][d]
    __shared__ bf16 Vs[64][72];    // rows 0-31 hi, 32-63 lo    ; [d][kpos]
    int qt = blockIdx.x, h = blockIdx.y, i = blockIdx.z;
    int q0 = qt * 128, tid = threadIdx.x;
    size_t qgb = ((size_t)(i * N_SEQ + q0)) * 128 + h * 32;
    for (int e = tid; e < 512; e += 256) {
        int r = e >> 2, c8 = (e & 3) * 8;
        *(uint4*)&Qs[r][c8]       = *(const uint4*)&Qh[qgb + (size_t)r * 128 + c8];
        *(uint4*)&Qs[128 + r][c8] = *(const uint4*)&Ql[qgb + (size_t)r * 128 + c8];
    }
    int w = tid >> 5, lane = tid & 31, g = lane >> 2, tg = lane & 3;
    int qr = w * 16;
    __syncthreads();
    uint32_t qa[2][2][4];
#pragma unroll
    for (int s = 0; s < 2; s++)
#pragma unroll
        for (int kc = 0; kc < 2; kc++) {
            int r = s * 128 + qr;
            int k2 = kc * 16 + tg * 2;
            qa[s][kc][0] = *(const uint32_t*)&Qs[r + g][k2];
            qa[s][kc][1] = *(const uint32_t*)&Qs[r + g + 8][k2];
            qa[s][kc][2] = *(const uint32_t*)&Qs[r + g][k2 + 8];
            qa[s][kc][3] = *(const uint32_t*)&Qs[r + g + 8][k2 + 8];
        }
    float oacc[4][4];
#pragma unroll
    for (int ni = 0; ni < 4; ni++)
#pragma unroll
        for (int j = 0; j < 4; j++) oacc[ni][j] = 0.f;
    float m0 = -1e30f, m1 = -1e30f, l0 = 0.f, l1 = 0.f;
    const float L2E = 1.4426950408889634f;
    size_t brow0 = ((size_t)h * N_SEQ + q0 + qr + g) * N_SEQ;
    size_t brow1 = brow0 + (size_t)8 * N_SEQ;

    for (int kt = 0; kt < 6; kt++) {
        int k0 = kt * 64;
        __syncthreads();
        size_t kb = ((size_t)(i * N_SEQ + k0)) * 128 + h * 32;
        {   // K tile: 64x32 hi/lo
            int r = tid >> 2, c8 = (tid & 3) * 8;
            if (tid < 256) {
                *(uint4*)&Ks[r][c8]      = *(const uint4*)&Kh[kb + (size_t)r * 128 + c8];
                *(uint4*)&Ks[64 + r][c8] = *(const uint4*)&Kl[kb + (size_t)r * 128 + c8];
            }
        }
        {   // V tile transpose: [kpos][d] -> Vs[d][kpos]
            int r = tid >> 2, d0 = (tid & 3) * 8;
            uint4 vh4 = *(const uint4*)&Vh[kb + (size_t)r * 128 + d0];
            uint4 vl4 = *(const uint4*)&Vl[kb + (size_t)r * 128 + d0];
            const bf16* ph = (const bf16*)&vh4;
            const bf16* pl = (const bf16*)&vl4;
#pragma unroll
            for (int u = 0; u < 8; u++) {
                Vs[d0 + u][r] = ph[u];
                Vs[32 + d0 + u][r] = pl[u];
            }
        }
        __syncthreads();

        float sc[8][4];
#pragma unroll
        for (int nf = 0; nf < 8; nf++) {   // init scores with bias
            int col = k0 + nf * 8 + tg * 2;
            float2 b0 = *(const float2*)&B[brow0 + col];
            float2 b1 = *(const float2*)&B[brow1 + col];
            sc[nf][0] = b0.x; sc[nf][1] = b0.y; sc[nf][2] = b1.x; sc[nf][3] = b1.y;
        }
#pragma unroll
        for (int p = 0; p < 3; p++) {      // QK^T: hh, hl, lh
            int aso = (p == 2) ? 1 : 0;
            int kso = (p == 1) ? 64 : 0;
#pragma unroll
            for (int kc = 0; kc < 2; kc++) {
                int k2 = kc * 16 + tg * 2;
#pragma unroll
                for (int nf = 0; nf < 8; nf++) {
                    uint32_t b0 = *(const uint32_t*)&Ks[kso + nf * 8 + g][k2];
                    uint32_t b1 = *(const uint32_t*)&Ks[kso + nf * 8 + g][k2 + 8];
                    mma_bf16(sc[nf], qa[aso][kc], b0, b1);
                }
            }
        }
        // online softmax
        float nm0 = m0, nm1 = m1;
#pragma unroll
        for (int nf = 0; nf < 8; nf++) {
            nm0 = fmaxf(nm0, fmaxf(sc[nf][0], sc[nf][1]));
            nm1 = fmaxf(nm1, fmaxf(sc[nf][2], sc[nf][3]));
        }
        nm0 = fmaxf(nm0, __shfl_xor_sync(0xffffffffu, nm0, 1));
        nm0 = fmaxf(nm0, __shfl_xor_sync(0xffffffffu, nm0, 2));
        nm1 = fmaxf(nm1, __shfl_xor_sync(0xffffffffu, nm1, 1));
        nm1 = fmaxf(nm1, __shfl_xor_sync(0xffffffffu, nm1, 2));
        float cor0 = exp2f((m0 - nm0) * L2E);
        float cor1 = exp2f((m1 - nm1) * L2E);
        m0 = nm0; m1 = nm1;
        l0 *= cor0; l1 *= cor1;
#pragma unroll
        for (int ni = 0; ni < 4; ni++) {
            oacc[ni][0] *= cor0; oacc[ni][1] *= cor0;
            oacc[ni][2] *= cor1; oacc[ni][3] *= cor1;
        }
#pragma unroll
        for (int nf = 0; nf < 8; nf++) {
            sc[nf][0] = exp2f((sc[nf][0] - m0) * L2E);
            sc[nf][1] = exp2f((sc[nf][1] - m0) * L2E);
            sc[nf][2] = exp2f((sc[nf][2] - m1) * L2E);
            sc[nf][3] = exp2f((sc[nf][3] - m1) * L2E);
            l0 += sc[nf][0] + sc[nf][1];
            l1 += sc[nf][2] + sc[nf][3];
        }
        // PV: split P into hi/lo, 3 passes (PhVh, PhVl, PlVh)
#pragma unroll
        for (int kc = 0; kc < 4; kc++) {
            float* f0 = sc[2 * kc];
            float* f1 = sc[2 * kc + 1];
            uint32_t pah[4], pal[4];
            pah[0] = pk2(f0[0], f0[1]); pah[1] = pk2(f0[2], f0[3]);
            pah[2] = pk2(f1[0], f1[1]); pah[3] = pk2(f1[2], f1[3]);
            pal[0] = pk2(f0[0] - bhi(f0[0]), f0[1] - bhi(f0[1]));
            pal[1] = pk2(f0[2] - bhi(f0[2]), f0[3] - bhi(f0[3]));
            pal[2] = pk2(f1[0] - bhi(f1[0]), f1[1] - bhi(f1[1]));
            pal[3] = pk2(f1[2] - bhi(f1[2]), f1[3] - bhi(f1[3]));
            int k2 = kc * 16 + tg * 2;
#pragma unroll
            for (int ni = 0; ni < 4; ni++) {
                uint32_t bh0 = *(const uint32_t*)&Vs[ni * 8 + g][k2];
                uint32_t bh1 = *(const uint32_t*)&Vs[ni * 8 + g][k2 + 8];
                uint32_t bl0 = *(const uint32_t*)&Vs[32 + ni * 8 + g][k2];
                uint32_t bl1 = *(const uint32_t*)&Vs[32 + ni * 8 + g][k2 + 8];
                mma_bf16(oacc[ni], pah, bh0, bh1);
                mma_bf16(oacc[ni], pah, bl0, bl1);
                mma_bf16(oacc[ni], pal, bh0, bh1);
            }
        }
    }
    l0 += __shfl_xor_sync(0xffffffffu, l0, 1);
    l0 += __shfl_xor_sync(0xffffffffu, l0, 2);
    l1 += __shfl_xor_sync(0xffffffffu, l1, 1);
    l1 += __shfl_xor_sync(0xffffffffu, l1, 2);
    float i0 = 1.f / l0, i1 = 1.f / l1;
    size_t ob0 = ((size_t)(i * N_SEQ + q0 + qr + g)) * 128 + h * 32;
    size_t ob1 = ob0 + 8 * 128;
#pragma unroll
    for (int ni = 0; ni < 4; ni++) {
        int d = ni * 8 + tg * 2;
        *(float2*)&O[ob0 + d] = make_float2(oacc[ni][0] * i0, oacc[ni][1] * i0);
        *(float2*)&O[ob1 + d] = make_float2(oacc[ni][2] * i1, oacc[ni][3] * i1);
    }
}

// ---------------- tensor-core output GEMM: out = (g.*o) @ Wo + bo ----------------
__global__ __launch_bounds__(256) void out_tc(
    const float* __restrict__ G, const float* __restrict__ O,
    const float* __restrict__ Wo, const float* __restrict__ bo,
    float* __restrict__ out) {
    extern __shared__ bf16 sm[];
    bf16 (*As)[136] = reinterpret_cast<bf16(*)[136]>(sm);
    bf16 (*Bs)[136] = reinterpret_cast<bf16(*)[136]>(sm + 256 * 136);
    int mb = blockIdx.x;
    int n0 = blockIdx.y * 64;
    int tid = threadIdx.x;
    size_t abase = (size_t)mb * 128 * 128;
    for (int e = tid; e < 4096; e += 256) {
        int r = e >> 5, c4 = (e & 31) * 4;
        float4 g4 = *(const float4*)&G[abase + (size_t)r * 128 + c4];
        float4 o4 = *(const float4*)&O[abase + (size_t)r * 128 + c4];
        float a0 = g4.x * o4.x, a1 = g4.y * o4.y, a2 = g4.z * o4.z, a3 = g4.w * o4.w;
        *(uint32_t*)&As[r][c4]           = pk2(a0, a1);
        *(uint32_t*)&As[r][c4 + 2]       = pk2(a2, a3);
        *(uint32_t*)&As[128 + r][c4]     = pk2(a0 - bhi(a0), a1 - bhi(a1));
        *(uint32_t*)&As[128 + r][c4 + 2] = pk2(a2 - bhi(a2), a3 - bhi(a3));
    }
    for (int e = tid; e < 8192; e += 256) {
        int k = e >> 6, n = e & 63;
        float wv = Wo[k * 128 + n0 + n];
        bf16 h = __float2bfloat16(wv);
        Bs[n][k] = h;
        Bs[64 + n][k] = __float2bfloat16(wv - __bfloat162float(h));
    }
    __syncthreads();
    int w = tid >> 5, lane = tid & 31, g = lane >> 2, tg = lane & 3;
    int wm = (w & 3) * 32, wn = (w >> 2) * 32;
    float acc[2][4][4];
#pragma unroll
    for (int mi = 0; mi < 2; mi++)
#pragma unroll
        for (int ni = 0; ni < 4; ni++)
#pragma unroll
            for (int j = 0; j < 4; j++) acc[mi][ni][j] = 0.f;
#pragma unroll
    for (int p = 0; p < 3; p++) {
        int ao = (p == 2) ? 128 : 0;
        int bo2 = (p == 1) ? 64 : 0;
#pragma unroll
        for (int kc = 0; kc < 8; kc++) {
            int k2 = kc * 16 + tg * 2;
            uint32_t a[2][4], b[4][2];
#pragma unroll
            for (int mi = 0; mi < 2; mi++) {
                int r = ao + wm + mi * 16;
                a[mi][0] = *(const uint32_t*)&As[r + g][k2];
                a[mi][1] = *(const uint32_t*)&As[r + g + 8][k2];
                a[mi][2] = *(const uint32_t*)&As[r + g][k2 + 8];
                a[mi][3] = *(const uint32_t*)&As[r + g + 8][k2 + 8];
            }
#pragma unroll
            for (int ni = 0; ni < 4; ni++) {
                int rn = bo2 + wn + ni * 8 + g;
                b[ni][0] = *(const uint32_t*)&Bs[rn][k2];
                b[ni][1] = *(const uint32_t*)&Bs[rn][k2 + 8];
            }
#pragma unroll
            for (int mi = 0; mi < 2; mi++)
#pragma unroll
                for (int ni = 0; ni < 4; ni++)
                    mma_bf16(acc[mi][ni], a[mi], b[ni][0], b[ni][1]);
        }
    }
#pragma unroll
    for (int mi = 0; mi < 2; mi++)
#pragma unroll
    for (int ni = 0; ni < 4; ni++) {
        size_t row0 = (size_t)mb * 128 + wm + mi * 16 + g;
        int col = n0 + wn + ni * 8 + tg * 2;
        float b0v = bo[col], b1v = bo[col + 1];
        float* c = acc[mi][ni];
        *(float2*)&out[row0 * 128 + col] = make_float2(c[0] + b0v, c[1] + b1v);
        *(float2*)&out[(row0 + 8) * 128 + col] = make_float2(c[2] + b0v, c[3] + b1v);
    }
}

// ---------------- launch ----------------
extern "C" void kernel_launch(void* const* d_in, const int* in_sizes, int n_in,
                              void* d_out, int out_size) {
    const float* x        = (const float*)d_in[0];
    const float* s_inputs = (const float*)d_in[1];
    const float* gamma    = (const float*)d_in[2];
    const float* beta     = (const float*)d_in[3];
    const float* Wq1      = (const float*)d_in[4];
    const float* Wq2      = (const float*)d_in[5];
    const float* Wq3      = (const float*)d_in[6];
    const float* Wk1      = (const float*)d_in[7];
    const float* Wk2      = (const float*)d_in[8];
    const float* Wk3      = (const float*)d_in[9];
    const float* Wq_att   = (const float*)d_in[10];
    const float* Wk_att   = (const float*)d_in[11];
    const float* Wv_att   = (const float*)d_in[12];
    const float* Wg       = (const float*)d_in[13];
    const float* bg       = (const float*)d_in[14];
    const float* Wo       = (const float*)d_in[15];
    const float* bo       = (const float*)d_in[16];
    float* out = (float*)d_out;

    bf16 *xh, *xl, *Qh, *Ql, *Kh, *Kl, *Vh, *Vl;
    float *Z, *H1, *H2, *QKB, *bias, *G, *O;
    cudaGetSymbolAddress((void**)&xh, g_xh);
    cudaGetSymbolAddress((void**)&xl, g_xl);
    cudaGetSymbolAddress((void**)&Z, g_Z);
    cudaGetSymbolAddress((void**)&H1, g_H1);
    cudaGetSymbolAddress((void**)&H2, g_H2);
    cudaGetSymbolAddress((void**)&QKB, g_QKB);
    cudaGetSymbolAddress((void**)&bias, g_bias);
    cudaGetSymbolAddress((void**)&Qh, g_Qh);
    cudaGetSymbolAddress((void**)&Ql, g_Ql);
    cudaGetSymbolAddress((void**)&Kh, g_Kh);
    cudaGetSymbolAddress((void**)&Kl, g_Kl);
    cudaGetSymbolAddress((void**)&Vh, g_Vh);
    cudaGetSymbolAddress((void**)&Vl, g_Vl);
    cudaGetSymbolAddress((void**)&G, g_G);
    cudaGetSymbolAddress((void**)&O, g_O);

    const int PROJ_SMEM = (256 * 136 + 128 * 136) * 2;  // 104448 bytes
    cudaFuncSetAttribute(proj_tc, cudaFuncAttributeMaxDynamicSharedMemorySize, PROJ_SMEM);
    cudaFuncSetAttribute(out_tc, cudaFuncAttributeMaxDynamicSharedMemorySize, PROJ_SMEM);

    // launch #1
    ln_kernel<<<M_TOT / 8, 256>>>(x, gamma, beta, xh, xl);
    // #2: fused means + concat
    meanz_kernel<<<2 * N_SEQ, 128>>>(xh, xl, s_inputs, Z);
    // #3-#5: fused q/k MLP chain on tensor cores
    mlp_tc<<<dim3(12, 4), 256>>>(Z, Wq1, Wk1, H1, ZD_DIM, MLP_H, 1);
    mlp_tc<<<dim3(12, 4), 256>>>(H1, Wq2, Wk2, H2, MLP_H, MLP_H, 1);
    mlp_tc<<<dim3(12, 6), 256>>>(H2, Wq3, Wk3, QKB, MLP_H, HR_DIM, 0);
    // #6: projections (ncu -s 5 -c 1 captures this launch)
    proj_tc<<<dim3(M_TOT / 128, 8), 256, PROJ_SMEM>>>(xh, xl, Wq_att, Wk_att, Wv_att, Wg, bg,
                                                      Qh, Ql, Kh, Kl, Vh, Vl, G);
    // #7: low-rank bias matrix
    bias_kernel<<<dim3(H_NUM, N_SEQ / 32, N_SEQ / 64), 256>>>(QKB, QKB + N_SEQ * HR_DIM, bias);
    // #8: attention
    attn_tc<<<dim3(3, H_NUM, N_SEQ), 256>>>(Qh, Ql, Kh, Kl, Vh, Vl, bias, O);
    // #9: gated output projection
    out_tc<<<dim3(M_TOT / 128, 2), 256, PROJ_SMEM>>>(G, O, Wo, bo, out);
}

// round 5
// speedup vs baseline: 1.4569x; 1.0668x over previous
#include <cuda_runtime.h>
#include <cuda_bf16.h>
#include <cstdint>
#include <math.h>

#define N_SEQ 384
#define C_DIM 128
#define H_NUM 4
#define DH_NUM 32
#define R_RANK 96
#define SD_DIM 449
#define ZD_DIM 577
#define MLP_H 256
#define HR_DIM 384
#define M_TOT (N_SEQ * N_SEQ)   // 147456

typedef __nv_bfloat16 bf16;

// ---------------- scratch (device globals) ----------------
__device__ bf16  g_xh[(size_t)M_TOT * C_DIM];
__device__ bf16  g_xl[(size_t)M_TOT * C_DIM];
__device__ float g_Z[2 * N_SEQ * ZD_DIM];
__device__ float g_H1[2 * N_SEQ * MLP_H];
__device__ float g_H2[2 * N_SEQ * MLP_H];
__device__ float g_QKB[2 * N_SEQ * HR_DIM];
__device__ float g_bias[(size_t)H_NUM * N_SEQ * N_SEQ];
__device__ bf16  g_Qh[(size_t)M_TOT * C_DIM];
__device__ bf16  g_Ql[(size_t)M_TOT * C_DIM];
__device__ bf16  g_Kh[(size_t)M_TOT * C_DIM];
__device__ bf16  g_Kl[(size_t)M_TOT * C_DIM];
__device__ bf16  g_Vh[(size_t)M_TOT * C_DIM];
__device__ bf16  g_Vl[(size_t)M_TOT * C_DIM];
__device__ float g_G[(size_t)M_TOT * C_DIM];
__device__ float g_O[(size_t)M_TOT * C_DIM];
__device__ bf16  g_Wh[5 * 128 * 128];   // pre-split weights, n-major [w][n][k]
__device__ bf16  g_Wl[5 * 128 * 128];

// ---------------- helpers ----------------
__device__ __forceinline__ uint32_t pk2(float a, float b) {
    __nv_bfloat162 t = __floats2bfloat162_rn(a, b);
    return *reinterpret_cast<uint32_t*>(&t);
}
__device__ __forceinline__ float bhi(float x) {
    return __bfloat162float(__float2bfloat16(x));
}
__device__ __forceinline__ void mma_bf16(float* c, const uint32_t* a, uint32_t b0, uint32_t b1) {
    asm volatile(
        "mma.sync.aligned.m16n8k16.row.col.f32.bf16.bf16.f32 "
        "{%0,%1,%2,%3},{%4,%5,%6,%7},{%8,%9},{%0,%1,%2,%3};"
        : "+f"(c[0]), "+f"(c[1]), "+f"(c[2]), "+f"(c[3])
        : "r"(a[0]), "r"(a[1]), "r"(a[2]), "r"(a[3]), "r"(b0), "r"(b1));
}
__device__ __forceinline__ void ldsm_x4(uint32_t& r0, uint32_t& r1, uint32_t& r2, uint32_t& r3,
                                        uint32_t addr) {
    asm volatile("ldmatrix.sync.aligned.m8n8.x4.shared.b16 {%0,%1,%2,%3}, [%4];"
                 : "=r"(r0), "=r"(r1), "=r"(r2), "=r"(r3) : "r"(addr));
}
__device__ __forceinline__ uint32_t sm_u32(const void* p) {
    return (uint32_t)__cvta_generic_to_shared(p);
}

// ---------------- pre-split attention weights (once) ----------------
__global__ void prep_w(const float* __restrict__ Wq, const float* __restrict__ Wk,
                       const float* __restrict__ Wv, const float* __restrict__ Wg,
                       const float* __restrict__ Wo,
                       bf16* __restrict__ Wh, bf16* __restrict__ Wl) {
    int idx = blockIdx.x * 256 + threadIdx.x;
    if (idx >= 5 * 16384) return;
    int w = idx >> 14, r = idx & 16383;
    int n = r >> 7, k = r & 127;
    const float* W = (w == 0) ? Wq : (w == 1) ? Wk : (w == 2) ? Wv : (w == 3) ? Wg : Wo;
    float v = W[k * 128 + n];
    bf16 h = __float2bfloat16(v);
    Wh[idx] = h;
    Wl[idx] = __float2bfloat16(v - __bfloat162float(h));
}

// ---------------- LayerNorm -> split bf16 hi/lo ----------------
__global__ void ln_kernel(const float* __restrict__ x, const float* __restrict__ gamma,
                          const float* __restrict__ beta,
                          bf16* __restrict__ xh, bf16* __restrict__ xl) {
    size_t pix = (size_t)blockIdx.x * 8 + (threadIdx.x >> 5);
    int l = threadIdx.x & 31;
    const float4* xp = reinterpret_cast<const float4*>(x + pix * 128);
    float4 v = xp[l];
    float s = v.x + v.y + v.z + v.w;
    float s2 = v.x * v.x + v.y * v.y + v.z * v.z + v.w * v.w;
#pragma unroll
    for (int o = 16; o; o >>= 1) {
        s  += __shfl_xor_sync(0xffffffffu, s, o);
        s2 += __shfl_xor_sync(0xffffffffu, s2, o);
    }
    float mu = s * (1.f / 128.f);
    float var = s2 * (1.f / 128.f) - mu * mu;
    float rs = rsqrtf(var + 1e-5f);
    float4 gm = reinterpret_cast<const float4*>(gamma)[l];
    float4 bt = reinterpret_cast<const float4*>(beta)[l];
    float o0 = (v.x - mu) * rs * gm.x + bt.x;
    float o1 = (v.y - mu) * rs * gm.y + bt.y;
    float o2 = (v.z - mu) * rs * gm.z + bt.z;
    float o3 = (v.w - mu) * rs * gm.w + bt.w;
    size_t base = pix * 128 + 4 * l;
    *(uint32_t*)&xh[base]     = pk2(o0, o1);
    *(uint32_t*)&xh[base + 2] = pk2(o2, o3);
    *(uint32_t*)&xl[base]     = pk2(o0 - bhi(o0), o1 - bhi(o1));
    *(uint32_t*)&xl[base + 2] = pk2(o2 - bhi(o2), o3 - bhi(o3));
}

// ---------------- fused row/col means + concat s_inputs -> Z ----------------
__global__ void meanz_kernel(const bf16* __restrict__ xh, const bf16* __restrict__ xl,
                             const float* __restrict__ s_inputs, float* __restrict__ Z) {
    int c = threadIdx.x;
    int idx = blockIdx.x;
    float s = 0.f;
    if (idx < N_SEQ) {
        size_t base = (size_t)idx * N_SEQ * C_DIM;
        for (int j = 0; j < N_SEQ; j++) {
            size_t e = base + (size_t)j * C_DIM + c;
            s += __bfloat162float(xh[e]) + __bfloat162float(xl[e]);
        }
    } else {
        int j = idx - N_SEQ;
        for (int i = 0; i < N_SEQ; i++) {
            size_t e = ((size_t)i * N_SEQ + j) * C_DIM + c;
            s += __bfloat162float(xh[e]) + __bfloat162float(xl[e]);
        }
    }
    Z[(size_t)idx * ZD_DIM + c] = s * (1.f / N_SEQ);
    int n = (idx < N_SEQ) ? idx : idx - N_SEQ;
    for (int t = c; t < SD_DIM; t += 128)
        Z[(size_t)idx * ZD_DIM + C_DIM + t] = s_inputs[n * SD_DIM + t];
}

// ---------------- TC MLP layer (q/k fused along M) ----------------
__global__ __launch_bounds__(256) void mlp_tc(
    const float* __restrict__ A, const float* __restrict__ Wq, const float* __restrict__ Wk,
    float* __restrict__ C, int K, int Nout, int act) {
    __shared__ __align__(16) bf16 As[128][34];
    __shared__ __align__(16) bf16 Bs[128][34];
    int m0 = blockIdx.x * 64;
    int n0 = blockIdx.y * 64;
    const float* W = (blockIdx.x < 6) ? Wq : Wk;
    int tid = threadIdx.x;
    int w = tid >> 5, lane = tid & 31, g = lane >> 2, tg = lane & 3;
    int wm = (w & 3) * 16, wn = (w >> 2) * 32;
    float acc[4][4];
#pragma unroll
    for (int ni = 0; ni < 4; ni++)
#pragma unroll
        for (int j = 0; j < 4; j++) acc[ni][j] = 0.f;

    for (int k0 = 0; k0 < K; k0 += 32) {
        for (int e = tid; e < 2048; e += 256) {
            int r = e >> 5, c = e & 31;
            int gk = k0 + c;
            float v = (gk < K) ? A[(size_t)(m0 + r) * K + gk] : 0.f;
            bf16 h = __float2bfloat16(v);
            As[r][c] = h;
            As[64 + r][c] = __float2bfloat16(v - __bfloat162float(h));
        }
        for (int e = tid; e < 2048; e += 256) {
            int k = e >> 6, n = e & 63;
            int gk = k0 + k;
            float v = (gk < K) ? W[(size_t)gk * Nout + n0 + n] : 0.f;
            bf16 h = __float2bfloat16(v);
            Bs[n][k] = h;
            Bs[64 + n][k] = __float2bfloat16(v - __bfloat162float(h));
        }
        __syncthreads();
#pragma unroll
        for (int p = 0; p < 3; p++) {
            int ao = (p == 2) ? 64 : 0;
            int bo = (p == 1) ? 64 : 0;
#pragma unroll
            for (int kc = 0; kc < 2; kc++) {
                int k2 = kc * 16 + tg * 2;
                uint32_t a[4];
                int ar = ao + wm;
                a[0] = *(const uint32_t*)&As[ar + g][k2];
                a[1] = *(const uint32_t*)&As[ar + g + 8][k2];
                a[2] = *(const uint32_t*)&As[ar + g][k2 + 8];
                a[3] = *(const uint32_t*)&As[ar + g + 8][k2 + 8];
#pragma unroll
                for (int ni = 0; ni < 4; ni++) {
                    int bn = bo + wn + ni * 8 + g;
                    uint32_t b0 = *(const uint32_t*)&Bs[bn][k2];
                    uint32_t b1 = *(const uint32_t*)&Bs[bn][k2 + 8];
                    mma_bf16(acc[ni], a, b0, b1);
                }
            }
        }
        __syncthreads();
    }
#pragma unroll
    for (int ni = 0; ni < 4; ni++) {
        int col = n0 + wn + ni * 8 + tg * 2;
        size_t r0 = (size_t)(m0 + wm + g) * Nout + col;
        size_t r1 = r0 + (size_t)8 * Nout;
        float v0 = acc[ni][0], v1 = acc[ni][1], v2 = acc[ni][2], v3 = acc[ni][3];
        if (act) { v0 = tanhf(v0); v1 = tanhf(v1); v2 = tanhf(v2); v3 = tanhf(v3); }
        *(float2*)&C[r0] = make_float2(v0, v1);
        *(float2*)&C[r1] = make_float2(v2, v3);
    }
}

// ---------------- low-rank bias matrix ----------------
__global__ void bias_kernel(const float* __restrict__ qb, const float* __restrict__ kb,
                            float* __restrict__ B) {
    __shared__ float qs[32][97];
    __shared__ float ks[64][97];
    int h = blockIdx.x, q0 = blockIdx.y * 32, k0 = blockIdx.z * 64;
    for (int e = threadIdx.x; e < 32 * 96; e += 256) {
        int q = e / 96, r = e % 96;
        qs[q][r] = qb[(q0 + q) * HR_DIM + h * R_RANK + r];
    }
    for (int e = threadIdx.x; e < 64 * 96; e += 256) {
        int k = e / 96, r = e % 96;
        ks[k][r] = kb[(k0 + k) * HR_DIM + h * R_RANK + r];
    }
    __syncthreads();
    int ki = threadIdx.x & 63, qg = threadIdx.x >> 6;
    float acc[8];
#pragma unroll
    for (int u = 0; u < 8; u++) acc[u] = 0.f;
    for (int r = 0; r < 96; r++) {
        float kv = ks[ki][r];
#pragma unroll
        for (int u = 0; u < 8; u++) acc[u] = fmaf(kv, qs[qg * 8 + u][r], acc[u]);
    }
#pragma unroll
    for (int u = 0; u < 8; u++)
        B[((size_t)h * N_SEQ + q0 + qg * 8 + u) * N_SEQ + k0 + ki] = acc[u];
}

// ---------------- tensor-core q/k/v/g projection (ldmatrix + prepped weights) ----------------
__global__ __launch_bounds__(256) void proj_tc(
    const bf16* __restrict__ xh, const bf16* __restrict__ xl,
    const bf16* __restrict__ WhAll, const bf16* __restrict__ WlAll,
    const float* __restrict__ bg,
    bf16* __restrict__ Qh, bf16* __restrict__ Ql,
    bf16* __restrict__ Kh, bf16* __restrict__ Kl,
    bf16* __restrict__ Vh, bf16* __restrict__ Vl,
    float* __restrict__ G) {
    extern __shared__ __align__(16) bf16 sm[];
    bf16 (*As)[136] = reinterpret_cast<bf16(*)[136]>(sm);             // rows 0-127 hi, 128-255 lo
    bf16 (*Bs)[136] = reinterpret_cast<bf16(*)[136]>(sm + 256 * 136); // rows 0-63 hi, 64-127 lo
    int mb = blockIdx.x;
    int which = blockIdx.y >> 1, n0 = (blockIdx.y & 1) * 64;
    const bf16* WhM = WhAll + which * 16384;
    const bf16* WlM = WlAll + which * 16384;
    int tid = threadIdx.x;
    size_t abase = (size_t)mb * 128 * 128;
    for (int e = tid; e < 2048; e += 256) {
        int r = e >> 4, c8 = (e & 15) * 8;
        *(uint4*)&As[r][c8]       = *(const uint4*)&xh[abase + (size_t)r * 128 + c8];
        *(uint4*)&As[128 + r][c8] = *(const uint4*)&xl[abase + (size_t)r * 128 + c8];
    }
    for (int e = tid; e < 2048; e += 256) {
        int r = e >> 4, c8 = (e & 15) * 8;
        const bf16* src = (r < 64) ? &WhM[(n0 + r) * 128 + c8] : &WlM[(n0 + r - 64) * 128 + c8];
        *(uint4*)&Bs[r][c8] = *(const uint4*)src;
    }
    __syncthreads();
    int w = tid >> 5, lane = tid & 31, g = lane >> 2, tg = lane & 3;
    int wm = (w & 3) * 32, wn = (w >> 2) * 32;
    uint32_t as_sm = sm_u32(&As[0][0]);
    uint32_t bs_sm = sm_u32(&Bs[0][0]);
    uint32_t a_pat = ((lane & 7) + ((lane >> 3) & 1) * 8) * 272 + (lane >> 4) * 16;
    uint32_t b_pat = ((lane & 7) + (lane >> 4) * 8) * 272 + ((lane >> 3) & 1) * 16;
    float acc[2][4][4];
#pragma unroll
    for (int mi = 0; mi < 2; mi++)
#pragma unroll
        for (int ni = 0; ni < 4; ni++)
#pragma unroll
            for (int j = 0; j < 4; j++) acc[mi][ni][j] = 0.f;
#pragma unroll
    for (int p = 0; p < 3; p++) {
        int ao = (p == 2) ? 128 : 0;
        int bo = (p == 1) ? 64 : 0;
#pragma unroll
        for (int kc = 0; kc < 8; kc++) {
            uint32_t kb = kc * 32;
            uint32_t a[2][4], b[4][2];
#pragma unroll
            for (int mi = 0; mi < 2; mi++)
                ldsm_x4(a[mi][0], a[mi][1], a[mi][2], a[mi][3],
                        as_sm + (ao + wm + mi * 16) * 272 + kb + a_pat);
#pragma unroll
            for (int j = 0; j < 2; j++)
                ldsm_x4(b[2 * j][0], b[2 * j][1], b[2 * j + 1][0], b[2 * j + 1][1],
                        bs_sm + (bo + wn + j * 16) * 272 + kb + b_pat);
#pragma unroll
            for (int mi = 0; mi < 2; mi++)
#pragma unroll
                for (int ni = 0; ni < 4; ni++)
                    mma_bf16(acc[mi][ni], a[mi], b[ni][0], b[ni][1]);
        }
    }
    const float qscale = 0.17677669529663687f;
#pragma unroll
    for (int mi = 0; mi < 2; mi++)
#pragma unroll
    for (int ni = 0; ni < 4; ni++) {
        size_t row0 = (size_t)mb * 128 + wm + mi * 16 + g;
        int col = n0 + wn + ni * 8 + tg * 2;
        float* c = acc[mi][ni];
        if (which == 0) { c[0] *= qscale; c[1] *= qscale; c[2] *= qscale; c[3] *= qscale; }
        if (which == 3) {
            float b0v = bg[col], b1v = bg[col + 1];
            float g0 = 1.f / (1.f + expf(-(c[0] + b0v)));
            float g1 = 1.f / (1.f + expf(-(c[1] + b1v)));
            float g2 = 1.f / (1.f + expf(-(c[2] + b0v)));
            float g3 = 1.f / (1.f + expf(-(c[3] + b1v)));
            *(float2*)&G[row0 * 128 + col] = make_float2(g0, g1);
            *(float2*)&G[(row0 + 8) * 128 + col] = make_float2(g2, g3);
        } else {
            bf16* Oh = (which == 0) ? Qh : (which == 1) ? Kh : Vh;
            bf16* Ol = (which == 0) ? Ql : (which == 1) ? Kl : Vl;
            *(uint32_t*)&Oh[row0 * 128 + col] = pk2(c[0], c[1]);
            *(uint32_t*)&Ol[row0 * 128 + col] = pk2(c[0] - bhi(c[0]), c[1] - bhi(c[1]));
            *(uint32_t*)&Oh[(row0 + 8) * 128 + col] = pk2(c[2], c[3]);
            *(uint32_t*)&Ol[(row0 + 8) * 128 + col] = pk2(c[2] - bhi(c[2]), c[3] - bhi(c[3]));
        }
    }
}

// ---------------- tensor-core flash attention (ldmatrix) ----------------
__global__ __launch_bounds__(256) void attn_tc(
    const bf16* __restrict__ Qh, const bf16* __restrict__ Ql,
    const bf16* __restrict__ Kh, const bf16* __restrict__ Kl,
    const bf16* __restrict__ Vh, const bf16* __restrict__ Vl,
    const float* __restrict__ B, float* __restrict__ O) {
    __shared__ __align__(16) bf16 Qs[256][40];
    __shared__ __align__(16) bf16 Ks[128][40];
    __shared__ __align__(16) bf16 Vs[64][72];
    int qt = blockIdx.x, h = blockIdx.y, i = blockIdx.z;
    int q0 = qt * 128, tid = threadIdx.x;
    size_t qgb = ((size_t)(i * N_SEQ + q0)) * 128 + h * 32;
    for (int e = tid; e < 512; e += 256) {
        int r = e >> 2, c8 = (e & 3) * 8;
        *(uint4*)&Qs[r][c8]       = *(const uint4*)&Qh[qgb + (size_t)r * 128 + c8];
        *(uint4*)&Qs[128 + r][c8] = *(const uint4*)&Ql[qgb + (size_t)r * 128 + c8];
    }
    int w = tid >> 5, lane = tid & 31, g = lane >> 2, tg = lane & 3;
    int qr = w * 16;
    uint32_t qs_sm = sm_u32(&Qs[0][0]);
    uint32_t ks_sm = sm_u32(&Ks[0][0]);
    uint32_t vs_sm = sm_u32(&Vs[0][0]);
    uint32_t qa_pat = ((lane & 7) + ((lane >> 3) & 1) * 8) * 80 + (lane >> 4) * 16;
    uint32_t kb_pat = ((lane & 7) + (lane >> 4) * 8) * 80 + ((lane >> 3) & 1) * 16;
    uint32_t v_pat  = ((lane & 7) + (lane >> 4) * 32) * 144 + ((lane >> 3) & 1) * 16;
    __syncthreads();
    uint32_t qa[2][2][4];
#pragma unroll
    for (int s = 0; s < 2; s++)
#pragma unroll
        for (int kc = 0; kc < 2; kc++)
            ldsm_x4(qa[s][kc][0], qa[s][kc][1], qa[s][kc][2], qa[s][kc][3],
                    qs_sm + (s * 128 + qr) * 80 + kc * 32 + qa_pat);
    float oacc[4][4];
#pragma unroll
    for (int ni = 0; ni < 4; ni++)
#pragma unroll
        for (int j = 0; j < 4; j++) oacc[ni][j] = 0.f;
    float m0 = -1e30f, m1 = -1e30f, l0 = 0.f, l1 = 0.f;
    const float L2E = 1.4426950408889634f;
    size_t brow0 = ((size_t)h * N_SEQ + q0 + qr + g) * N_SEQ;
    size_t brow1 = brow0 + (size_t)8 * N_SEQ;

    for (int kt = 0; kt < 6; kt++) {
        int k0 = kt * 64;
        __syncthreads();
        size_t kb = ((size_t)(i * N_SEQ + k0)) * 128 + h * 32;
        {
            int r = tid >> 2, c8 = (tid & 3) * 8;
            *(uint4*)&Ks[r][c8]      = *(const uint4*)&Kh[kb + (size_t)r * 128 + c8];
            *(uint4*)&Ks[64 + r][c8] = *(const uint4*)&Kl[kb + (size_t)r * 128 + c8];
        }
        {
            int r = tid >> 2, d0 = (tid & 3) * 8;
            uint4 vh4 = *(const uint4*)&Vh[kb + (size_t)r * 128 + d0];
            uint4 vl4 = *(const uint4*)&Vl[kb + (size_t)r * 128 + d0];
            const bf16* ph = (const bf16*)&vh4;
            const bf16* pl = (const bf16*)&vl4;
#pragma unroll
            for (int u = 0; u < 8; u++) {
                Vs[d0 + u][r] = ph[u];
                Vs[32 + d0 + u][r] = pl[u];
            }
        }
        __syncthreads();

        float sc[8][4];
#pragma unroll
        for (int nf = 0; nf < 8; nf++) {
            int col = k0 + nf * 8 + tg * 2;
            float2 b0 = *(const float2*)&B[brow0 + col];
            float2 b1 = *(const float2*)&B[brow1 + col];
            sc[nf][0] = b0.x; sc[nf][1] = b0.y; sc[nf][2] = b1.x; sc[nf][3] = b1.y;
        }
#pragma unroll
        for (int p = 0; p < 3; p++) {
            int aso = (p == 2) ? 1 : 0;
            int kso = (p == 1) ? 64 : 0;
#pragma unroll
            for (int kc = 0; kc < 2; kc++) {
#pragma unroll
                for (int nfp = 0; nfp < 4; nfp++) {
                    uint32_t t0, t1, t2, t3;
                    ldsm_x4(t0, t1, t2, t3,
                            ks_sm + (kso + nfp * 16) * 80 + kc * 32 + kb_pat);
                    mma_bf16(sc[2 * nfp],     qa[aso][kc], t0, t1);
                    mma_bf16(sc[2 * nfp + 1], qa[aso][kc], t2, t3);
                }
            }
        }
        // online softmax
        float nm0 = m0, nm1 = m1;
#pragma unroll
        for (int nf = 0; nf < 8; nf++) {
            nm0 = fmaxf(nm0, fmaxf(sc[nf][0], sc[nf][1]));
            nm1 = fmaxf(nm1, fmaxf(sc[nf][2], sc[nf][3]));
        }
        nm0 = fmaxf(nm0, __shfl_xor_sync(0xffffffffu, nm0, 1));
        nm0 = fmaxf(nm0, __shfl_xor_sync(0xffffffffu, nm0, 2));
        nm1 = fmaxf(nm1, __shfl_xor_sync(0xffffffffu, nm1, 1));
        nm1 = fmaxf(nm1, __shfl_xor_sync(0xffffffffu, nm1, 2));
        float cor0 = exp2f((m0 - nm0) * L2E);
        float cor1 = exp2f((m1 - nm1) * L2E);
        m0 = nm0; m1 = nm1;
        l0 *= cor0; l1 *= cor1;
#pragma unroll
        for (int ni = 0; ni < 4; ni++) {
            oacc[ni][0] *= cor0; oacc[ni][1] *= cor0;
            oacc[ni][2] *= cor1; oacc[ni][3] *= cor1;
        }
#pragma unroll
        for (int nf = 0; nf < 8; nf++) {
            sc[nf][0] = exp2f((sc[nf][0] - m0) * L2E);
            sc[nf][1] = exp2f((sc[nf][1] - m0) * L2E);
            sc[nf][2] = exp2f((sc[nf][2] - m1) * L2E);
            sc[nf][3] = exp2f((sc[nf][3] - m1) * L2E);
            l0 += sc[nf][0] + sc[nf][1];
            l1 += sc[nf][2] + sc[nf][3];
        }
        // PV
#pragma unroll
        for (int kc = 0; kc < 4; kc++) {
            float* f0 = sc[2 * kc];
            float* f1 = sc[2 * kc + 1];
            uint32_t pah[4], pal[4];
            pah[0] = pk2(f0[0], f0[1]); pah[1] = pk2(f0[2], f0[3]);
            pah[2] = pk2(f1[0], f1[1]); pah[3] = pk2(f1[2], f1[3]);
            pal[0] = pk2(f0[0] - bhi(f0[0]), f0[1] - bhi(f0[1]));
            pal[1] = pk2(f0[2] - bhi(f0[2]), f0[3] - bhi(f0[3]));
            pal[2] = pk2(f1[0] - bhi(f1[0]), f1[1] - bhi(f1[1]));
            pal[3] = pk2(f1[2] - bhi(f1[2]), f1[3] - bhi(f1[3]));
#pragma unroll
            for (int ni = 0; ni < 4; ni++) {
                uint32_t bh0, bh1, bl0, bl1;
                ldsm_x4(bh0, bh1, bl0, bl1,
                        vs_sm + (ni * 8) * 144 + kc * 32 + v_pat);
                mma_bf16(oacc[ni], pah, bh0, bh1);
                mma_bf16(oacc[ni], pah, bl0, bl1);
                mma_bf16(oacc[ni], pal, bh0, bh1);
            }
        }
    }
    l0 += __shfl_xor_sync(0xffffffffu, l0, 1);
    l0 += __shfl_xor_sync(0xffffffffu, l0, 2);
    l1 += __shfl_xor_sync(0xffffffffu, l1, 1);
    l1 += __shfl_xor_sync(0xffffffffu, l1, 2);
    float i0 = 1.f / l0, i1 = 1.f / l1;
    size_t ob0 = ((size_t)(i * N_SEQ + q0 + qr + g)) * 128 + h * 32;
    size_t ob1 = ob0 + 8 * 128;
#pragma unroll
    for (int ni = 0; ni < 4; ni++) {
        int d = ni * 8 + tg * 2;
        *(float2*)&O[ob0 + d] = make_float2(oacc[ni][0] * i0, oacc[ni][1] * i0);
        *(float2*)&O[ob1 + d] = make_float2(oacc[ni][2] * i1, oacc[ni][3] * i1);
    }
}

// ---------------- tensor-core output GEMM (ldmatrix + prepped Wo) ----------------
__global__ __launch_bounds__(256) void out_tc(
    const float* __restrict__ G, const float* __restrict__ O,
    const bf16* __restrict__ WhAll, const bf16* __restrict__ WlAll,
    const float* __restrict__ bo,
    float* __restrict__ out) {
    extern __shared__ __align__(16) bf16 sm[];
    bf16 (*As)[136] = reinterpret_cast<bf16(*)[136]>(sm);
    bf16 (*Bs)[136] = reinterpret_cast<bf16(*)[136]>(sm + 256 * 136);
    int mb = blockIdx.x;
    int n0 = blockIdx.y * 64;
    const bf16* WhM = WhAll + 4 * 16384;
    const bf16* WlM = WlAll + 4 * 16384;
    int tid = threadIdx.x;
    size_t abase = (size_t)mb * 128 * 128;
    for (int e = tid; e < 4096; e += 256) {
        int r = e >> 5, c4 = (e & 31) * 4;
        float4 g4 = *(const float4*)&G[abase + (size_t)r * 128 + c4];
        float4 o4 = *(const float4*)&O[abase + (size_t)r * 128 + c4];
        float a0 = g4.x * o4.x, a1 = g4.y * o4.y, a2 = g4.z * o4.z, a3 = g4.w * o4.w;
        *(uint32_t*)&As[r][c4]           = pk2(a0, a1);
        *(uint32_t*)&As[r][c4 + 2]       = pk2(a2, a3);
        *(uint32_t*)&As[128 + r][c4]     = pk2(a0 - bhi(a0), a1 - bhi(a1));
        *(uint32_t*)&As[128 + r][c4 + 2] = pk2(a2 - bhi(a2), a3 - bhi(a3));
    }
    for (int e = tid; e < 2048; e += 256) {
        int r = e >> 4, c8 = (e & 15) * 8;
        const bf16* src = (r < 64) ? &WhM[(n0 + r) * 128 + c8] : &WlM[(n0 + r - 64) * 128 + c8];
        *(uint4*)&Bs[r][c8] = *(const uint4*)src;
    }
    __syncthreads();
    int w = tid >> 5, lane = tid & 31, g = lane >> 2, tg = lane & 3;
    int wm = (w & 3) * 32, wn = (w >> 2) * 32;
    uint32_t as_sm = sm_u32(&As[0][0]);
    uint32_t bs_sm = sm_u32(&Bs[0][0]);
    uint32_t a_pat = ((lane & 7) + ((lane >> 3) & 1) * 8) * 272 + (lane >> 4) * 16;
    uint32_t b_pat = ((lane & 7) + (lane >> 4) * 8) * 272 + ((lane >> 3) & 1) * 16;
    float acc[2][4][4];
#pragma unroll
    for (int mi = 0; mi < 2; mi++)
#pragma unroll
        for (int ni = 0; ni < 4; ni++)
#pragma unroll
            for (int j = 0; j < 4; j++) acc[mi][ni][j] = 0.f;
#pragma unroll
    for (int p = 0; p < 3; p++) {
        int ao = (p == 2) ? 128 : 0;
        int bo2 = (p == 1) ? 64 : 0;
#pragma unroll
        for (int kc = 0; kc < 8; kc++) {
            uint32_t kb = kc * 32;
            uint32_t a[2][4], b[4][2];
#pragma unroll
            for (int mi = 0; mi < 2; mi++)
                ldsm_x4(a[mi][0], a[mi][1], a[mi][2], a[mi][3],
                        as_sm + (ao + wm + mi * 16) * 272 + kb + a_pat);
#pragma unroll
            for (int j = 0; j < 2; j++)
                ldsm_x4(b[2 * j][0], b[2 * j][1], b[2 * j + 1][0], b[2 * j + 1][1],
                        bs_sm + (bo2 + wn + j * 16) * 272 + kb + b_pat);
#pragma unroll
            for (int mi = 0; mi < 2; mi++)
#pragma unroll
                for (int ni = 0; ni < 4; ni++)
                    mma_bf16(acc[mi][ni], a[mi], b[ni][0], b[ni][1]);
        }
    }
#pragma unroll
    for (int mi = 0; mi < 2; mi++)
#pragma unroll
    for (int ni = 0; ni < 4; ni++) {
        size_t row0 = (size_t)mb * 128 + wm + mi * 16 + g;
        int col = n0 + wn + ni * 8 + tg * 2;
        float b0v = bo[col], b1v = bo[col + 1];
        float* c = acc[mi][ni];
        *(float2*)&out[row0 * 128 + col] = make_float2(c[0] + b0v, c[1] + b1v);
        *(float2*)&out[(row0 + 8) * 128 + col] = make_float2(c[2] + b0v, c[3] + b1v);
    }
}

// ---------------- launch ----------------
extern "C" void kernel_launch(void* const* d_in, const int* in_sizes, int n_in,
                              void* d_out, int out_size) {
    const float* x        = (const float*)d_in[0];
    const float* s_inputs = (const float*)d_in[1];
    const float* gamma    = (const float*)d_in[2];
    const float* beta     = (const float*)d_in[3];
    const float* Wq1      = (const float*)d_in[4];
    const float* Wq2      = (const float*)d_in[5];
    const float* Wq3      = (const float*)d_in[6];
    const float* Wk1      = (const float*)d_in[7];
    const float* Wk2      = (const float*)d_in[8];
    const float* Wk3      = (const float*)d_in[9];
    const float* Wq_att   = (const float*)d_in[10];
    const float* Wk_att   = (const float*)d_in[11];
    const float* Wv_att   = (const float*)d_in[12];
    const float* Wg       = (const float*)d_in[13];
    const float* bg       = (const float*)d_in[14];
    const float* Wo       = (const float*)d_in[15];
    const float* bo       = (const float*)d_in[16];
    float* out = (float*)d_out;

    bf16 *xh, *xl, *Qh, *Ql, *Kh, *Kl, *Vh, *Vl, *Wh, *Wl;
    float *Z, *H1, *H2, *QKB, *bias, *G, *O;
    cudaGetSymbolAddress((void**)&xh, g_xh);
    cudaGetSymbolAddress((void**)&xl, g_xl);
    cudaGetSymbolAddress((void**)&Z, g_Z);
    cudaGetSymbolAddress((void**)&H1, g_H1);
    cudaGetSymbolAddress((void**)&H2, g_H2);
    cudaGetSymbolAddress((void**)&QKB, g_QKB);
    cudaGetSymbolAddress((void**)&bias, g_bias);
    cudaGetSymbolAddress((void**)&Qh, g_Qh);
    cudaGetSymbolAddress((void**)&Ql, g_Ql);
    cudaGetSymbolAddress((void**)&Kh, g_Kh);
    cudaGetSymbolAddress((void**)&Kl, g_Kl);
    cudaGetSymbolAddress((void**)&Vh, g_Vh);
    cudaGetSymbolAddress((void**)&Vl, g_Vl);
    cudaGetSymbolAddress((void**)&G, g_G);
    cudaGetSymbolAddress((void**)&O, g_O);
    cudaGetSymbolAddress((void**)&Wh, g_Wh);
    cudaGetSymbolAddress((void**)&Wl, g_Wl);

    const int PROJ_SMEM = (256 * 136 + 128 * 136) * 2;  // 104448 bytes
    cudaFuncSetAttribute(proj_tc, cudaFuncAttributeMaxDynamicSharedMemorySize, PROJ_SMEM);
    cudaFuncSetAttribute(out_tc, cudaFuncAttributeMaxDynamicSharedMemorySize, PROJ_SMEM);

    // #1: weight pre-split
    prep_w<<<320, 256>>>(Wq_att, Wk_att, Wv_att, Wg, Wo, Wh, Wl);
    // #2: layernorm
    ln_kernel<<<M_TOT / 8, 256>>>(x, gamma, beta, xh, xl);
    // #3: means + concat
    meanz_kernel<<<2 * N_SEQ, 128>>>(xh, xl, s_inputs, Z);
    // #4: projections (position 4 -> profiled by ncu with the 2-launch harness offset)
    proj_tc<<<dim3(M_TOT / 128, 8), 256, PROJ_SMEM>>>(xh, xl, Wh, Wl, bg,
                                                      Qh, Ql, Kh, Kl, Vh, Vl, G);
    // #5-#7: bias MLP chain
    mlp_tc<<<dim3(12, 4), 256>>>(Z, Wq1, Wk1, H1, ZD_DIM, MLP_H, 1);
    mlp_tc<<<dim3(12, 4), 256>>>(H1, Wq2, Wk2, H2, MLP_H, MLP_H, 1);
    mlp_tc<<<dim3(12, 6), 256>>>(H2, Wq3, Wk3, QKB, MLP_H, HR_DIM, 0);
    // #8: low-rank bias matrix
    bias_kernel<<<dim3(H_NUM, N_SEQ / 32, N_SEQ / 64), 256>>>(QKB, QKB + N_SEQ * HR_DIM, bias);
    // #9: attention
    attn_tc<<<dim3(3, H_NUM, N_SEQ), 256>>>(Qh, Ql, Kh, Kl, Vh, Vl, bias, O);
    // #10: gated output projection
    out_tc<<<dim3(M_TOT / 128, 2), 256, PROJ_SMEM>>>(G, O, Wh, Wl, bo, out);
}

// round 7
// speedup vs baseline: 1.9198x; 1.3178x over previous
#include <cuda_runtime.h>
#include <cuda_bf16.h>
#include <cstdint>
#include <math.h>

#define N_SEQ 384
#define C_DIM 128
#define H_NUM 4
#define DH_NUM 32
#define R_RANK 96
#define SD_DIM 449
#define ZD_DIM 577
#define MLP_H 256
#define HR_DIM 384
#define M_TOT (N_SEQ * N_SEQ)   // 147456

typedef __nv_bfloat16 bf16;

// ---------------- scratch (device globals) ----------------
__device__ bf16  g_xh[(size_t)M_TOT * C_DIM];
__device__ bf16  g_xl[(size_t)M_TOT * C_DIM];
__device__ float g_Z[2 * N_SEQ * ZD_DIM];
__device__ float g_H1[2 * N_SEQ * MLP_H];
__device__ float g_H2[2 * N_SEQ * MLP_H];
__device__ float g_QKB[2 * N_SEQ * HR_DIM];
__device__ float g_bias[(size_t)H_NUM * N_SEQ * N_SEQ];
__device__ bf16  g_Qh[(size_t)M_TOT * C_DIM];
__device__ bf16  g_Ql[(size_t)M_TOT * C_DIM];
__device__ bf16  g_Kh[(size_t)M_TOT * C_DIM];
__device__ bf16  g_Kl[(size_t)M_TOT * C_DIM];
__device__ bf16  g_Vh[(size_t)M_TOT * C_DIM];
__device__ bf16  g_Vl[(size_t)M_TOT * C_DIM];
__device__ float g_G[(size_t)M_TOT * C_DIM];
__device__ float g_O[(size_t)M_TOT * C_DIM];
__device__ bf16  g_Wh[5 * 128 * 128];   // pre-split weights, n-major [w][n][k]
__device__ bf16  g_Wl[5 * 128 * 128];

// ---------------- helpers ----------------
__device__ __forceinline__ uint32_t pk2(float a, float b) {
    __nv_bfloat162 t = __floats2bfloat162_rn(a, b);
    return *reinterpret_cast<uint32_t*>(&t);
}
__device__ __forceinline__ float bhi(float x) {
    return __bfloat162float(__float2bfloat16(x));
}
__device__ __forceinline__ void mma_bf16(float* c, const uint32_t* a, uint32_t b0, uint32_t b1) {
    asm volatile(
        "mma.sync.aligned.m16n8k16.row.col.f32.bf16.bf16.f32 "
        "{%0,%1,%2,%3},{%4,%5,%6,%7},{%8,%9},{%0,%1,%2,%3};"
        : "+f"(c[0]), "+f"(c[1]), "+f"(c[2]), "+f"(c[3])
        : "r"(a[0]), "r"(a[1]), "r"(a[2]), "r"(a[3]), "r"(b0), "r"(b1));
}
__device__ __forceinline__ void ldsm_x4(uint32_t& r0, uint32_t& r1, uint32_t& r2, uint32_t& r3,
                                        uint32_t addr) {
    asm volatile("ldmatrix.sync.aligned.m8n8.x4.shared.b16 {%0,%1,%2,%3}, [%4];"
                 : "=r"(r0), "=r"(r1), "=r"(r2), "=r"(r3) : "r"(addr));
}
__device__ __forceinline__ uint32_t sm_u32(const void* p) {
    return (uint32_t)__cvta_generic_to_shared(p);
}

// ---------------- pre-split attention weights (once) ----------------
__global__ void prep_w(const float* __restrict__ Wq, const float* __restrict__ Wk,
                       const float* __restrict__ Wv, const float* __restrict__ Wg,
                       const float* __restrict__ Wo,
                       bf16* __restrict__ Wh, bf16* __restrict__ Wl) {
    int idx = blockIdx.x * 256 + threadIdx.x;
    if (idx >= 5 * 16384) return;
    int w = idx >> 14, r = idx & 16383;
    int n = r >> 7, k = r & 127;
    const float* W = (w == 0) ? Wq : (w == 1) ? Wk : (w == 2) ? Wv : (w == 3) ? Wg : Wo;
    float v = W[k * 128 + n];
    bf16 h = __float2bfloat16(v);
    Wh[idx] = h;
    Wl[idx] = __float2bfloat16(v - __bfloat162float(h));
}

// ---------------- LayerNorm -> split bf16 hi/lo ----------------
__global__ void ln_kernel(const float* __restrict__ x, const float* __restrict__ gamma,
                          const float* __restrict__ beta,
                          bf16* __restrict__ xh, bf16* __restrict__ xl) {
    size_t pix = (size_t)blockIdx.x * 8 + (threadIdx.x >> 5);
    int l = threadIdx.x & 31;
    const float4* xp = reinterpret_cast<const float4*>(x + pix * 128);
    float4 v = xp[l];
    float s = v.x + v.y + v.z + v.w;
    float s2 = v.x * v.x + v.y * v.y + v.z * v.z + v.w * v.w;
#pragma unroll
    for (int o = 16; o; o >>= 1) {
        s  += __shfl_xor_sync(0xffffffffu, s, o);
        s2 += __shfl_xor_sync(0xffffffffu, s2, o);
    }
    float mu = s * (1.f / 128.f);
    float var = s2 * (1.f / 128.f) - mu * mu;
    float rs = rsqrtf(var + 1e-5f);
    float4 gm = reinterpret_cast<const float4*>(gamma)[l];
    float4 bt = reinterpret_cast<const float4*>(beta)[l];
    float o0 = (v.x - mu) * rs * gm.x + bt.x;
    float o1 = (v.y - mu) * rs * gm.y + bt.y;
    float o2 = (v.z - mu) * rs * gm.z + bt.z;
    float o3 = (v.w - mu) * rs * gm.w + bt.w;
    size_t base = pix * 128 + 4 * l;
    *(uint32_t*)&xh[base]     = pk2(o0, o1);
    *(uint32_t*)&xh[base + 2] = pk2(o2, o3);
    *(uint32_t*)&xl[base]     = pk2(o0 - bhi(o0), o1 - bhi(o1));
    *(uint32_t*)&xl[base + 2] = pk2(o2 - bhi(o2), o3 - bhi(o3));
}

// ---------------- fused row/col means + concat s_inputs -> Z ----------------
__global__ void meanz_kernel(const bf16* __restrict__ xh, const bf16* __restrict__ xl,
                             const float* __restrict__ s_inputs, float* __restrict__ Z) {
    int c = threadIdx.x;
    int idx = blockIdx.x;
    float s = 0.f;
    if (idx < N_SEQ) {
        size_t base = (size_t)idx * N_SEQ * C_DIM;
        for (int j = 0; j < N_SEQ; j++) {
            size_t e = base + (size_t)j * C_DIM + c;
            s += __bfloat162float(xh[e]) + __bfloat162float(xl[e]);
        }
    } else {
        int j = idx - N_SEQ;
        for (int i = 0; i < N_SEQ; i++) {
            size_t e = ((size_t)i * N_SEQ + j) * C_DIM + c;
            s += __bfloat162float(xh[e]) + __bfloat162float(xl[e]);
        }
    }
    Z[(size_t)idx * ZD_DIM + c] = s * (1.f / N_SEQ);
    int n = (idx < N_SEQ) ? idx : idx - N_SEQ;
    for (int t = c; t < SD_DIM; t += 128)
        Z[(size_t)idx * ZD_DIM + C_DIM + t] = s_inputs[n * SD_DIM + t];
}

// ---------------- TC MLP layer (q/k fused along M) ----------------
__global__ __launch_bounds__(256) void mlp_tc(
    const float* __restrict__ A, const float* __restrict__ Wq, const float* __restrict__ Wk,
    float* __restrict__ C, int K, int Nout, int act) {
    __shared__ __align__(16) bf16 As[128][34];
    __shared__ __align__(16) bf16 Bs[128][34];
    int m0 = blockIdx.x * 64;
    int n0 = blockIdx.y * 64;
    const float* W = (blockIdx.x < 6) ? Wq : Wk;
    int tid = threadIdx.x;
    int w = tid >> 5, lane = tid & 31, g = lane >> 2, tg = lane & 3;
    int wm = (w & 3) * 16, wn = (w >> 2) * 32;
    float acc[4][4];
#pragma unroll
    for (int ni = 0; ni < 4; ni++)
#pragma unroll
        for (int j = 0; j < 4; j++) acc[ni][j] = 0.f;

    for (int k0 = 0; k0 < K; k0 += 32) {
        for (int e = tid; e < 2048; e += 256) {
            int r = e >> 5, c = e & 31;
            int gk = k0 + c;
            float v = (gk < K) ? A[(size_t)(m0 + r) * K + gk] : 0.f;
            bf16 h = __float2bfloat16(v);
            As[r][c] = h;
            As[64 + r][c] = __float2bfloat16(v - __bfloat162float(h));
        }
        for (int e = tid; e < 2048; e += 256) {
            int k = e >> 6, n = e & 63;
            int gk = k0 + k;
            float v = (gk < K) ? W[(size_t)gk * Nout + n0 + n] : 0.f;
            bf16 h = __float2bfloat16(v);
            Bs[n][k] = h;
            Bs[64 + n][k] = __float2bfloat16(v - __bfloat162float(h));
        }
        __syncthreads();
#pragma unroll
        for (int p = 0; p < 3; p++) {
            int ao = (p == 2) ? 64 : 0;
            int bo = (p == 1) ? 64 : 0;
#pragma unroll
            for (int kc = 0; kc < 2; kc++) {
                int k2 = kc * 16 + tg * 2;
                uint32_t a[4];
                int ar = ao + wm;
                a[0] = *(const uint32_t*)&As[ar + g][k2];
                a[1] = *(const uint32_t*)&As[ar + g + 8][k2];
                a[2] = *(const uint32_t*)&As[ar + g][k2 + 8];
                a[3] = *(const uint32_t*)&As[ar + g + 8][k2 + 8];
#pragma unroll
                for (int ni = 0; ni < 4; ni++) {
                    int bn = bo + wn + ni * 8 + g;
                    uint32_t b0 = *(const uint32_t*)&Bs[bn][k2];
                    uint32_t b1 = *(const uint32_t*)&Bs[bn][k2 + 8];
                    mma_bf16(acc[ni], a, b0, b1);
                }
            }
        }
        __syncthreads();
    }
#pragma unroll
    for (int ni = 0; ni < 4; ni++) {
        int col = n0 + wn + ni * 8 + tg * 2;
        size_t r0 = (size_t)(m0 + wm + g) * Nout + col;
        size_t r1 = r0 + (size_t)8 * Nout;
        float v0 = acc[ni][0], v1 = acc[ni][1], v2 = acc[ni][2], v3 = acc[ni][3];
        if (act) { v0 = tanhf(v0); v1 = tanhf(v1); v2 = tanhf(v2); v3 = tanhf(v3); }
        *(float2*)&C[r0] = make_float2(v0, v1);
        *(float2*)&C[r1] = make_float2(v2, v3);
    }
}

// ---------------- low-rank bias matrix ----------------
__global__ void bias_kernel(const float* __restrict__ qb, const float* __restrict__ kb,
                            float* __restrict__ B) {
    __shared__ float qs[32][97];
    __shared__ float ks[64][97];
    int h = blockIdx.x, q0 = blockIdx.y * 32, k0 = blockIdx.z * 64;
    for (int e = threadIdx.x; e < 32 * 96; e += 256) {
        int q = e / 96, r = e % 96;
        qs[q][r] = qb[(q0 + q) * HR_DIM + h * R_RANK + r];
    }
    for (int e = threadIdx.x; e < 64 * 96; e += 256) {
        int k = e / 96, r = e % 96;
        ks[k][r] = kb[(k0 + k) * HR_DIM + h * R_RANK + r];
    }
    __syncthreads();
    int ki = threadIdx.x & 63, qg = threadIdx.x >> 6;
    float acc[8];
#pragma unroll
    for (int u = 0; u < 8; u++) acc[u] = 0.f;
    for (int r = 0; r < 96; r++) {
        float kv = ks[ki][r];
#pragma unroll
        for (int u = 0; u < 8; u++) acc[u] = fmaf(kv, qs[qg * 8 + u][r], acc[u]);
    }
#pragma unroll
    for (int u = 0; u < 8; u++)
        B[((size_t)h * N_SEQ + q0 + qg * 8 + u) * N_SEQ + k0 + ki] = acc[u];
}

// ---------------- proj v2: A tile resident, loop over 8 (weight, half) chunks ----------------
// grid = M_TOT/64 blocks; block keeps 64-row x tile (hi+lo) in smem; weights stream from L2.
__global__ __launch_bounds__(256) void proj_tc(
    const bf16* __restrict__ xh, const bf16* __restrict__ xl,
    const bf16* __restrict__ WhAll, const bf16* __restrict__ WlAll,
    const float* __restrict__ bg,
    bf16* __restrict__ Qh, bf16* __restrict__ Ql,
    bf16* __restrict__ Kh, bf16* __restrict__ Kl,
    bf16* __restrict__ Vh, bf16* __restrict__ Vl,
    float* __restrict__ G) {
    extern __shared__ __align__(16) bf16 sm[];
    bf16 (*As)[136] = reinterpret_cast<bf16(*)[136]>(sm);              // rows 0-63 hi, 64-127 lo
    bf16 (*Bs)[136] = reinterpret_cast<bf16(*)[136]>(sm + 128 * 136);  // rows 0-63 hi, 64-127 lo
    int mb = blockIdx.x;
    int tid = threadIdx.x;
    size_t abase = (size_t)mb * 64 * 128;
    for (int e = tid; e < 1024; e += 256) {
        int r = e >> 4, c8 = (e & 15) * 8;
        *(uint4*)&As[r][c8]      = *(const uint4*)&xh[abase + (size_t)r * 128 + c8];
        *(uint4*)&As[64 + r][c8] = *(const uint4*)&xl[abase + (size_t)r * 128 + c8];
    }
    int w = tid >> 5, lane = tid & 31, g = lane >> 2, tg = lane & 3;
    int wm = (w & 1) * 32, wn = (w >> 1) * 16;   // 2 m-warps x 4 n-warps -> 64x64 per chunk
    uint32_t as_sm = sm_u32(&As[0][0]);
    uint32_t bs_sm = sm_u32(&Bs[0][0]);
    uint32_t a_pat = ((lane & 7) + ((lane >> 3) & 1) * 8) * 272 + (lane >> 4) * 16;
    uint32_t b_pat = ((lane & 7) + (lane >> 4) * 8) * 272 + ((lane >> 3) & 1) * 16;
    const float qscale = 0.17677669529663687f;

    for (int ch = 0; ch < 8; ch++) {
        int which = ch >> 1, n0 = (ch & 1) * 64;
        const bf16* WhM = WhAll + which * 16384;
        const bf16* WlM = WlAll + which * 16384;
        __syncthreads();   // As ready (iter 0) / Bs consumers done (iters 1+)
        for (int e = tid; e < 2048; e += 256) {
            int r = e >> 4, c8 = (e & 15) * 8;
            const bf16* src = (r < 64) ? &WhM[(n0 + r) * 128 + c8]
                                       : &WlM[(n0 + r - 64) * 128 + c8];
            *(uint4*)&Bs[r][c8] = *(const uint4*)src;
        }
        __syncthreads();

        float acc[2][2][4];
#pragma unroll
        for (int mi = 0; mi < 2; mi++)
#pragma unroll
            for (int ni = 0; ni < 2; ni++)
#pragma unroll
                for (int j = 0; j < 4; j++) acc[mi][ni][j] = 0.f;
#pragma unroll
        for (int p = 0; p < 3; p++) {
            int ao = (p == 2) ? 64 : 0;
            int bo = (p == 1) ? 64 : 0;
#pragma unroll
            for (int kc = 0; kc < 8; kc++) {
                uint32_t kb = kc * 32;
                uint32_t a[2][4], b[4];
#pragma unroll
                for (int mi = 0; mi < 2; mi++)
                    ldsm_x4(a[mi][0], a[mi][1], a[mi][2], a[mi][3],
                            as_sm + (ao + wm + mi * 16) * 272 + kb + a_pat);
                ldsm_x4(b[0], b[1], b[2], b[3],
                        bs_sm + (bo + wn) * 272 + kb + b_pat);
#pragma unroll
                for (int mi = 0; mi < 2; mi++) {
                    mma_bf16(acc[mi][0], a[mi], b[0], b[1]);
                    mma_bf16(acc[mi][1], a[mi], b[2], b[3]);
                }
            }
        }
#pragma unroll
        for (int mi = 0; mi < 2; mi++)
#pragma unroll
        for (int ni = 0; ni < 2; ni++) {
            size_t row0 = (size_t)mb * 64 + wm + mi * 16 + g;
            int col = n0 + wn + ni * 8 + tg * 2;
            float* c = acc[mi][ni];
            if (which == 0) { c[0] *= qscale; c[1] *= qscale; c[2] *= qscale; c[3] *= qscale; }
            if (which == 3) {
                float b0v = bg[col], b1v = bg[col + 1];
                float g0 = 1.f / (1.f + expf(-(c[0] + b0v)));
                float g1 = 1.f / (1.f + expf(-(c[1] + b1v)));
                float g2 = 1.f / (1.f + expf(-(c[2] + b0v)));
                float g3 = 1.f / (1.f + expf(-(c[3] + b1v)));
                *(float2*)&G[row0 * 128 + col] = make_float2(g0, g1);
                *(float2*)&G[(row0 + 8) * 128 + col] = make_float2(g2, g3);
            } else {
                bf16* Oh = (which == 0) ? Qh : (which == 1) ? Kh : Vh;
                bf16* Ol = (which == 0) ? Ql : (which == 1) ? Kl : Vl;
                *(uint32_t*)&Oh[row0 * 128 + col] = pk2(c[0], c[1]);
                *(uint32_t*)&Ol[row0 * 128 + col] = pk2(c[0] - bhi(c[0]), c[1] - bhi(c[1]));
                *(uint32_t*)&Oh[(row0 + 8) * 128 + col] = pk2(c[2], c[3]);
                *(uint32_t*)&Ol[(row0 + 8) * 128 + col] = pk2(c[2] - bhi(c[2]), c[3] - bhi(c[3]));
            }
        }
    }
}

// ---------------- tensor-core flash attention (ldmatrix) ----------------
__global__ __launch_bounds__(256) void attn_tc(
    const bf16* __restrict__ Qh, const bf16* __restrict__ Ql,
    const bf16* __restrict__ Kh, const bf16* __restrict__ Kl,
    const bf16* __restrict__ Vh, const bf16* __restrict__ Vl,
    const float* __restrict__ B, float* __restrict__ O) {
    __shared__ __align__(16) bf16 Qs[256][40];
    __shared__ __align__(16) bf16 Ks[128][40];
    __shared__ __align__(16) bf16 Vs[64][72];
    int qt = blockIdx.x, h = blockIdx.y, i = blockIdx.z;
    int q0 = qt * 128, tid = threadIdx.x;
    size_t qgb = ((size_t)(i * N_SEQ + q0)) * 128 + h * 32;
    for (int e = tid; e < 512; e += 256) {
        int r = e >> 2, c8 = (e & 3) * 8;
        *(uint4*)&Qs[r][c8]       = *(const uint4*)&Qh[qgb + (size_t)r * 128 + c8];
        *(uint4*)&Qs[128 + r][c8] = *(const uint4*)&Ql[qgb + (size_t)r * 128 + c8];
    }
    int w = tid >> 5, lane = tid & 31, g = lane >> 2, tg = lane & 3;
    int qr = w * 16;
    uint32_t qs_sm = sm_u32(&Qs[0][0]);
    uint32_t ks_sm = sm_u32(&Ks[0][0]);
    uint32_t vs_sm = sm_u32(&Vs[0][0]);
    uint32_t qa_pat = ((lane & 7) + ((lane >> 3) & 1) * 8) * 80 + (lane >> 4) * 16;
    uint32_t kb_pat = ((lane & 7) + (lane >> 4) * 8) * 80 + ((lane >> 3) & 1) * 16;
    uint32_t v_pat  = ((lane & 7) + (lane >> 4) * 32) * 144 + ((lane >> 3) & 1) * 16;
    __syncthreads();
    uint32_t qa[2][2][4];
#pragma unroll
    for (int s = 0; s < 2; s++)
#pragma unroll
        for (int kc = 0; kc < 2; kc++)
            ldsm_x4(qa[s][kc][0], qa[s][kc][1], qa[s][kc][2], qa[s][kc][3],
                    qs_sm + (s * 128 + qr) * 80 + kc * 32 + qa_pat);
    float oacc[4][4];
#pragma unroll
    for (int ni = 0; ni < 4; ni++)
#pragma unroll
        for (int j = 0; j < 4; j++) oacc[ni][j] = 0.f;
    float m0 = -1e30f, m1 = -1e30f, l0 = 0.f, l1 = 0.f;
    const float L2E = 1.4426950408889634f;
    size_t brow0 = ((size_t)h * N_SEQ + q0 + qr + g) * N_SEQ;
    size_t brow1 = brow0 + (size_t)8 * N_SEQ;

    for (int kt = 0; kt < 6; kt++) {
        int k0 = kt * 64;
        __syncthreads();
        size_t kb = ((size_t)(i * N_SEQ + k0)) * 128 + h * 32;
        {
            int r = tid >> 2, c8 = (tid & 3) * 8;
            *(uint4*)&Ks[r][c8]      = *(const uint4*)&Kh[kb + (size_t)r * 128 + c8];
            *(uint4*)&Ks[64 + r][c8] = *(const uint4*)&Kl[kb + (size_t)r * 128 + c8];
        }
        {
            int r = tid >> 2, d0 = (tid & 3) * 8;
            uint4 vh4 = *(const uint4*)&Vh[kb + (size_t)r * 128 + d0];
            uint4 vl4 = *(const uint4*)&Vl[kb + (size_t)r * 128 + d0];
            const bf16* ph = (const bf16*)&vh4;
            const bf16* pl = (const bf16*)&vl4;
#pragma unroll
            for (int u = 0; u < 8; u++) {
                Vs[d0 + u][r] = ph[u];
                Vs[32 + d0 + u][r] = pl[u];
            }
        }
        __syncthreads();

        float sc[8][4];
#pragma unroll
        for (int nf = 0; nf < 8; nf++) {
            int col = k0 + nf * 8 + tg * 2;
            float2 b0 = *(const float2*)&B[brow0 + col];
            float2 b1 = *(const float2*)&B[brow1 + col];
            sc[nf][0] = b0.x; sc[nf][1] = b0.y; sc[nf][2] = b1.x; sc[nf][3] = b1.y;
        }
#pragma unroll
        for (int p = 0; p < 3; p++) {
            int aso = (p == 2) ? 1 : 0;
            int kso = (p == 1) ? 64 : 0;
#pragma unroll
            for (int kc = 0; kc < 2; kc++) {
#pragma unroll
                for (int nfp = 0; nfp < 4; nfp++) {
                    uint32_t t0, t1, t2, t3;
                    ldsm_x4(t0, t1, t2, t3,
                            ks_sm + (kso + nfp * 16) * 80 + kc * 32 + kb_pat);
                    mma_bf16(sc[2 * nfp],     qa[aso][kc], t0, t1);
                    mma_bf16(sc[2 * nfp + 1], qa[aso][kc], t2, t3);
                }
            }
        }
        // online softmax
        float nm0 = m0, nm1 = m1;
#pragma unroll
        for (int nf = 0; nf < 8; nf++) {
            nm0 = fmaxf(nm0, fmaxf(sc[nf][0], sc[nf][1]));
            nm1 = fmaxf(nm1, fmaxf(sc[nf][2], sc[nf][3]));
        }
        nm0 = fmaxf(nm0, __shfl_xor_sync(0xffffffffu, nm0, 1));
        nm0 = fmaxf(nm0, __shfl_xor_sync(0xffffffffu, nm0, 2));
        nm1 = fmaxf(nm1, __shfl_xor_sync(0xffffffffu, nm1, 1));
        nm1 = fmaxf(nm1, __shfl_xor_sync(0xffffffffu, nm1, 2));
        float cor0 = exp2f((m0 - nm0) * L2E);
        float cor1 = exp2f((m1 - nm1) * L2E);
        m0 = nm0; m1 = nm1;
        l0 *= cor0; l1 *= cor1;
#pragma unroll
        for (int ni = 0; ni < 4; ni++) {
            oacc[ni][0] *= cor0; oacc[ni][1] *= cor0;
            oacc[ni][2] *= cor1; oacc[ni][3] *= cor1;
        }
#pragma unroll
        for (int nf = 0; nf < 8; nf++) {
            sc[nf][0] = exp2f((sc[nf][0] - m0) * L2E);
            sc[nf][1] = exp2f((sc[nf][1] - m0) * L2E);
            sc[nf][2] = exp2f((sc[nf][2] - m1) * L2E);
            sc[nf][3] = exp2f((sc[nf][3] - m1) * L2E);
            l0 += sc[nf][0] + sc[nf][1];
            l1 += sc[nf][2] + sc[nf][3];
        }
        // PV
#pragma unroll
        for (int kc = 0; kc < 4; kc++) {
            float* f0 = sc[2 * kc];
            float* f1 = sc[2 * kc + 1];
            uint32_t pah[4], pal[4];
            pah[0] = pk2(f0[0], f0[1]); pah[1] = pk2(f0[2], f0[3]);
            pah[2] = pk2(f1[0], f1[1]); pah[3] = pk2(f1[2], f1[3]);
            pal[0] = pk2(f0[0] - bhi(f0[0]), f0[1] - bhi(f0[1]));
            pal[1] = pk2(f0[2] - bhi(f0[2]), f0[3] - bhi(f0[3]));
            pal[2] = pk2(f1[0] - bhi(f1[0]), f1[1] - bhi(f1[1]));
            pal[3] = pk2(f1[2] - bhi(f1[2]), f1[3] - bhi(f1[3]));
#pragma unroll
            for (int ni = 0; ni < 4; ni++) {
                uint32_t bh0, bh1, bl0, bl1;
                ldsm_x4(bh0, bh1, bl0, bl1,
                        vs_sm + (ni * 8) * 144 + kc * 32 + v_pat);
                mma_bf16(oacc[ni], pah, bh0, bh1);
                mma_bf16(oacc[ni], pah, bl0, bl1);
                mma_bf16(oacc[ni], pal, bh0, bh1);
            }
        }
    }
    l0 += __shfl_xor_sync(0xffffffffu, l0, 1);
    l0 += __shfl_xor_sync(0xffffffffu, l0, 2);
    l1 += __shfl_xor_sync(0xffffffffu, l1, 1);
    l1 += __shfl_xor_sync(0xffffffffu, l1, 2);
    float i0 = 1.f / l0, i1 = 1.f / l1;
    size_t ob0 = ((size_t)(i * N_SEQ + q0 + qr + g)) * 128 + h * 32;
    size_t ob1 = ob0 + 8 * 128;
#pragma unroll
    for (int ni = 0; ni < 4; ni++) {
        int d = ni * 8 + tg * 2;
        *(float2*)&O[ob0 + d] = make_float2(oacc[ni][0] * i0, oacc[ni][1] * i0);
        *(float2*)&O[ob1 + d] = make_float2(oacc[ni][2] * i1, oacc[ni][3] * i1);
    }
}

// ---------------- tensor-core output GEMM (ldmatrix + prepped Wo) ----------------
__global__ __launch_bounds__(256) void out_tc(
    const float* __restrict__ G, const float* __restrict__ O,
    const bf16* __restrict__ WhAll, const bf16* __restrict__ WlAll,
    const float* __restrict__ bo,
    float* __restrict__ out) {
    extern __shared__ __align__(16) bf16 sm[];
    bf16 (*As)[136] = reinterpret_cast<bf16(*)[136]>(sm);
    bf16 (*Bs)[136] = reinterpret_cast<bf16(*)[136]>(sm + 256 * 136);
    int mb = blockIdx.x;
    int n0 = blockIdx.y * 64;
    const bf16* WhM = WhAll + 4 * 16384;
    const bf16* WlM = WlAll + 4 * 16384;
    int tid = threadIdx.x;
    size_t abase = (size_t)mb * 128 * 128;
    for (int e = tid; e < 4096; e += 256) {
        int r = e >> 5, c4 = (e & 31) * 4;
        float4 g4 = *(const float4*)&G[abase + (size_t)r * 128 + c4];
        float4 o4 = *(const float4*)&O[abase + (size_t)r * 128 + c4];
        float a0 = g4.x * o4.x, a1 = g4.y * o4.y, a2 = g4.z * o4.z, a3 = g4.w * o4.w;
        *(uint32_t*)&As[r][c4]           = pk2(a0, a1);
        *(uint32_t*)&As[r][c4 + 2]       = pk2(a2, a3);
        *(uint32_t*)&As[128 + r][c4]     = pk2(a0 - bhi(a0), a1 - bhi(a1));
        *(uint32_t*)&As[128 + r][c4 + 2] = pk2(a2 - bhi(a2), a3 - bhi(a3));
    }
    for (int e = tid; e < 2048; e += 256) {
        int r = e >> 4, c8 = (e & 15) * 8;
        const bf16* src = (r < 64) ? &WhM[(n0 + r) * 128 + c8] : &WlM[(n0 + r - 64) * 128 + c8];
        *(uint4*)&Bs[r][c8] = *(const uint4*)src;
    }
    __syncthreads();
    int w = tid >> 5, lane = tid & 31, g = lane >> 2, tg = lane & 3;
    int wm = (w & 3) * 32, wn = (w >> 2) * 32;
    uint32_t as_sm = sm_u32(&As[0][0]);
    uint32_t bs_sm = sm_u32(&Bs[0][0]);
    uint32_t a_pat = ((lane & 7) + ((lane >> 3) & 1) * 8) * 272 + (lane >> 4) * 16;
    uint32_t b_pat = ((lane & 7) + (lane >> 4) * 8) * 272 + ((lane >> 3) & 1) * 16;
    float acc[2][4][4];
#pragma unroll
    for (int mi = 0; mi < 2; mi++)
#pragma unroll
        for (int ni = 0; ni < 4; ni++)
#pragma unroll
            for (int j = 0; j < 4; j++) acc[mi][ni][j] = 0.f;
#pragma unroll
    for (int p = 0; p < 3; p++) {
        int ao = (p == 2) ? 128 : 0;
        int bo2 = (p == 1) ? 64 : 0;
#pragma unroll
        for (int kc = 0; kc < 8; kc++) {
            uint32_t kb = kc * 32;
            uint32_t a[2][4], b[4][2];
#pragma unroll
            for (int mi = 0; mi < 2; mi++)
                ldsm_x4(a[mi][0], a[mi][1], a[mi][2], a[mi][3],
                        as_sm + (ao + wm + mi * 16) * 272 + kb + a_pat);
#pragma unroll
            for (int j = 0; j < 2; j++)
                ldsm_x4(b[2 * j][0], b[2 * j][1], b[2 * j + 1][0], b[2 * j + 1][1],
                        bs_sm + (bo2 + wn + j * 16) * 272 + kb + b_pat);
#pragma unroll
            for (int mi = 0; mi < 2; mi++)
#pragma unroll
                for (int ni = 0; ni < 4; ni++)
                    mma_bf16(acc[mi][ni], a[mi], b[ni][0], b[ni][1]);
        }
    }
#pragma unroll
    for (int mi = 0; mi < 2; mi++)
#pragma unroll
    for (int ni = 0; ni < 4; ni++) {
        size_t row0 = (size_t)mb * 128 + wm + mi * 16 + g;
        int col = n0 + wn + ni * 8 + tg * 2;
        float b0v = bo[col], b1v = bo[col + 1];
        float* c = acc[mi][ni];
        *(float2*)&out[row0 * 128 + col] = make_float2(c[0] + b0v, c[1] + b1v);
        *(float2*)&out[(row0 + 8) * 128 + col] = make_float2(c[2] + b0v, c[3] + b1v);
    }
}

// ---------------- launch ----------------
extern "C" void kernel_launch(void* const* d_in, const int* in_sizes, int n_in,
                              void* d_out, int out_size) {
    const float* x        = (const float*)d_in[0];
    const float* s_inputs = (const float*)d_in[1];
    const float* gamma    = (const float*)d_in[2];
    const float* beta     = (const float*)d_in[3];
    const float* Wq1      = (const float*)d_in[4];
    const float* Wq2      = (const float*)d_in[5];
    const float* Wq3      = (const float*)d_in[6];
    const float* Wk1      = (const float*)d_in[7];
    const float* Wk2      = (const float*)d_in[8];
    const float* Wk3      = (const float*)d_in[9];
    const float* Wq_att   = (const float*)d_in[10];
    const float* Wk_att   = (const float*)d_in[11];
    const float* Wv_att   = (const float*)d_in[12];
    const float* Wg       = (const float*)d_in[13];
    const float* bg       = (const float*)d_in[14];
    const float* Wo       = (const float*)d_in[15];
    const float* bo       = (const float*)d_in[16];
    float* out = (float*)d_out;

    bf16 *xh, *xl, *Qh, *Ql, *Kh, *Kl, *Vh, *Vl, *Wh, *Wl;
    float *Z, *H1, *H2, *QKB, *bias, *G, *O;
    cudaGetSymbolAddress((void**)&xh, g_xh);
    cudaGetSymbolAddress((void**)&xl, g_xl);
    cudaGetSymbolAddress((void**)&Z, g_Z);
    cudaGetSymbolAddress((void**)&H1, g_H1);
    cudaGetSymbolAddress((void**)&H2, g_H2);
    cudaGetSymbolAddress((void**)&QKB, g_QKB);
    cudaGetSymbolAddress((void**)&bias, g_bias);
    cudaGetSymbolAddress((void**)&Qh, g_Qh);
    cudaGetSymbolAddress((void**)&Ql, g_Ql);
    cudaGetSymbolAddress((void**)&Kh, g_Kh);
    cudaGetSymbolAddress((void**)&Kl, g_Kl);
    cudaGetSymbolAddress((void**)&Vh, g_Vh);
    cudaGetSymbolAddress((void**)&Vl, g_Vl);
    cudaGetSymbolAddress((void**)&G, g_G);
    cudaGetSymbolAddress((void**)&O, g_O);
    cudaGetSymbolAddress((void**)&Wh, g_Wh);
    cudaGetSymbolAddress((void**)&Wl, g_Wl);

    const int PROJ_SMEM = (128 * 136 + 128 * 136) * 2;   // 69632 bytes (v2)
    const int OUT_SMEM  = (256 * 136 + 128 * 136) * 2;   // 104448 bytes
    cudaFuncSetAttribute(proj_tc, cudaFuncAttributeMaxDynamicSharedMemorySize, PROJ_SMEM);
    cudaFuncSetAttribute(out_tc, cudaFuncAttributeMaxDynamicSharedMemorySize, OUT_SMEM);

    // #1: weight pre-split
    prep_w<<<320, 256>>>(Wq_att, Wk_att, Wv_att, Wg, Wo, Wh, Wl);
    // #2: layernorm
    ln_kernel<<<M_TOT / 8, 256>>>(x, gamma, beta, xh, xl);
    // #3: means + concat
    meanz_kernel<<<2 * N_SEQ, 128>>>(xh, xl, s_inputs, Z);
    // #4: projections v2 (profiled position)
    proj_tc<<<M_TOT / 64, 256, PROJ_SMEM>>>(xh, xl, Wh, Wl, bg,
                                            Qh, Ql, Kh, Kl, Vh, Vl, G);
    // #5-#7: bias MLP chain
    mlp_tc<<<dim3(12, 4), 256>>>(Z, Wq1, Wk1, H1, ZD_DIM, MLP_H, 1);
    mlp_tc<<<dim3(12, 4), 256>>>(H1, Wq2, Wk2, H2, MLP_H, MLP_H, 1);
    mlp_tc<<<dim3(12, 6), 256>>>(H2, Wq3, Wk3, QKB, MLP_H, HR_DIM, 0);
    // #8: low-rank bias matrix
    bias_kernel<<<dim3(H_NUM, N_SEQ / 32, N_SEQ / 64), 256>>>(QKB, QKB + N_SEQ * HR_DIM, bias);
    // #9: attention
    attn_tc<<<dim3(3, H_NUM, N_SEQ), 256>>>(Qh, Ql, Kh, Kl, Vh, Vl, bias, O);
    // #10: gated output projection
    out_tc<<<dim3(M_TOT / 128, 2), 256, OUT_SMEM>>>(G, O, Wh, Wl, bo, out);
}

// round 8
// speedup vs baseline: 2.2671x; 1.1809x over previous
#include <cuda_runtime.h>
#include <cuda_bf16.h>
#include <cstdint>
#include <math.h>

#define N_SEQ 384
#define C_DIM 128
#define H_NUM 4
#define DH_NUM 32
#define R_RANK 96
#define SD_DIM 449
#define ZD_DIM 577
#define MLP_H 256
#define HR_DIM 384
#define M_TOT (N_SEQ * N_SEQ)   // 147456

typedef __nv_bfloat16 bf16;

// ---------------- scratch (device globals) ----------------
__device__ bf16  g_xh[(size_t)M_TOT * C_DIM];
__device__ bf16  g_xl[(size_t)M_TOT * C_DIM];
__device__ float g_Z[2 * N_SEQ * ZD_DIM];
__device__ float g_H1[2 * N_SEQ * MLP_H];
__device__ float g_H2[2 * N_SEQ * MLP_H];
__device__ float g_QKB[2 * N_SEQ * HR_DIM];
__device__ float g_bias[(size_t)H_NUM * N_SEQ * N_SEQ];
__device__ bf16  g_Qh[(size_t)M_TOT * C_DIM];
__device__ bf16  g_Ql[(size_t)M_TOT * C_DIM];
__device__ bf16  g_Kh[(size_t)M_TOT * C_DIM];
__device__ bf16  g_Kl[(size_t)M_TOT * C_DIM];
__device__ bf16  g_Vh[(size_t)M_TOT * C_DIM];
__device__ bf16  g_Vl[(size_t)M_TOT * C_DIM];
__device__ float g_G[(size_t)M_TOT * C_DIM];
__device__ float g_O[(size_t)M_TOT * C_DIM];
__device__ bf16  g_Wh[5 * 128 * 128];   // pre-split weights, n-major [w][n][k]
__device__ bf16  g_Wl[5 * 128 * 128];

// ---------------- helpers ----------------
__device__ __forceinline__ uint32_t pk2(float a, float b) {
    __nv_bfloat162 t = __floats2bfloat162_rn(a, b);
    return *reinterpret_cast<uint32_t*>(&t);
}
__device__ __forceinline__ float bhi(float x) {
    return __bfloat162float(__float2bfloat16(x));
}
__device__ __forceinline__ void mma_bf16(float* c, const uint32_t* a, uint32_t b0, uint32_t b1) {
    asm volatile(
        "mma.sync.aligned.m16n8k16.row.col.f32.bf16.bf16.f32 "
        "{%0,%1,%2,%3},{%4,%5,%6,%7},{%8,%9},{%0,%1,%2,%3};"
        : "+f"(c[0]), "+f"(c[1]), "+f"(c[2]), "+f"(c[3])
        : "r"(a[0]), "r"(a[1]), "r"(a[2]), "r"(a[3]), "r"(b0), "r"(b1));
}
__device__ __forceinline__ void ldsm_x4(uint32_t& r0, uint32_t& r1, uint32_t& r2, uint32_t& r3,
                                        uint32_t addr) {
    asm volatile("ldmatrix.sync.aligned.m8n8.x4.shared.b16 {%0,%1,%2,%3}, [%4];"
                 : "=r"(r0), "=r"(r1), "=r"(r2), "=r"(r3) : "r"(addr));
}
__device__ __forceinline__ void ldsm_x4_t(uint32_t& r0, uint32_t& r1, uint32_t& r2, uint32_t& r3,
                                          uint32_t addr) {
    asm volatile("ldmatrix.sync.aligned.m8n8.x4.trans.shared.b16 {%0,%1,%2,%3}, [%4];"
                 : "=r"(r0), "=r"(r1), "=r"(r2), "=r"(r3) : "r"(addr));
}
__device__ __forceinline__ uint32_t sm_u32(const void* p) {
    return (uint32_t)__cvta_generic_to_shared(p);
}

// ---------------- pre-split attention weights (once) ----------------
__global__ void prep_w(const float* __restrict__ Wq, const float* __restrict__ Wk,
                       const float* __restrict__ Wv, const float* __restrict__ Wg,
                       const float* __restrict__ Wo,
                       bf16* __restrict__ Wh, bf16* __restrict__ Wl) {
    int idx = blockIdx.x * 256 + threadIdx.x;
    if (idx >= 5 * 16384) return;
    int w = idx >> 14, r = idx & 16383;
    int n = r >> 7, k = r & 127;
    const float* W = (w == 0) ? Wq : (w == 1) ? Wk : (w == 2) ? Wv : (w == 3) ? Wg : Wo;
    float v = W[k * 128 + n];
    bf16 h = __float2bfloat16(v);
    Wh[idx] = h;
    Wl[idx] = __float2bfloat16(v - __bfloat162float(h));
}

// ---------------- LayerNorm -> split bf16 hi/lo ----------------
__global__ void ln_kernel(const float* __restrict__ x, const float* __restrict__ gamma,
                          const float* __restrict__ beta,
                          bf16* __restrict__ xh, bf16* __restrict__ xl) {
    size_t pix = (size_t)blockIdx.x * 8 + (threadIdx.x >> 5);
    int l = threadIdx.x & 31;
    const float4* xp = reinterpret_cast<const float4*>(x + pix * 128);
    float4 v = xp[l];
    float s = v.x + v.y + v.z + v.w;
    float s2 = v.x * v.x + v.y * v.y + v.z * v.z + v.w * v.w;
#pragma unroll
    for (int o = 16; o; o >>= 1) {
        s  += __shfl_xor_sync(0xffffffffu, s, o);
        s2 += __shfl_xor_sync(0xffffffffu, s2, o);
    }
    float mu = s * (1.f / 128.f);
    float var = s2 * (1.f / 128.f) - mu * mu;
    float rs = rsqrtf(var + 1e-5f);
    float4 gm = reinterpret_cast<const float4*>(gamma)[l];
    float4 bt = reinterpret_cast<const float4*>(beta)[l];
    float o0 = (v.x - mu) * rs * gm.x + bt.x;
    float o1 = (v.y - mu) * rs * gm.y + bt.y;
    float o2 = (v.z - mu) * rs * gm.z + bt.z;
    float o3 = (v.w - mu) * rs * gm.w + bt.w;
    size_t base = pix * 128 + 4 * l;
    *(uint32_t*)&xh[base]     = pk2(o0, o1);
    *(uint32_t*)&xh[base + 2] = pk2(o2, o3);
    *(uint32_t*)&xl[base]     = pk2(o0 - bhi(o0), o1 - bhi(o1));
    *(uint32_t*)&xl[base + 2] = pk2(o2 - bhi(o2), o3 - bhi(o3));
}

// ---------------- fused row/col means + concat s_inputs -> Z ----------------
__global__ void meanz_kernel(const bf16* __restrict__ xh, const bf16* __restrict__ xl,
                             const float* __restrict__ s_inputs, float* __restrict__ Z) {
    int c = threadIdx.x;
    int idx = blockIdx.x;
    float s = 0.f;
    if (idx < N_SEQ) {
        size_t base = (size_t)idx * N_SEQ * C_DIM;
        for (int j = 0; j < N_SEQ; j++) {
            size_t e = base + (size_t)j * C_DIM + c;
            s += __bfloat162float(xh[e]) + __bfloat162float(xl[e]);
        }
    } else {
        int j = idx - N_SEQ;
        for (int i = 0; i < N_SEQ; i++) {
            size_t e = ((size_t)i * N_SEQ + j) * C_DIM + c;
            s += __bfloat162float(xh[e]) + __bfloat162float(xl[e]);
        }
    }
    Z[(size_t)idx * ZD_DIM + c] = s * (1.f / N_SEQ);
    int n = (idx < N_SEQ) ? idx : idx - N_SEQ;
    for (int t = c; t < SD_DIM; t += 128)
        Z[(size_t)idx * ZD_DIM + C_DIM + t] = s_inputs[n * SD_DIM + t];
}

// ---------------- TC MLP layer (q/k fused along M) ----------------
__global__ __launch_bounds__(256) void mlp_tc(
    const float* __restrict__ A, const float* __restrict__ Wq, const float* __restrict__ Wk,
    float* __restrict__ C, int K, int Nout, int act) {
    __shared__ __align__(16) bf16 As[128][34];
    __shared__ __align__(16) bf16 Bs[128][34];
    int m0 = blockIdx.x * 64;
    int n0 = blockIdx.y * 64;
    const float* W = (blockIdx.x < 6) ? Wq : Wk;
    int tid = threadIdx.x;
    int w = tid >> 5, lane = tid & 31, g = lane >> 2, tg = lane & 3;
    int wm = (w & 3) * 16, wn = (w >> 2) * 32;
    float acc[4][4];
#pragma unroll
    for (int ni = 0; ni < 4; ni++)
#pragma unroll
        for (int j = 0; j < 4; j++) acc[ni][j] = 0.f;

    for (int k0 = 0; k0 < K; k0 += 32) {
        for (int e = tid; e < 2048; e += 256) {
            int r = e >> 5, c = e & 31;
            int gk = k0 + c;
            float v = (gk < K) ? A[(size_t)(m0 + r) * K + gk] : 0.f;
            bf16 h = __float2bfloat16(v);
            As[r][c] = h;
            As[64 + r][c] = __float2bfloat16(v - __bfloat162float(h));
        }
        for (int e = tid; e < 2048; e += 256) {
            int k = e >> 6, n = e & 63;
            int gk = k0 + k;
            float v = (gk < K) ? W[(size_t)gk * Nout + n0 + n] : 0.f;
            bf16 h = __float2bfloat16(v);
            Bs[n][k] = h;
            Bs[64 + n][k] = __float2bfloat16(v - __bfloat162float(h));
        }
        __syncthreads();
#pragma unroll
        for (int p = 0; p < 3; p++) {
            int ao = (p == 2) ? 64 : 0;
            int bo = (p == 1) ? 64 : 0;
#pragma unroll
            for (int kc = 0; kc < 2; kc++) {
                int k2 = kc * 16 + tg * 2;
                uint32_t a[4];
                int ar = ao + wm;
                a[0] = *(const uint32_t*)&As[ar + g][k2];
                a[1] = *(const uint32_t*)&As[ar + g + 8][k2];
                a[2] = *(const uint32_t*)&As[ar + g][k2 + 8];
                a[3] = *(const uint32_t*)&As[ar + g + 8][k2 + 8];
#pragma unroll
                for (int ni = 0; ni < 4; ni++) {
                    int bn = bo + wn + ni * 8 + g;
                    uint32_t b0 = *(const uint32_t*)&Bs[bn][k2];
                    uint32_t b1 = *(const uint32_t*)&Bs[bn][k2 + 8];
                    mma_bf16(acc[ni], a, b0, b1);
                }
            }
        }
        __syncthreads();
    }
#pragma unroll
    for (int ni = 0; ni < 4; ni++) {
        int col = n0 + wn + ni * 8 + tg * 2;
        size_t r0 = (size_t)(m0 + wm + g) * Nout + col;
        size_t r1 = r0 + (size_t)8 * Nout;
        float v0 = acc[ni][0], v1 = acc[ni][1], v2 = acc[ni][2], v3 = acc[ni][3];
        if (act) { v0 = tanhf(v0); v1 = tanhf(v1); v2 = tanhf(v2); v3 = tanhf(v3); }
        *(float2*)&C[r0] = make_float2(v0, v1);
        *(float2*)&C[r1] = make_float2(v2, v3);
    }
}

// ---------------- low-rank bias matrix ----------------
__global__ void bias_kernel(const float* __restrict__ qb, const float* __restrict__ kb,
                            float* __restrict__ B) {
    __shared__ float qs[32][97];
    __shared__ float ks[64][97];
    int h = blockIdx.x, q0 = blockIdx.y * 32, k0 = blockIdx.z * 64;
    for (int e = threadIdx.x; e < 32 * 96; e += 256) {
        int q = e / 96, r = e % 96;
        qs[q][r] = qb[(q0 + q) * HR_DIM + h * R_RANK + r];
    }
    for (int e = threadIdx.x; e < 64 * 96; e += 256) {
        int k = e / 96, r = e % 96;
        ks[k][r] = kb[(k0 + k) * HR_DIM + h * R_RANK + r];
    }
    __syncthreads();
    int ki = threadIdx.x & 63, qg = threadIdx.x >> 6;
    float acc[8];
#pragma unroll
    for (int u = 0; u < 8; u++) acc[u] = 0.f;
    for (int r = 0; r < 96; r++) {
        float kv = ks[ki][r];
#pragma unroll
        for (int u = 0; u < 8; u++) acc[u] = fmaf(kv, qs[qg * 8 + u][r], acc[u]);
    }
#pragma unroll
    for (int u = 0; u < 8; u++)
        B[((size_t)h * N_SEQ + q0 + qg * 8 + u) * N_SEQ + k0 + ki] = acc[u];
}

// ---------------- proj v2: A tile resident, loop over 8 (weight, half) chunks ----------------
__global__ __launch_bounds__(256) void proj_tc(
    const bf16* __restrict__ xh, const bf16* __restrict__ xl,
    const bf16* __restrict__ WhAll, const bf16* __restrict__ WlAll,
    const float* __restrict__ bg,
    bf16* __restrict__ Qh, bf16* __restrict__ Ql,
    bf16* __restrict__ Kh, bf16* __restrict__ Kl,
    bf16* __restrict__ Vh, bf16* __restrict__ Vl,
    float* __restrict__ G) {
    extern __shared__ __align__(16) bf16 sm[];
    bf16 (*As)[136] = reinterpret_cast<bf16(*)[136]>(sm);              // rows 0-63 hi, 64-127 lo
    bf16 (*Bs)[136] = reinterpret_cast<bf16(*)[136]>(sm + 128 * 136);  // rows 0-63 hi, 64-127 lo
    int mb = blockIdx.x;
    int tid = threadIdx.x;
    size_t abase = (size_t)mb * 64 * 128;
    for (int e = tid; e < 1024; e += 256) {
        int r = e >> 4, c8 = (e & 15) * 8;
        *(uint4*)&As[r][c8]      = *(const uint4*)&xh[abase + (size_t)r * 128 + c8];
        *(uint4*)&As[64 + r][c8] = *(const uint4*)&xl[abase + (size_t)r * 128 + c8];
    }
    int w = tid >> 5, lane = tid & 31, g = lane >> 2, tg = lane & 3;
    int wm = (w & 1) * 32, wn = (w >> 1) * 16;
    uint32_t as_sm = sm_u32(&As[0][0]);
    uint32_t bs_sm = sm_u32(&Bs[0][0]);
    uint32_t a_pat = ((lane & 7) + ((lane >> 3) & 1) * 8) * 272 + (lane >> 4) * 16;
    uint32_t b_pat = ((lane & 7) + (lane >> 4) * 8) * 272 + ((lane >> 3) & 1) * 16;
    const float qscale = 0.17677669529663687f;

    for (int ch = 0; ch < 8; ch++) {
        int which = ch >> 1, n0 = (ch & 1) * 64;
        const bf16* WhM = WhAll + which * 16384;
        const bf16* WlM = WlAll + which * 16384;
        __syncthreads();
        for (int e = tid; e < 2048; e += 256) {
            int r = e >> 4, c8 = (e & 15) * 8;
            const bf16* src = (r < 64) ? &WhM[(n0 + r) * 128 + c8]
                                       : &WlM[(n0 + r - 64) * 128 + c8];
            *(uint4*)&Bs[r][c8] = *(const uint4*)src;
        }
        __syncthreads();

        float acc[2][2][4];
#pragma unroll
        for (int mi = 0; mi < 2; mi++)
#pragma unroll
            for (int ni = 0; ni < 2; ni++)
#pragma unroll
                for (int j = 0; j < 4; j++) acc[mi][ni][j] = 0.f;
#pragma unroll
        for (int p = 0; p < 3; p++) {
            int ao = (p == 2) ? 64 : 0;
            int bo = (p == 1) ? 64 : 0;
#pragma unroll
            for (int kc = 0; kc < 8; kc++) {
                uint32_t kb = kc * 32;
                uint32_t a[2][4], b[4];
#pragma unroll
                for (int mi = 0; mi < 2; mi++)
                    ldsm_x4(a[mi][0], a[mi][1], a[mi][2], a[mi][3],
                            as_sm + (ao + wm + mi * 16) * 272 + kb + a_pat);
                ldsm_x4(b[0], b[1], b[2], b[3],
                        bs_sm + (bo + wn) * 272 + kb + b_pat);
#pragma unroll
                for (int mi = 0; mi < 2; mi++) {
                    mma_bf16(acc[mi][0], a[mi], b[0], b[1]);
                    mma_bf16(acc[mi][1], a[mi], b[2], b[3]);
                }
            }
        }
#pragma unroll
        for (int mi = 0; mi < 2; mi++)
#pragma unroll
        for (int ni = 0; ni < 2; ni++) {
            size_t row0 = (size_t)mb * 64 + wm + mi * 16 + g;
            int col = n0 + wn + ni * 8 + tg * 2;
            float* c = acc[mi][ni];
            if (which == 0) { c[0] *= qscale; c[1] *= qscale; c[2] *= qscale; c[3] *= qscale; }
            if (which == 3) {
                float b0v = bg[col], b1v = bg[col + 1];
                float g0 = 1.f / (1.f + expf(-(c[0] + b0v)));
                float g1 = 1.f / (1.f + expf(-(c[1] + b1v)));
                float g2 = 1.f / (1.f + expf(-(c[2] + b0v)));
                float g3 = 1.f / (1.f + expf(-(c[3] + b1v)));
                *(float2*)&G[row0 * 128 + col] = make_float2(g0, g1);
                *(float2*)&G[(row0 + 8) * 128 + col] = make_float2(g2, g3);
            } else {
                bf16* Oh = (which == 0) ? Qh : (which == 1) ? Kh : Vh;
                bf16* Ol = (which == 0) ? Ql : (which == 1) ? Kl : Vl;
                *(uint32_t*)&Oh[row0 * 128 + col] = pk2(c[0], c[1]);
                *(uint32_t*)&Ol[row0 * 128 + col] = pk2(c[0] - bhi(c[0]), c[1] - bhi(c[1]));
                *(uint32_t*)&Oh[(row0 + 8) * 128 + col] = pk2(c[2], c[3]);
                *(uint32_t*)&Ol[(row0 + 8) * 128 + col] = pk2(c[2] - bhi(c[2]), c[3] - bhi(c[3]));
            }
        }
    }
}

// ---------------- tensor-core flash attention (ldmatrix + trans-V) ----------------
__global__ __launch_bounds__(256) void attn_tc(
    const bf16* __restrict__ Qh, const bf16* __restrict__ Ql,
    const bf16* __restrict__ Kh, const bf16* __restrict__ Kl,
    const bf16* __restrict__ Vh, const bf16* __restrict__ Vl,
    const float* __restrict__ B, float* __restrict__ O) {
    __shared__ __align__(16) bf16 Qs[256][40];   // rows 0-127 hi, 128-255 lo ; [qrow][d]
    __shared__ __align__(16) bf16 Ks[128][40];   // rows 0-63 hi, 64-127 lo   ; [kpos][d]
    __shared__ __align__(16) bf16 Vs[128][40];   // rows 0-63 hi, 64-127 lo   ; [kpos][d]
    int qt = blockIdx.x, h = blockIdx.y, i = blockIdx.z;
    int q0 = qt * 128, tid = threadIdx.x;
    size_t qgb = ((size_t)(i * N_SEQ + q0)) * 128 + h * 32;
    for (int e = tid; e < 512; e += 256) {
        int r = e >> 2, c8 = (e & 3) * 8;
        *(uint4*)&Qs[r][c8]       = *(const uint4*)&Qh[qgb + (size_t)r * 128 + c8];
        *(uint4*)&Qs[128 + r][c8] = *(const uint4*)&Ql[qgb + (size_t)r * 128 + c8];
    }
    int w = tid >> 5, lane = tid & 31, g = lane >> 2, tg = lane & 3;
    int qr = w * 16;
    uint32_t qs_sm = sm_u32(&Qs[0][0]);
    uint32_t ks_sm = sm_u32(&Ks[0][0]);
    uint32_t vs_sm = sm_u32(&Vs[0][0]);
    uint32_t qa_pat = ((lane & 7) + ((lane >> 3) & 1) * 8) * 80 + (lane >> 4) * 16;
    uint32_t kb_pat = ((lane & 7) + (lane >> 4) * 8) * 80 + ((lane >> 3) & 1) * 16;
    // trans-V pattern: row = (lane&7) + ((lane>>3)&1)*8 (k within 16), col-half = (lane>>4)*8 (d)
    uint32_t vt_pat = ((lane & 7) + ((lane >> 3) & 1) * 8) * 80 + (lane >> 4) * 16;
    __syncthreads();
    uint32_t qa[2][2][4];
#pragma unroll
    for (int s = 0; s < 2; s++)
#pragma unroll
        for (int kc = 0; kc < 2; kc++)
            ldsm_x4(qa[s][kc][0], qa[s][kc][1], qa[s][kc][2], qa[s][kc][3],
                    qs_sm + (s * 128 + qr) * 80 + kc * 32 + qa_pat);
    float oacc[4][4];
#pragma unroll
    for (int ni = 0; ni < 4; ni++)
#pragma unroll
        for (int j = 0; j < 4; j++) oacc[ni][j] = 0.f;
    float m0 = -1e30f, m1 = -1e30f, l0 = 0.f, l1 = 0.f;
    const float L2E = 1.4426950408889634f;
    size_t brow0 = ((size_t)h * N_SEQ + q0 + qr + g) * N_SEQ;
    size_t brow1 = brow0 + (size_t)8 * N_SEQ;

    for (int kt = 0; kt < 6; kt++) {
        int k0 = kt * 64;
        __syncthreads();
        size_t kb = ((size_t)(i * N_SEQ + k0)) * 128 + h * 32;
        {   // K + V tiles: 64x32 hi/lo, plain vector copies (ldmatrix.trans does V transpose)
            int r = tid >> 2, c8 = (tid & 3) * 8;
            *(uint4*)&Ks[r][c8]      = *(const uint4*)&Kh[kb + (size_t)r * 128 + c8];
            *(uint4*)&Ks[64 + r][c8] = *(const uint4*)&Kl[kb + (size_t)r * 128 + c8];
            *(uint4*)&Vs[r][c8]      = *(const uint4*)&Vh[kb + (size_t)r * 128 + c8];
            *(uint4*)&Vs[64 + r][c8] = *(const uint4*)&Vl[kb + (size_t)r * 128 + c8];
        }
        __syncthreads();

        float sc[8][4];
#pragma unroll
        for (int nf = 0; nf < 8; nf++) {
            int col = k0 + nf * 8 + tg * 2;
            float2 b0 = *(const float2*)&B[brow0 + col];
            float2 b1 = *(const float2*)&B[brow1 + col];
            sc[nf][0] = b0.x; sc[nf][1] = b0.y; sc[nf][2] = b1.x; sc[nf][3] = b1.y;
        }
#pragma unroll
        for (int p = 0; p < 3; p++) {
            int aso = (p == 2) ? 1 : 0;
            int kso = (p == 1) ? 64 : 0;
#pragma unroll
            for (int kc = 0; kc < 2; kc++) {
#pragma unroll
                for (int nfp = 0; nfp < 4; nfp++) {
                    uint32_t t0, t1, t2, t3;
                    ldsm_x4(t0, t1, t2, t3,
                            ks_sm + (kso + nfp * 16) * 80 + kc * 32 + kb_pat);
                    mma_bf16(sc[2 * nfp],     qa[aso][kc], t0, t1);
                    mma_bf16(sc[2 * nfp + 1], qa[aso][kc], t2, t3);
                }
            }
        }
        // online softmax
        float nm0 = m0, nm1 = m1;
#pragma unroll
        for (int nf = 0; nf < 8; nf++) {
            nm0 = fmaxf(nm0, fmaxf(sc[nf][0], sc[nf][1]));
            nm1 = fmaxf(nm1, fmaxf(sc[nf][2], sc[nf][3]));
        }
        nm0 = fmaxf(nm0, __shfl_xor_sync(0xffffffffu, nm0, 1));
        nm0 = fmaxf(nm0, __shfl_xor_sync(0xffffffffu, nm0, 2));
        nm1 = fmaxf(nm1, __shfl_xor_sync(0xffffffffu, nm1, 1));
        nm1 = fmaxf(nm1, __shfl_xor_sync(0xffffffffu, nm1, 2));
        float cor0 = exp2f((m0 - nm0) * L2E);
        float cor1 = exp2f((m1 - nm1) * L2E);
        m0 = nm0; m1 = nm1;
        l0 *= cor0; l1 *= cor1;
#pragma unroll
        for (int ni = 0; ni < 4; ni++) {
            oacc[ni][0] *= cor0; oacc[ni][1] *= cor0;
            oacc[ni][2] *= cor1; oacc[ni][3] *= cor1;
        }
#pragma unroll
        for (int nf = 0; nf < 8; nf++) {
            sc[nf][0] = exp2f((sc[nf][0] - m0) * L2E);
            sc[nf][1] = exp2f((sc[nf][1] - m0) * L2E);
            sc[nf][2] = exp2f((sc[nf][2] - m1) * L2E);
            sc[nf][3] = exp2f((sc[nf][3] - m1) * L2E);
            l0 += sc[nf][0] + sc[nf][1];
            l1 += sc[nf][2] + sc[nf][3];
        }
        // PV: P split hi/lo; V fragments via ldmatrix.trans from [kpos][d] tiles
#pragma unroll
        for (int kc = 0; kc < 4; kc++) {
            float* f0 = sc[2 * kc];
            float* f1 = sc[2 * kc + 1];
            uint32_t pah[4], pal[4];
            pah[0] = pk2(f0[0], f0[1]); pah[1] = pk2(f0[2], f0[3]);
            pah[2] = pk2(f1[0], f1[1]); pah[3] = pk2(f1[2], f1[3]);
            pal[0] = pk2(f0[0] - bhi(f0[0]), f0[1] - bhi(f0[1]));
            pal[1] = pk2(f0[2] - bhi(f0[2]), f0[3] - bhi(f0[3]));
            pal[2] = pk2(f1[0] - bhi(f1[0]), f1[1] - bhi(f1[1]));
            pal[3] = pk2(f1[2] - bhi(f1[2]), f1[3] - bhi(f1[3]));
#pragma unroll
            for (int dh = 0; dh < 2; dh++) {
                uint32_t bh0, bh1, bh2, bh3, bl0, bl1, bl2, bl3;
                ldsm_x4_t(bh0, bh1, bh2, bh3,
                          vs_sm + (kc * 16) * 80 + dh * 32 + vt_pat);
                ldsm_x4_t(bl0, bl1, bl2, bl3,
                          vs_sm + (64 + kc * 16) * 80 + dh * 32 + vt_pat);
                mma_bf16(oacc[dh * 2],     pah, bh0, bh1);
                mma_bf16(oacc[dh * 2],     pah, bl0, bl1);
                mma_bf16(oacc[dh * 2],     pal, bh0, bh1);
                mma_bf16(oacc[dh * 2 + 1], pah, bh2, bh3);
                mma_bf16(oacc[dh * 2 + 1], pah, bl2, bl3);
                mma_bf16(oacc[dh * 2 + 1], pal, bh2, bh3);
            }
        }
    }
    l0 += __shfl_xor_sync(0xffffffffu, l0, 1);
    l0 += __shfl_xor_sync(0xffffffffu, l0, 2);
    l1 += __shfl_xor_sync(0xffffffffu, l1, 1);
    l1 += __shfl_xor_sync(0xffffffffu, l1, 2);
    float i0 = 1.f / l0, i1 = 1.f / l1;
    size_t ob0 = ((size_t)(i * N_SEQ + q0 + qr + g)) * 128 + h * 32;
    size_t ob1 = ob0 + 8 * 128;
#pragma unroll
    for (int ni = 0; ni < 4; ni++) {
        int d = ni * 8 + tg * 2;
        *(float2*)&O[ob0 + d] = make_float2(oacc[ni][0] * i0, oacc[ni][1] * i0);
        *(float2*)&O[ob1 + d] = make_float2(oacc[ni][2] * i1, oacc[ni][3] * i1);
    }
}

// ---------------- out v2: A (g.*o) resident 64 rows, loop over 2 n-chunks ----------------
__global__ __launch_bounds__(256) void out_tc(
    const float* __restrict__ G, const float* __restrict__ O,
    const bf16* __restrict__ WhAll, const bf16* __restrict__ WlAll,
    const float* __restrict__ bo,
    float* __restrict__ out) {
    extern __shared__ __align__(16) bf16 sm[];
    bf16 (*As)[136] = reinterpret_cast<bf16(*)[136]>(sm);              // rows 0-63 hi, 64-127 lo
    bf16 (*Bs)[136] = reinterpret_cast<bf16(*)[136]>(sm + 128 * 136);
    int mb = blockIdx.x;
    int tid = threadIdx.x;
    const bf16* WhM = WhAll + 4 * 16384;
    const bf16* WlM = WlAll + 4 * 16384;
    size_t abase = (size_t)mb * 64 * 128;
    for (int e = tid; e < 2048; e += 256) {
        int r = e >> 5, c4 = (e & 31) * 4;
        float4 g4 = *(const float4*)&G[abase + (size_t)r * 128 + c4];
        float4 o4 = *(const float4*)&O[abase + (size_t)r * 128 + c4];
        float a0 = g4.x * o4.x, a1 = g4.y * o4.y, a2 = g4.z * o4.z, a3 = g4.w * o4.w;
        *(uint32_t*)&As[r][c4]          = pk2(a0, a1);
        *(uint32_t*)&As[r][c4 + 2]      = pk2(a2, a3);
        *(uint32_t*)&As[64 + r][c4]     = pk2(a0 - bhi(a0), a1 - bhi(a1));
        *(uint32_t*)&As[64 + r][c4 + 2] = pk2(a2 - bhi(a2), a3 - bhi(a3));
    }
    int w = tid >> 5, lane = tid & 31, g = lane >> 2, tg = lane & 3;
    int wm = (w & 1) * 32, wn = (w >> 1) * 16;
    uint32_t as_sm = sm_u32(&As[0][0]);
    uint32_t bs_sm = sm_u32(&Bs[0][0]);
    uint32_t a_pat = ((lane & 7) + ((lane >> 3) & 1) * 8) * 272 + (lane >> 4) * 16;
    uint32_t b_pat = ((lane & 7) + (lane >> 4) * 8) * 272 + ((lane >> 3) & 1) * 16;

    for (int ch = 0; ch < 2; ch++) {
        int n0 = ch * 64;
        __syncthreads();
        for (int e = tid; e < 2048; e += 256) {
            int r = e >> 4, c8 = (e & 15) * 8;
            const bf16* src = (r < 64) ? &WhM[(n0 + r) * 128 + c8]
                                       : &WlM[(n0 + r - 64) * 128 + c8];
            *(uint4*)&Bs[r][c8] = *(const uint4*)src;
        }
        __syncthreads();

        float acc[2][2][4];
#pragma unroll
        for (int mi = 0; mi < 2; mi++)
#pragma unroll
            for (int ni = 0; ni < 2; ni++)
#pragma unroll
                for (int j = 0; j < 4; j++) acc[mi][ni][j] = 0.f;
#pragma unroll
        for (int p = 0; p < 3; p++) {
            int ao = (p == 2) ? 64 : 0;
            int bo2 = (p == 1) ? 64 : 0;
#pragma unroll
            for (int kc = 0; kc < 8; kc++) {
                uint32_t kb = kc * 32;
                uint32_t a[2][4], b[4];
#pragma unroll
                for (int mi = 0; mi < 2; mi++)
                    ldsm_x4(a[mi][0], a[mi][1], a[mi][2], a[mi][3],
                            as_sm + (ao + wm + mi * 16) * 272 + kb + a_pat);
                ldsm_x4(b[0], b[1], b[2], b[3],
                        bs_sm + (bo2 + wn) * 272 + kb + b_pat);
#pragma unroll
                for (int mi = 0; mi < 2; mi++) {
                    mma_bf16(acc[mi][0], a[mi], b[0], b[1]);
                    mma_bf16(acc[mi][1], a[mi], b[2], b[3]);
                }
            }
        }
#pragma unroll
        for (int mi = 0; mi < 2; mi++)
#pragma unroll
        for (int ni = 0; ni < 2; ni++) {
            size_t row0 = (size_t)mb * 64 + wm + mi * 16 + g;
            int col = n0 + wn + ni * 8 + tg * 2;
            float b0v = bo[col], b1v = bo[col + 1];
            float* c = acc[mi][ni];
            *(float2*)&out[row0 * 128 + col] = make_float2(c[0] + b0v, c[1] + b1v);
            *(float2*)&out[(row0 + 8) * 128 + col] = make_float2(c[2] + b0v, c[3] + b1v);
        }
    }
}

// ---------------- launch ----------------
extern "C" void kernel_launch(void* const* d_in, const int* in_sizes, int n_in,
                              void* d_out, int out_size) {
    const float* x        = (const float*)d_in[0];
    const float* s_inputs = (const float*)d_in[1];
    const float* gamma    = (const float*)d_in[2];
    const float* beta     = (const float*)d_in[3];
    const float* Wq1      = (const float*)d_in[4];
    const float* Wq2      = (const float*)d_in[5];
    const float* Wq3      = (const float*)d_in[6];
    const float* Wk1      = (const float*)d_in[7];
    const float* Wk2      = (const float*)d_in[8];
    const float* Wk3      = (const float*)d_in[9];
    const float* Wq_att   = (const float*)d_in[10];
    const float* Wk_att   = (const float*)d_in[11];
    const float* Wv_att   = (const float*)d_in[12];
    const float* Wg       = (const float*)d_in[13];
    const float* bg       = (const float*)d_in[14];
    const float* Wo       = (const float*)d_in[15];
    const float* bo       = (const float*)d_in[16];
    float* out = (float*)d_out;

    bf16 *xh, *xl, *Qh, *Ql, *Kh, *Kl, *Vh, *Vl, *Wh, *Wl;
    float *Z, *H1, *H2, *QKB, *bias, *G, *O;
    cudaGetSymbolAddress((void**)&xh, g_xh);
    cudaGetSymbolAddress((void**)&xl, g_xl);
    cudaGetSymbolAddress((void**)&Z, g_Z);
    cudaGetSymbolAddress((void**)&H1, g_H1);
    cudaGetSymbolAddress((void**)&H2, g_H2);
    cudaGetSymbolAddress((void**)&QKB, g_QKB);
    cudaGetSymbolAddress((void**)&bias, g_bias);
    cudaGetSymbolAddress((void**)&Qh, g_Qh);
    cudaGetSymbolAddress((void**)&Ql, g_Ql);
    cudaGetSymbolAddress((void**)&Kh, g_Kh);
    cudaGetSymbolAddress((void**)&Kl, g_Kl);
    cudaGetSymbolAddress((void**)&Vh, g_Vh);
    cudaGetSymbolAddress((void**)&Vl, g_Vl);
    cudaGetSymbolAddress((void**)&G, g_G);
    cudaGetSymbolAddress((void**)&O, g_O);
    cudaGetSymbolAddress((void**)&Wh, g_Wh);
    cudaGetSymbolAddress((void**)&Wl, g_Wl);

    const int TILE_SMEM = (128 * 136 + 128 * 136) * 2;   // 69632 bytes
    cudaFuncSetAttribute(proj_tc, cudaFuncAttributeMaxDynamicSharedMemorySize, TILE_SMEM);
    cudaFuncSetAttribute(out_tc, cudaFuncAttributeMaxDynamicSharedMemorySize, TILE_SMEM);

    // #1: weight pre-split
    prep_w<<<320, 256>>>(Wq_att, Wk_att, Wv_att, Wg, Wo, Wh, Wl);
    // #2: layernorm
    ln_kernel<<<M_TOT / 8, 256>>>(x, gamma, beta, xh, xl);
    // #3: means + concat
    meanz_kernel<<<2 * N_SEQ, 128>>>(xh, xl, s_inputs, Z);
    // #4: projections v2 (profiled position — control: expect ~264us unchanged)
    proj_tc<<<M_TOT / 64, 256, TILE_SMEM>>>(xh, xl, Wh, Wl, bg,
                                            Qh, Ql, Kh, Kl, Vh, Vl, G);
    // #5-#7: bias MLP chain
    mlp_tc<<<dim3(12, 4), 256>>>(Z, Wq1, Wk1, H1, ZD_DIM, MLP_H, 1);
    mlp_tc<<<dim3(12, 4), 256>>>(H1, Wq2, Wk2, H2, MLP_H, MLP_H, 1);
    mlp_tc<<<dim3(12, 6), 256>>>(H2, Wq3, Wk3, QKB, MLP_H, HR_DIM, 0);
    // #8: low-rank bias matrix
    bias_kernel<<<dim3(H_NUM, N_SEQ / 32, N_SEQ / 64), 256>>>(QKB, QKB + N_SEQ * HR_DIM, bias);
    // #9: attention (trans-V)
    attn_tc<<<dim3(3, H_NUM, N_SEQ), 256>>>(Qh, Ql, Kh, Kl, Vh, Vl, bias, O);
    // #10: gated output projection v2
    out_tc<<<M_TOT / 64, 256, TILE_SMEM>>>(G, O, Wh, Wl, bo, out);
}

// round 10
// speedup vs baseline: 2.5294x; 1.1157x over previous
#include <cuda_runtime.h>
#include <cuda_bf16.h>
#include <cstdint>
#include <math.h>

#define N_SEQ 384
#define C_DIM 128
#define H_NUM 4
#define DH_NUM 32
#define R_RANK 96
#define SD_DIM 449
#define ZD_DIM 577
#define MLP_H 256
#define HR_DIM 384
#define M_TOT (N_SEQ * N_SEQ)   // 147456

typedef __nv_bfloat16 bf16;

// ---------------- scratch (device globals) ----------------
__device__ bf16  g_xh[(size_t)M_TOT * C_DIM];
__device__ bf16  g_xl[(size_t)M_TOT * C_DIM];
__device__ float g_Z[2 * N_SEQ * ZD_DIM];
__device__ float g_H1[2 * N_SEQ * MLP_H];
__device__ float g_H2[2 * N_SEQ * MLP_H];
__device__ float g_QKB[2 * N_SEQ * HR_DIM];
__device__ float g_bias[(size_t)H_NUM * N_SEQ * N_SEQ];
__device__ bf16  g_Qh[(size_t)M_TOT * C_DIM];
__device__ bf16  g_Ql[(size_t)M_TOT * C_DIM];
__device__ bf16  g_Kh[(size_t)M_TOT * C_DIM];
__device__ bf16  g_Kl[(size_t)M_TOT * C_DIM];
__device__ bf16  g_Vh[(size_t)M_TOT * C_DIM];
__device__ bf16  g_Vl[(size_t)M_TOT * C_DIM];
__device__ float g_G[(size_t)M_TOT * C_DIM];
__device__ float g_O[(size_t)M_TOT * C_DIM];
__device__ bf16  g_Wh[5 * 128 * 128];   // pre-split weights, n-major [w][n][k]
__device__ bf16  g_Wl[5 * 128 * 128];

// ---------------- helpers ----------------
__device__ __forceinline__ uint32_t pk2(float a, float b) {
    __nv_bfloat162 t = __floats2bfloat162_rn(a, b);
    return *reinterpret_cast<uint32_t*>(&t);
}
__device__ __forceinline__ float bhi(float x) {
    return __bfloat162float(__float2bfloat16(x));
}
__device__ __forceinline__ void mma_bf16(float* c, const uint32_t* a, uint32_t b0, uint32_t b1) {
    asm volatile(
        "mma.sync.aligned.m16n8k16.row.col.f32.bf16.bf16.f32 "
        "{%0,%1,%2,%3},{%4,%5,%6,%7},{%8,%9},{%0,%1,%2,%3};"
        : "+f"(c[0]), "+f"(c[1]), "+f"(c[2]), "+f"(c[3])
        : "r"(a[0]), "r"(a[1]), "r"(a[2]), "r"(a[3]), "r"(b0), "r"(b1));
}
__device__ __forceinline__ void ldsm_x4(uint32_t& r0, uint32_t& r1, uint32_t& r2, uint32_t& r3,
                                        uint32_t addr) {
    asm volatile("ldmatrix.sync.aligned.m8n8.x4.shared.b16 {%0,%1,%2,%3}, [%4];"
                 : "=r"(r0), "=r"(r1), "=r"(r2), "=r"(r3) : "r"(addr));
}
__device__ __forceinline__ void ldsm_x4_t(uint32_t& r0, uint32_t& r1, uint32_t& r2, uint32_t& r3,
                                          uint32_t addr) {
    asm volatile("ldmatrix.sync.aligned.m8n8.x4.trans.shared.b16 {%0,%1,%2,%3}, [%4];"
                 : "=r"(r0), "=r"(r1), "=r"(r2), "=r"(r3) : "r"(addr));
}
__device__ __forceinline__ uint32_t sm_u32(const void* p) {
    return (uint32_t)__cvta_generic_to_shared(p);
}

// ---------------- pre-split attention weights (once) ----------------
__global__ void prep_w(const float* __restrict__ Wq, const float* __restrict__ Wk,
                       const float* __restrict__ Wv, const float* __restrict__ Wg,
                       const float* __restrict__ Wo,
                       bf16* __restrict__ Wh, bf16* __restrict__ Wl) {
    int idx = blockIdx.x * 256 + threadIdx.x;
    if (idx >= 5 * 16384) return;
    int w = idx >> 14, r = idx & 16383;
    int n = r >> 7, k = r & 127;
    const float* W = (w == 0) ? Wq : (w == 1) ? Wk : (w == 2) ? Wv : (w == 3) ? Wg : Wo;
    float v = W[k * 128 + n];
    bf16 h = __float2bfloat16(v);
    Wh[idx] = h;
    Wl[idx] = __float2bfloat16(v - __bfloat162float(h));
}

// ---------------- LayerNorm -> split bf16 hi/lo ----------------
__global__ void ln_kernel(const float* __restrict__ x, const float* __restrict__ gamma,
                          const float* __restrict__ beta,
                          bf16* __restrict__ xh, bf16* __restrict__ xl) {
    size_t pix = (size_t)blockIdx.x * 8 + (threadIdx.x >> 5);
    int l = threadIdx.x & 31;
    const float4* xp = reinterpret_cast<const float4*>(x + pix * 128);
    float4 v = xp[l];
    float s = v.x + v.y + v.z + v.w;
    float s2 = v.x * v.x + v.y * v.y + v.z * v.z + v.w * v.w;
#pragma unroll
    for (int o = 16; o; o >>= 1) {
        s  += __shfl_xor_sync(0xffffffffu, s, o);
        s2 += __shfl_xor_sync(0xffffffffu, s2, o);
    }
    float mu = s * (1.f / 128.f);
    float var = s2 * (1.f / 128.f) - mu * mu;
    float rs = rsqrtf(var + 1e-5f);
    float4 gm = reinterpret_cast<const float4*>(gamma)[l];
    float4 bt = reinterpret_cast<const float4*>(beta)[l];
    float o0 = (v.x - mu) * rs * gm.x + bt.x;
    float o1 = (v.y - mu) * rs * gm.y + bt.y;
    float o2 = (v.z - mu) * rs * gm.z + bt.z;
    float o3 = (v.w - mu) * rs * gm.w + bt.w;
    size_t base = pix * 128 + 4 * l;
    *(uint32_t*)&xh[base]     = pk2(o0, o1);
    *(uint32_t*)&xh[base + 2] = pk2(o2, o3);
    *(uint32_t*)&xl[base]     = pk2(o0 - bhi(o0), o1 - bhi(o1));
    *(uint32_t*)&xl[base + 2] = pk2(o2 - bhi(o2), o3 - bhi(o3));
}

// ---------------- fused row/col means + concat s_inputs -> Z ----------------
__global__ void meanz_kernel(const bf16* __restrict__ xh, const bf16* __restrict__ xl,
                             const float* __restrict__ s_inputs, float* __restrict__ Z) {
    int c = threadIdx.x;
    int idx = blockIdx.x;
    float s = 0.f;
    if (idx < N_SEQ) {
        size_t base = (size_t)idx * N_SEQ * C_DIM;
        for (int j = 0; j < N_SEQ; j++) {
            size_t e = base + (size_t)j * C_DIM + c;
            s += __bfloat162float(xh[e]) + __bfloat162float(xl[e]);
        }
    } else {
        int j = idx - N_SEQ;
        for (int i = 0; i < N_SEQ; i++) {
            size_t e = ((size_t)i * N_SEQ + j) * C_DIM + c;
            s += __bfloat162float(xh[e]) + __bfloat162float(xl[e]);
        }
    }
    Z[(size_t)idx * ZD_DIM + c] = s * (1.f / N_SEQ);
    int n = (idx < N_SEQ) ? idx : idx - N_SEQ;
    for (int t = c; t < SD_DIM; t += 128)
        Z[(size_t)idx * ZD_DIM + C_DIM + t] = s_inputs[n * SD_DIM + t];
}

// ---------------- TC MLP layer (q/k fused along M, register-prefetch pipelined) ----------------
__global__ __launch_bounds__(256) void mlp_tc(
    const float* __restrict__ A, const float* __restrict__ Wq, const float* __restrict__ Wk,
    float* __restrict__ C, int K, int Nout, int act) {
    __shared__ __align__(16) bf16 As[128][34];
    __shared__ __align__(16) bf16 Bs[128][34];
    int m0 = blockIdx.x * 64;
    int n0 = blockIdx.y * 64;
    const float* W = (blockIdx.x < 6) ? Wq : Wk;
    int tid = threadIdx.x;
    int w = tid >> 5, lane = tid & 31, g = lane >> 2, tg = lane & 3;
    int wm = (w & 3) * 16, wn = (w >> 2) * 32;
    float acc[4][4];
#pragma unroll
    for (int ni = 0; ni < 4; ni++)
#pragma unroll
        for (int j = 0; j < 4; j++) acc[ni][j] = 0.f;

    // prefetch registers: 8 A elems + 8 W elems per thread per tile
    float va[8], vb[8];
#pragma unroll
    for (int i = 0; i < 8; i++) {
        int e = tid + i * 256;
        int r = e >> 5, c = e & 31;
        va[i] = (c < K) ? A[(size_t)(m0 + r) * K + c] : 0.f;
        int k = e >> 6, n = e & 63;
        vb[i] = (k < K) ? W[(size_t)k * Nout + n0 + n] : 0.f;
    }

    for (int k0 = 0; k0 < K; k0 += 32) {
        // store prefetched tile to smem (hi/lo split)
#pragma unroll
        for (int i = 0; i < 8; i++) {
            int e = tid + i * 256;
            int r = e >> 5, c = e & 31;
            bf16 h = __float2bfloat16(va[i]);
            As[r][c] = h;
            As[64 + r][c] = __float2bfloat16(va[i] - __bfloat162float(h));
            int k = e >> 6, n = e & 63;
            bf16 hb = __float2bfloat16(vb[i]);
            Bs[n][k] = hb;
            Bs[64 + n][k] = __float2bfloat16(vb[i] - __bfloat162float(hb));
        }
        __syncthreads();
        // issue next tile's global loads (latency overlapped with MMAs below)
        int kn = k0 + 32;
        if (kn < K) {
#pragma unroll
            for (int i = 0; i < 8; i++) {
                int e = tid + i * 256;
                int r = e >> 5, c = e & 31;
                int gk = kn + c;
                va[i] = (gk < K) ? A[(size_t)(m0 + r) * K + gk] : 0.f;
                int k = e >> 6, n = e & 63;
                int gk2 = kn + k;
                vb[i] = (gk2 < K) ? W[(size_t)gk2 * Nout + n0 + n] : 0.f;
            }
        }
#pragma unroll
        for (int kc = 0; kc < 2; kc++) {
            int k2 = kc * 16 + tg * 2;
            uint32_t ah[4], al[4];
            ah[0] = *(const uint32_t*)&As[wm + g][k2];
            ah[1] = *(const uint32_t*)&As[wm + g + 8][k2];
            ah[2] = *(const uint32_t*)&As[wm + g][k2 + 8];
            ah[3] = *(const uint32_t*)&As[wm + g + 8][k2 + 8];
            al[0] = *(const uint32_t*)&As[64 + wm + g][k2];
            al[1] = *(const uint32_t*)&As[64 + wm + g + 8][k2];
            al[2] = *(const uint32_t*)&As[64 + wm + g][k2 + 8];
            al[3] = *(const uint32_t*)&As[64 + wm + g + 8][k2 + 8];
#pragma unroll
            for (int ni = 0; ni < 4; ni++) {
                int bn = wn + ni * 8 + g;
                uint32_t bh0 = *(const uint32_t*)&Bs[bn][k2];
                uint32_t bh1 = *(const uint32_t*)&Bs[bn][k2 + 8];
                uint32_t bl0 = *(const uint32_t*)&Bs[64 + bn][k2];
                uint32_t bl1 = *(const uint32_t*)&Bs[64 + bn][k2 + 8];
                mma_bf16(acc[ni], ah, bh0, bh1);
                mma_bf16(acc[ni], ah, bl0, bl1);
                mma_bf16(acc[ni], al, bh0, bh1);
            }
        }
        __syncthreads();
    }
#pragma unroll
    for (int ni = 0; ni < 4; ni++) {
        int col = n0 + wn + ni * 8 + tg * 2;
        size_t r0 = (size_t)(m0 + wm + g) * Nout + col;
        size_t r1 = r0 + (size_t)8 * Nout;
        float v0 = acc[ni][0], v1 = acc[ni][1], v2 = acc[ni][2], v3 = acc[ni][3];
        if (act) { v0 = tanhf(v0); v1 = tanhf(v1); v2 = tanhf(v2); v3 = tanhf(v3); }
        *(float2*)&C[r0] = make_float2(v0, v1);
        *(float2*)&C[r1] = make_float2(v2, v3);
    }
}

// ---------------- low-rank bias matrix ----------------
__global__ void bias_kernel(const float* __restrict__ qb, const float* __restrict__ kb,
                            float* __restrict__ B) {
    __shared__ float qs[32][97];
    __shared__ float ks[64][97];
    int h = blockIdx.x, q0 = blockIdx.y * 32, k0 = blockIdx.z * 64;
    for (int e = threadIdx.x; e < 32 * 96; e += 256) {
        int q = e / 96, r = e % 96;
        qs[q][r] = qb[(q0 + q) * HR_DIM + h * R_RANK + r];
    }
    for (int e = threadIdx.x; e < 64 * 96; e += 256) {
        int k = e / 96, r = e % 96;
        ks[k][r] = kb[(k0 + k) * HR_DIM + h * R_RANK + r];
    }
    __syncthreads();
    int ki = threadIdx.x & 63, qg = threadIdx.x >> 6;
    float acc[8];
#pragma unroll
    for (int u = 0; u < 8; u++) acc[u] = 0.f;
    for (int r = 0; r < 96; r++) {
        float kv = ks[ki][r];
#pragma unroll
        for (int u = 0; u < 8; u++) acc[u] = fmaf(kv, qs[qg * 8 + u][r], acc[u]);
    }
#pragma unroll
    for (int u = 0; u < 8; u++)
        B[((size_t)h * N_SEQ + q0 + qg * 8 + u) * N_SEQ + k0 + ki] = acc[u];
}

// ---------------- proj v3: A resident, kc-outer fragment reuse (0.5 ldsm/MMA) ----------------
__global__ __launch_bounds__(256) void proj_tc(
    const bf16* __restrict__ xh, const bf16* __restrict__ xl,
    const bf16* __restrict__ WhAll, const bf16* __restrict__ WlAll,
    const float* __restrict__ bg,
    bf16* __restrict__ Qh, bf16* __restrict__ Ql,
    bf16* __restrict__ Kh, bf16* __restrict__ Kl,
    bf16* __restrict__ Vh, bf16* __restrict__ Vl,
    float* __restrict__ G) {
    extern __shared__ __align__(16) bf16 sm[];
    bf16 (*As)[136] = reinterpret_cast<bf16(*)[136]>(sm);              // rows 0-63 hi, 64-127 lo
    bf16 (*Bs)[136] = reinterpret_cast<bf16(*)[136]>(sm + 128 * 136);  // rows 0-63 hi, 64-127 lo
    int mb = blockIdx.x;
    int tid = threadIdx.x;
    size_t abase = (size_t)mb * 64 * 128;
    for (int e = tid; e < 1024; e += 256) {
        int r = e >> 4, c8 = (e & 15) * 8;
        *(uint4*)&As[r][c8]      = *(const uint4*)&xh[abase + (size_t)r * 128 + c8];
        *(uint4*)&As[64 + r][c8] = *(const uint4*)&xl[abase + (size_t)r * 128 + c8];
    }
    int w = tid >> 5, lane = tid & 31, g = lane >> 2, tg = lane & 3;
    int wm = (w & 1) * 32, wn = (w >> 1) * 16;
    uint32_t as_sm = sm_u32(&As[0][0]);
    uint32_t bs_sm = sm_u32(&Bs[0][0]);
    uint32_t a_pat = ((lane & 7) + ((lane >> 3) & 1) * 8) * 272 + (lane >> 4) * 16;
    uint32_t b_pat = ((lane & 7) + (lane >> 4) * 8) * 272 + ((lane >> 3) & 1) * 16;
    const float qscale = 0.17677669529663687f;

    for (int ch = 0; ch < 8; ch++) {
        int which = ch >> 1, n0 = (ch & 1) * 64;
        const bf16* WhM = WhAll + which * 16384;
        const bf16* WlM = WlAll + which * 16384;
        __syncthreads();
        for (int e = tid; e < 2048; e += 256) {
            int r = e >> 4, c8 = (e & 15) * 8;
            const bf16* src = (r < 64) ? &WhM[(n0 + r) * 128 + c8]
                                       : &WlM[(n0 + r - 64) * 128 + c8];
            *(uint4*)&Bs[r][c8] = *(const uint4*)src;
        }
        __syncthreads();

        float acc[2][2][4];
#pragma unroll
        for (int mi = 0; mi < 2; mi++)
#pragma unroll
            for (int ni = 0; ni < 2; ni++)
#pragma unroll
                for (int j = 0; j < 4; j++) acc[mi][ni][j] = 0.f;
#pragma unroll
        for (int kc = 0; kc < 8; kc++) {
            uint32_t kb = kc * 32;
            uint32_t ah[2][4], al[2][4], bv[2][4];  // bv[0]=b_hi, bv[1]=b_lo
#pragma unroll
            for (int mi = 0; mi < 2; mi++) {
                ldsm_x4(ah[mi][0], ah[mi][1], ah[mi][2], ah[mi][3],
                        as_sm + (wm + mi * 16) * 272 + kb + a_pat);
                ldsm_x4(al[mi][0], al[mi][1], al[mi][2], al[mi][3],
                        as_sm + (64 + wm + mi * 16) * 272 + kb + a_pat);
            }
            ldsm_x4(bv[0][0], bv[0][1], bv[0][2], bv[0][3],
                    bs_sm + wn * 272 + kb + b_pat);
            ldsm_x4(bv[1][0], bv[1][1], bv[1][2], bv[1][3],
                    bs_sm + (64 + wn) * 272 + kb + b_pat);
#pragma unroll
            for (int mi = 0; mi < 2; mi++) {
                mma_bf16(acc[mi][0], ah[mi], bv[0][0], bv[0][1]);
                mma_bf16(acc[mi][1], ah[mi], bv[0][2], bv[0][3]);
                mma_bf16(acc[mi][0], ah[mi], bv[1][0], bv[1][1]);
                mma_bf16(acc[mi][1], ah[mi], bv[1][2], bv[1][3]);
                mma_bf16(acc[mi][0], al[mi], bv[0][0], bv[0][1]);
                mma_bf16(acc[mi][1], al[mi], bv[0][2], bv[0][3]);
            }
        }
#pragma unroll
        for (int mi = 0; mi < 2; mi++)
#pragma unroll
        for (int ni = 0; ni < 2; ni++) {
            size_t row0 = (size_t)mb * 64 + wm + mi * 16 + g;
            int col = n0 + wn + ni * 8 + tg * 2;
            float* c = acc[mi][ni];
            if (which == 0) { c[0] *= qscale; c[1] *= qscale; c[2] *= qscale; c[3] *= qscale; }
            if (which == 3) {
                float b0v = bg[col], b1v = bg[col + 1];
                float g0 = 1.f / (1.f + expf(-(c[0] + b0v)));
                float g1 = 1.f / (1.f + expf(-(c[1] + b1v)));
                float g2 = 1.f / (1.f + expf(-(c[2] + b0v)));
                float g3 = 1.f / (1.f + expf(-(c[3] + b1v)));
                *(float2*)&G[row0 * 128 + col] = make_float2(g0, g1);
                *(float2*)&G[(row0 + 8) * 128 + col] = make_float2(g2, g3);
            } else {
                bf16* Oh = (which == 0) ? Qh : (which == 1) ? Kh : Vh;
                bf16* Ol = (which == 0) ? Ql : (which == 1) ? Kl : Vl;
                *(uint32_t*)&Oh[row0 * 128 + col] = pk2(c[0], c[1]);
                *(uint32_t*)&Ol[row0 * 128 + col] = pk2(c[0] - bhi(c[0]), c[1] - bhi(c[1]));
                *(uint32_t*)&Oh[(row0 + 8) * 128 + col] = pk2(c[2], c[3]);
                *(uint32_t*)&Ol[(row0 + 8) * 128 + col] = pk2(c[2] - bhi(c[2]), c[3] - bhi(c[3]));
            }
        }
    }
}

// ---------------- tensor-core flash attention (trans-V + K-frag reuse) ----------------
__global__ __launch_bounds__(256) void attn_tc(
    const bf16* __restrict__ Qh, const bf16* __restrict__ Ql,
    const bf16* __restrict__ Kh, const bf16* __restrict__ Kl,
    const bf16* __restrict__ Vh, const bf16* __restrict__ Vl,
    const float* __restrict__ B, float* __restrict__ O) {
    __shared__ __align__(16) bf16 Qs[256][40];   // rows 0-127 hi, 128-255 lo ; [qrow][d]
    __shared__ __align__(16) bf16 Ks[128][40];   // rows 0-63 hi, 64-127 lo   ; [kpos][d]
    __shared__ __align__(16) bf16 Vs[128][40];   // rows 0-63 hi, 64-127 lo   ; [kpos][d]
    int qt = blockIdx.x, h = blockIdx.y, i = blockIdx.z;
    int q0 = qt * 128, tid = threadIdx.x;
    size_t qgb = ((size_t)(i * N_SEQ + q0)) * 128 + h * 32;
    for (int e = tid; e < 512; e += 256) {
        int r = e >> 2, c8 = (e & 3) * 8;
        *(uint4*)&Qs[r][c8]       = *(const uint4*)&Qh[qgb + (size_t)r * 128 + c8];
        *(uint4*)&Qs[128 + r][c8] = *(const uint4*)&Ql[qgb + (size_t)r * 128 + c8];
    }
    int w = tid >> 5, lane = tid & 31, g = lane >> 2, tg = lane & 3;
    int qr = w * 16;
    uint32_t qs_sm = sm_u32(&Qs[0][0]);
    uint32_t ks_sm = sm_u32(&Ks[0][0]);
    uint32_t vs_sm = sm_u32(&Vs[0][0]);
    uint32_t qa_pat = ((lane & 7) + ((lane >> 3) & 1) * 8) * 80 + (lane >> 4) * 16;
    uint32_t kb_pat = ((lane & 7) + (lane >> 4) * 8) * 80 + ((lane >> 3) & 1) * 16;
    uint32_t vt_pat = ((lane & 7) + ((lane >> 3) & 1) * 8) * 80 + (lane >> 4) * 16;
    __syncthreads();
    uint32_t qa[2][2][4];
#pragma unroll
    for (int s = 0; s < 2; s++)
#pragma unroll
        for (int kc = 0; kc < 2; kc++)
            ldsm_x4(qa[s][kc][0], qa[s][kc][1], qa[s][kc][2], qa[s][kc][3],
                    qs_sm + (s * 128 + qr) * 80 + kc * 32 + qa_pat);
    float oacc[4][4];
#pragma unroll
    for (int ni = 0; ni < 4; ni++)
#pragma unroll
        for (int j = 0; j < 4; j++) oacc[ni][j] = 0.f;
    float m0 = -1e30f, m1 = -1e30f, l0 = 0.f, l1 = 0.f;
    const float L2E = 1.4426950408889634f;
    size_t brow0 = ((size_t)h * N_SEQ + q0 + qr + g) * N_SEQ;
    size_t brow1 = brow0 + (size_t)8 * N_SEQ;

    for (int kt = 0; kt < 6; kt++) {
        int k0 = kt * 64;
        __syncthreads();
        size_t kb = ((size_t)(i * N_SEQ + k0)) * 128 + h * 32;
        {
            int r = tid >> 2, c8 = (tid & 3) * 8;
            *(uint4*)&Ks[r][c8]      = *(const uint4*)&Kh[kb + (size_t)r * 128 + c8];
            *(uint4*)&Ks[64 + r][c8] = *(const uint4*)&Kl[kb + (size_t)r * 128 + c8];
            *(uint4*)&Vs[r][c8]      = *(const uint4*)&Vh[kb + (size_t)r * 128 + c8];
            *(uint4*)&Vs[64 + r][c8] = *(const uint4*)&Vl[kb + (size_t)r * 128 + c8];
        }
        __syncthreads();

        float sc[8][4];
#pragma unroll
        for (int nf = 0; nf < 8; nf++) {
            int col = k0 + nf * 8 + tg * 2;
            float2 b0 = *(const float2*)&B[brow0 + col];
            float2 b1 = *(const float2*)&B[brow1 + col];
            sc[nf][0] = b0.x; sc[nf][1] = b0.y; sc[nf][2] = b1.x; sc[nf][3] = b1.y;
        }
        // QK^T with K-fragment reuse: load K hi+lo once per (kc, nfp), 6 MMAs
#pragma unroll
        for (int kc = 0; kc < 2; kc++) {
#pragma unroll
            for (int nfp = 0; nfp < 4; nfp++) {
                uint32_t h0, h1, h2, h3, e0, e1, e2, e3;
                ldsm_x4(h0, h1, h2, h3, ks_sm + (nfp * 16) * 80 + kc * 32 + kb_pat);
                ldsm_x4(e0, e1, e2, e3, ks_sm + (64 + nfp * 16) * 80 + kc * 32 + kb_pat);
                mma_bf16(sc[2 * nfp],     qa[0][kc], h0, h1);   // hh
                mma_bf16(sc[2 * nfp + 1], qa[0][kc], h2, h3);
                mma_bf16(sc[2 * nfp],     qa[0][kc], e0, e1);   // hl
                mma_bf16(sc[2 * nfp + 1], qa[0][kc], e2, e3);
                mma_bf16(sc[2 * nfp],     qa[1][kc], h0, h1);   // lh
                mma_bf16(sc[2 * nfp + 1], qa[1][kc], h2, h3);
            }
        }
        // online softmax
        float nm0 = m0, nm1 = m1;
#pragma unroll
        for (int nf = 0; nf < 8; nf++) {
            nm0 = fmaxf(nm0, fmaxf(sc[nf][0], sc[nf][1]));
            nm1 = fmaxf(nm1, fmaxf(sc[nf][2], sc[nf][3]));
        }
        nm0 = fmaxf(nm0, __shfl_xor_sync(0xffffffffu, nm0, 1));
        nm0 = fmaxf(nm0, __shfl_xor_sync(0xffffffffu, nm0, 2));
        nm1 = fmaxf(nm1, __shfl_xor_sync(0xffffffffu, nm1, 1));
        nm1 = fmaxf(nm1, __shfl_xor_sync(0xffffffffu, nm1, 2));
        float cor0 = exp2f((m0 - nm0) * L2E);
        float cor1 = exp2f((m1 - nm1) * L2E);
        m0 = nm0; m1 = nm1;
        l0 *= cor0; l1 *= cor1;
#pragma unroll
        for (int ni = 0; ni < 4; ni++) {
            oacc[ni][0] *= cor0; oacc[ni][1] *= cor0;
            oacc[ni][2] *= cor1; oacc[ni][3] *= cor1;
        }
#pragma unroll
        for (int nf = 0; nf < 8; nf++) {
            sc[nf][0] = exp2f((sc[nf][0] - m0) * L2E);
            sc[nf][1] = exp2f((sc[nf][1] - m0) * L2E);
            sc[nf][2] = exp2f((sc[nf][2] - m1) * L2E);
            sc[nf][3] = exp2f((sc[nf][3] - m1) * L2E);
            l0 += sc[nf][0] + sc[nf][1];
            l1 += sc[nf][2] + sc[nf][3];
        }
        // PV: P split hi/lo; V fragments via ldmatrix.trans
#pragma unroll
        for (int kc = 0; kc < 4; kc++) {
            float* f0 = sc[2 * kc];
            float* f1 = sc[2 * kc + 1];
            uint32_t pah[4], pal[4];
            pah[0] = pk2(f0[0], f0[1]); pah[1] = pk2(f0[2], f0[3]);
            pah[2] = pk2(f1[0], f1[1]); pah[3] = pk2(f1[2], f1[3]);
            pal[0] = pk2(f0[0] - bhi(f0[0]), f0[1] - bhi(f0[1]));
            pal[1] = pk2(f0[2] - bhi(f0[2]), f0[3] - bhi(f0[3]));
            pal[2] = pk2(f1[0] - bhi(f1[0]), f1[1] - bhi(f1[1]));
            pal[3] = pk2(f1[2] - bhi(f1[2]), f1[3] - bhi(f1[3]));
#pragma unroll
            for (int dh = 0; dh < 2; dh++) {
                uint32_t bh0, bh1, bh2, bh3, bl0, bl1, bl2, bl3;
                ldsm_x4_t(bh0, bh1, bh2, bh3,
                          vs_sm + (kc * 16) * 80 + dh * 32 + vt_pat);
                ldsm_x4_t(bl0, bl1, bl2, bl3,
                          vs_sm + (64 + kc * 16) * 80 + dh * 32 + vt_pat);
                mma_bf16(oacc[dh * 2],     pah, bh0, bh1);
                mma_bf16(oacc[dh * 2],     pah, bl0, bl1);
                mma_bf16(oacc[dh * 2],     pal, bh0, bh1);
                mma_bf16(oacc[dh * 2 + 1], pah, bh2, bh3);
                mma_bf16(oacc[dh * 2 + 1], pah, bl2, bl3);
                mma_bf16(oacc[dh * 2 + 1], pal, bh2, bh3);
            }
        }
    }
    l0 += __shfl_xor_sync(0xffffffffu, l0, 1);
    l0 += __shfl_xor_sync(0xffffffffu, l0, 2);
    l1 += __shfl_xor_sync(0xffffffffu, l1, 1);
    l1 += __shfl_xor_sync(0xffffffffu, l1, 2);
    float i0 = 1.f / l0, i1 = 1.f / l1;
    size_t ob0 = ((size_t)(i * N_SEQ + q0 + qr + g)) * 128 + h * 32;
    size_t ob1 = ob0 + 8 * 128;
#pragma unroll
    for (int ni = 0; ni < 4; ni++) {
        int d = ni * 8 + tg * 2;
        *(float2*)&O[ob0 + d] = make_float2(oacc[ni][0] * i0, oacc[ni][1] * i0);
        *(float2*)&O[ob1 + d] = make_float2(oacc[ni][2] * i1, oacc[ni][3] * i1);
    }
}

// ---------------- out v3: A resident, kc-outer fragment reuse ----------------
__global__ __launch_bounds__(256) void out_tc(
    const float* __restrict__ G, const float* __restrict__ O,
    const bf16* __restrict__ WhAll, const bf16* __restrict__ WlAll,
    const float* __restrict__ bo,
    float* __restrict__ out) {
    extern __shared__ __align__(16) bf16 sm[];
    bf16 (*As)[136] = reinterpret_cast<bf16(*)[136]>(sm);              // rows 0-63 hi, 64-127 lo
    bf16 (*Bs)[136] = reinterpret_cast<bf16(*)[136]>(sm + 128 * 136);
    int mb = blockIdx.x;
    int tid = threadIdx.x;
    const bf16* WhM = WhAll + 4 * 16384;
    const bf16* WlM = WlAll + 4 * 16384;
    size_t abase = (size_t)mb * 64 * 128;
    for (int e = tid; e < 2048; e += 256) {
        int r = e >> 5, c4 = (e & 31) * 4;
        float4 g4 = *(const float4*)&G[abase + (size_t)r * 128 + c4];
        float4 o4 = *(const float4*)&O[abase + (size_t)r * 128 + c4];
        float a0 = g4.x * o4.x, a1 = g4.y * o4.y, a2 = g4.z * o4.z, a3 = g4.w * o4.w;
        *(uint32_t*)&As[r][c4]          = pk2(a0, a1);
        *(uint32_t*)&As[r][c4 + 2]      = pk2(a2, a3);
        *(uint32_t*)&As[64 + r][c4]     = pk2(a0 - bhi(a0), a1 - bhi(a1));
        *(uint32_t*)&As[64 + r][c4 + 2] = pk2(a2 - bhi(a2), a3 - bhi(a3));
    }
    int w = tid >> 5, lane = tid & 31, g = lane >> 2, tg = lane & 3;
    int wm = (w & 1) * 32, wn = (w >> 1) * 16;
    uint32_t as_sm = sm_u32(&As[0][0]);
    uint32_t bs_sm = sm_u32(&Bs[0][0]);
    uint32_t a_pat = ((lane & 7) + ((lane >> 3) & 1) * 8) * 272 + (lane >> 4) * 16;
    uint32_t b_pat = ((lane & 7) + (lane >> 4) * 8) * 272 + ((lane >> 3) & 1) * 16;

    for (int ch = 0; ch < 2; ch++) {
        int n0 = ch * 64;
        __syncthreads();
        for (int e = tid; e < 2048; e += 256) {
            int r = e >> 4, c8 = (e & 15) * 8;
            const bf16* src = (r < 64) ? &WhM[(n0 + r) * 128 + c8]
                                       : &WlM[(n0 + r - 64) * 128 + c8];
            *(uint4*)&Bs[r][c8] = *(const uint4*)src;
        }
        __syncthreads();

        float acc[2][2][4];
#pragma unroll
        for (int mi = 0; mi < 2; mi++)
#pragma unroll
            for (int ni = 0; ni < 2; ni++)
#pragma unroll
                for (int j = 0; j < 4; j++) acc[mi][ni][j] = 0.f;
#pragma unroll
        for (int kc = 0; kc < 8; kc++) {
            uint32_t kb = kc * 32;
            uint32_t ah[2][4], al[2][4], bv[2][4];
#pragma unroll
            for (int mi = 0; mi < 2; mi++) {
                ldsm_x4(ah[mi][0], ah[mi][1], ah[mi][2], ah[mi][3],
                        as_sm + (wm + mi * 16) * 272 + kb + a_pat);
                ldsm_x4(al[mi][0], al[mi][1], al[mi][2], al[mi][3],
                        as_sm + (64 + wm + mi * 16) * 272 + kb + a_pat);
            }
            ldsm_x4(bv[0][0], bv[0][1], bv[0][2], bv[0][3],
                    bs_sm + wn * 272 + kb + b_pat);
            ldsm_x4(bv[1][0], bv[1][1], bv[1][2], bv[1][3],
                    bs_sm + (64 + wn) * 272 + kb + b_pat);
#pragma unroll
            for (int mi = 0; mi < 2; mi++) {
                mma_bf16(acc[mi][0], ah[mi], bv[0][0], bv[0][1]);
                mma_bf16(acc[mi][1], ah[mi], bv[0][2], bv[0][3]);
                mma_bf16(acc[mi][0], ah[mi], bv[1][0], bv[1][1]);
                mma_bf16(acc[mi][1], ah[mi], bv[1][2], bv[1][3]);
                mma_bf16(acc[mi][0], al[mi], bv[0][0], bv[0][1]);
                mma_bf16(acc[mi][1], al[mi], bv[0][2], bv[0][3]);
            }
        }
#pragma unroll
        for (int mi = 0; mi < 2; mi++)
#pragma unroll
        for (int ni = 0; ni < 2; ni++) {
            size_t row0 = (size_t)mb * 64 + wm + mi * 16 + g;
            int col = n0 + wn + ni * 8 + tg * 2;
            float b0v = bo[col], b1v = bo[col + 1];
            float* c = acc[mi][ni];
            *(float2*)&out[row0 * 128 + col] = make_float2(c[0] + b0v, c[1] + b1v);
            *(float2*)&out[(row0 + 8) * 128 + col] = make_float2(c[2] + b0v, c[3] + b1v);
        }
    }
}

// ---------------- launch ----------------
extern "C" void kernel_launch(void* const* d_in, const int* in_sizes, int n_in,
                              void* d_out, int out_size) {
    const float* x        = (const float*)d_in[0];
    const float* s_inputs = (const float*)d_in[1];
    const float* gamma    = (const float*)d_in[2];
    const float* beta     = (const float*)d_in[3];
    const float* Wq1      = (const float*)d_in[4];
    const float* Wq2      = (const float*)d_in[5];
    const float* Wq3      = (const float*)d_in[6];
    const float* Wk1      = (const float*)d_in[7];
    const float* Wk2      = (const float*)d_in[8];
    const float* Wk3      = (const float*)d_in[9];
    const float* Wq_att   = (const float*)d_in[10];
    const float* Wk_att   = (const float*)d_in[11];
    const float* Wv_att   = (const float*)d_in[12];
    const float* Wg       = (const float*)d_in[13];
    const float* bg       = (const float*)d_in[14];
    const float* Wo       = (const float*)d_in[15];
    const float* bo       = (const float*)d_in[16];
    float* out = (float*)d_out;

    bf16 *xh, *xl, *Qh, *Ql, *Kh, *Kl, *Vh, *Vl, *Wh, *Wl;
    float *Z, *H1, *H2, *QKB, *bias, *G, *O;
    cudaGetSymbolAddress((void**)&xh, g_xh);
    cudaGetSymbolAddress((void**)&xl, g_xl);
    cudaGetSymbolAddress((void**)&Z, g_Z);
    cudaGetSymbolAddress((void**)&H1, g_H1);
    cudaGetSymbolAddress((void**)&H2, g_H2);
    cudaGetSymbolAddress((void**)&QKB, g_QKB);
    cudaGetSymbolAddress((void**)&bias, g_bias);
    cudaGetSymbolAddress((void**)&Qh, g_Qh);
    cudaGetSymbolAddress((void**)&Ql, g_Ql);
    cudaGetSymbolAddress((void**)&Kh, g_Kh);
    cudaGetSymbolAddress((void**)&Kl, g_Kl);
    cudaGetSymbolAddress((void**)&Vh, g_Vh);
    cudaGetSymbolAddress((void**)&Vl, g_Vl);
    cudaGetSymbolAddress((void**)&G, g_G);
    cudaGetSymbolAddress((void**)&O, g_O);
    cudaGetSymbolAddress((void**)&Wh, g_Wh);
    cudaGetSymbolAddress((void**)&Wl, g_Wl);

    const int TILE_SMEM = (128 * 136 + 128 * 136) * 2;   // 69632 bytes
    cudaFuncSetAttribute(proj_tc, cudaFuncAttributeMaxDynamicSharedMemorySize, TILE_SMEM);
    cudaFuncSetAttribute(out_tc, cudaFuncAttributeMaxDynamicSharedMemorySize, TILE_SMEM);

    // #1: weight pre-split
    prep_w<<<320, 256>>>(Wq_att, Wk_att, Wv_att, Wg, Wo, Wh, Wl);
    // #2: layernorm
    ln_kernel<<<M_TOT / 8, 256>>>(x, gamma, beta, xh, xl);
    // #3: means + concat
    meanz_kernel<<<2 * N_SEQ, 128>>>(xh, xl, s_inputs, Z);
    // #4: projections v3 (profiled position — predict ~205us, L1 ~55%, tensor ~45%)
    proj_tc<<<M_TOT / 64, 256, TILE_SMEM>>>(xh, xl, Wh, Wl, bg,
                                            Qh, Ql, Kh, Kl, Vh, Vl, G);
    // #5-#7: bias MLP chain (pipelined)
    mlp_tc<<<dim3(12, 4), 256>>>(Z, Wq1, Wk1, H1, ZD_DIM, MLP_H, 1);
    mlp_tc<<<dim3(12, 4), 256>>>(H1, Wq2, Wk2, H2, MLP_H, MLP_H, 1);
    mlp_tc<<<dim3(12, 6), 256>>>(H2, Wq3, Wk3, QKB, MLP_H, HR_DIM, 0);
    // #8: low-rank bias matrix
    bias_kernel<<<dim3(H_NUM, N_SEQ / 32, N_SEQ / 64), 256>>>(QKB, QKB + N_SEQ * HR_DIM, bias);
    // #9: attention (K-frag reuse)
    attn_tc<<<dim3(3, H_NUM, N_SEQ), 256>>>(Qh, Ql, Kh, Kl, Vh, Vl, bias, O);
    // #10: gated output projection v3
    out_tc<<<M_TOT / 64, 256, TILE_SMEM>>>(G, O, Wh, Wl, bo, out);
}